// round 5
// baseline (speedup 1.0000x reference)
#include <cuda_runtime.h>
#include <math.h>

// Problem constants
constexpr int Bb = 8;
constexpr int Cc = 512;
constexpr int Ss = 1024;     // H*W
constexpr int M3 = 1536;     // 3*C
constexpr int NH = 8;
constexpr int HD = 64;

// Scratch buffers (static device globals; allocation is forbidden)
__device__ float g_h[Bb * Cc * Ss];      // groupnorm output, [b][c][s]
__device__ float g_qkv[Bb * M3 * Ss];    // qkv, [b][o][s]
__device__ float g_hf[Bb * Ss * Cc];     // attn out / INL ping, [b*s][c]
__device__ float g_hf2[Bb * Ss * Cc];    // INL pong

// ---- packed fp32x2 helpers (sm_100+: FFMA2 path, only reachable via PTX) ----
typedef unsigned long long ull;
struct alignas(16) U2 { ull a, b; };

__device__ __forceinline__ ull dup2(float x) {
    ull r; asm("mov.b64 %0, {%1, %1};" : "=l"(r) : "f"(x)); return r;
}
__device__ __forceinline__ void dfma(ull& d, ull a, ull b) {
    asm("fma.rn.f32x2 %0, %1, %2, %3;" : "=l"(d) : "l"(a), "l"(b), "l"(d));
}
__device__ __forceinline__ void dmul(ull& d, ull a) {
    asm("mul.rn.f32x2 %0, %1, %2;" : "=l"(d) : "l"(d), "l"(a));
}
__device__ __forceinline__ void unpk(ull v, float& lo, float& hi) {
    asm("mov.b64 {%0, %1}, %2;" : "=f"(lo), "=f"(hi) : "l"(v));
}

__device__ __forceinline__ float fast_tanh(float x) {
    x = fminf(fmaxf(x, -15.f), 15.f);
    float e = __expf(2.f * x);
    return __fdividef(e - 1.f, e + 1.f);
}

// ---------------------------------------------------------------------------
// GroupNorm: one block per (b, group). 64 channels x 1024 spatial per group.
// ---------------------------------------------------------------------------
__global__ void gn_kernel(const float* __restrict__ x,
                          const float* __restrict__ scale,
                          const float* __restrict__ bias) {
    const int b = blockIdx.x >> 3;
    const int g = blockIdx.x & 7;
    const int N = 64 * Ss;  // 65536
    const size_t base = (size_t)b * Cc * Ss + (size_t)g * 64 * Ss;
    const float* xp = x + base;

    float s = 0.f, s2 = 0.f;
    for (int i = threadIdx.x * 4; i < N; i += 1024) {
        float4 v = *(const float4*)(xp + i);
        s += v.x + v.y + v.z + v.w;
        s2 += v.x * v.x + v.y * v.y + v.z * v.z + v.w * v.w;
    }
    __shared__ float rs[256], rs2[256];
    rs[threadIdx.x] = s; rs2[threadIdx.x] = s2;
    __syncthreads();
    for (int o = 128; o > 0; o >>= 1) {
        if (threadIdx.x < o) {
            rs[threadIdx.x] += rs[threadIdx.x + o];
            rs2[threadIdx.x] += rs2[threadIdx.x + o];
        }
        __syncthreads();
    }
    const float mean = rs[0] / N;
    float var = rs2[0] / N - mean * mean;
    var = fmaxf(var, 0.f);
    const float rstd = rsqrtf(var + 1e-5f);

    for (int i = threadIdx.x * 4; i < N; i += 1024) {
        int c = g * 64 + (i >> 10);
        const float a = rstd * scale[c];
        const float bb2 = bias[c] - mean * a;
        float4 v = *(const float4*)(xp + i);
        float4 r = make_float4(v.x * a + bb2, v.y * a + bb2,
                               v.z * a + bb2, v.w * a + bb2);
        *(float4*)(g_h + base + i) = r;
    }
}

// ---------------------------------------------------------------------------
// QKV GEMM (NN): qkv[b,m,n] = sum_k W[m,k] * h[b,k,n] + bias[m]
// 128x128 tile, BK=8, 256 threads, 8x8 micro-tile via packed f32x2 FMA.
// ---------------------------------------------------------------------------
__global__ void __launch_bounds__(256) qkv_gemm(const float* __restrict__ W,
                                                const float* __restrict__ bias) {
    __shared__ __align__(16) float As[8][128];
    __shared__ __align__(16) float Bs[8][128];
    const int b = blockIdx.z;
    const int n0 = blockIdx.x * 128;
    const int m0 = blockIdx.y * 128;
    const int tid = threadIdx.x;
    const int tx = tid & 15, ty = tid >> 4;

    const float* Bbase = g_h + (size_t)b * Cc * Ss;
    const int a_m = tid >> 1;
    const int a_k = (tid & 1) * 4;
    const int b_k = tid >> 5;
    const int b_n = (tid & 31) * 4;

    const float* Aptr = W + (size_t)(m0 + a_m) * Cc + a_k;
    const float* Bptr = Bbase + (size_t)b_k * Ss + n0 + b_n;

    float4 pa = *(const float4*)Aptr;
    float4 pb = *(const float4*)Bptr;

    ull acc2[4][8] = {};   // row-pairs (a-idx 01,23,45,67) x 8 cols

    for (int k0 = 0; k0 < Cc; k0 += 8) {
        As[a_k + 0][a_m] = pa.x;
        As[a_k + 1][a_m] = pa.y;
        As[a_k + 2][a_m] = pa.z;
        As[a_k + 3][a_m] = pa.w;
        *(float4*)&Bs[b_k][b_n] = pb;
        __syncthreads();
        if (k0 + 8 < Cc) {
            pa = *(const float4*)(Aptr + k0 + 8);
            pb = *(const float4*)(Bptr + (size_t)(k0 + 8) * Ss);
        }
#pragma unroll
        for (int kk = 0; kk < 8; kk++) {
            U2 aA = *(const U2*)&As[kk][ty * 4];
            U2 aB = *(const U2*)&As[kk][64 + ty * 4];
            float4 bx = *(const float4*)&Bs[kk][tx * 4];
            float4 by = *(const float4*)&Bs[kk][64 + tx * 4];
            ull ap[4] = {aA.a, aA.b, aB.a, aB.b};
            ull bd[8] = {dup2(bx.x), dup2(bx.y), dup2(bx.z), dup2(bx.w),
                         dup2(by.x), dup2(by.y), dup2(by.z), dup2(by.w)};
#pragma unroll
            for (int ri = 0; ri < 4; ri++)
#pragma unroll
                for (int j = 0; j < 8; j++)
                    dfma(acc2[ri][j], ap[ri], bd[j]);
        }
        __syncthreads();
    }

    // Unpack: pair ri covers a-idx 2ri (lo) and 2ri+1 (hi)
    float acc[8][8];
#pragma unroll
    for (int ri = 0; ri < 4; ri++)
#pragma unroll
        for (int j = 0; j < 8; j++)
            unpk(acc2[ri][j], acc[2 * ri][j], acc[2 * ri + 1][j]);

    float* out = g_qkv + (size_t)b * M3 * Ss;
#pragma unroll
    for (int i = 0; i < 8; i++) {
        const int m = m0 + (i < 4 ? ty * 4 + i : 64 + ty * 4 + i - 4);
        const float bv = bias[m];
#pragma unroll
        for (int gj = 0; gj < 2; gj++) {
            const int n = n0 + gj * 64 + tx * 4;
            float4 r = make_float4(acc[i][gj * 4 + 0] + bv, acc[i][gj * 4 + 1] + bv,
                                   acc[i][gj * 4 + 2] + bv, acc[i][gj * 4 + 3] + bv);
            *(float4*)(out + (size_t)m * Ss + n) = r;
        }
    }
}

// ---------------------------------------------------------------------------
// Attention (flash-style, fp32, packed f32x2 FMA). One block per
// (b, head, s-tile of 128), t-tile of 64. Score micro-tile 8x4, O 8x4.
// ---------------------------------------------------------------------------
__global__ void attn_kernel() {
    extern __shared__ float sm[];
    float* Qs = sm;                  // [64 d][128 s]
    float* Ks = Qs + 64 * 128;       // [64 d][64 t]
    float* Vst = Ks + 64 * 64;       // [64 t][68]  (t-major, padded)
    float* Ps = Vst + 64 * 68;       // [128 s][68] (s-major, padded)

    const int tid = threadIdx.x;
    const int tx = tid & 15, ty = tid >> 4;
    const int b = blockIdx.y >> 3;
    const int hh = blockIdx.y & 7;
    const int s0 = blockIdx.x * 128;

    const float* qk = g_qkv + (size_t)b * M3 * Ss;
    const float* Qg = qk + (size_t)(hh * HD) * Ss + s0;
    const float* Kg = qk + (size_t)(Cc + hh * HD) * Ss;
    const float* Vg = qk + (size_t)(2 * Cc + hh * HD) * Ss;

    // Load Q tile [64 d][128 s], pre-scaled by hd^-0.5 = 0.125
#pragma unroll
    for (int r = 0; r < 32; r++) {
        int idx = r * 256 + tid;
        int d = idx >> 7, ss = idx & 127;
        Qs[idx] = Qg[(size_t)d * Ss + ss] * 0.125f;
    }

    float m_i[8], l_i[8];
#pragma unroll
    for (int i = 0; i < 8; i++) { m_i[i] = -1e30f; l_i[i] = 0.f; }
    ull accO2[8][2] = {};   // rows x d-pairs (d4+01, d4+23)

    int row[8];
#pragma unroll
    for (int i = 0; i < 8; i++)
        row[i] = (i < 4 ? ty * 4 + i : 64 + ty * 4 + i - 4);

    __syncthreads();

    for (int t0 = 0; t0 < Ss; t0 += 64) {
        // Load K tile [64 d][64 t] and V tile transposed [64 t][68]
#pragma unroll
        for (int r = 0; r < 16; r++) {
            int idx = r * 256 + tid;
            int d = idx >> 6, tt = idx & 63;
            Ks[idx] = Kg[(size_t)d * Ss + t0 + tt];
            Vst[tt * 68 + d] = Vg[(size_t)d * Ss + t0 + tt];
        }
        __syncthreads();

        // Score tile: sc[s][t] = sum_d Q[d][s]*K[d][t], packed over s-pairs
        ull sc2[4][4] = {};
#pragma unroll 4
        for (int kk = 0; kk < 64; kk++) {
            U2 qA = *(const U2*)&Qs[kk * 128 + ty * 4];
            U2 qB = *(const U2*)&Qs[kk * 128 + 64 + ty * 4];
            float4 kv = *(const float4*)&Ks[kk * 64 + tx * 4];
            ull qp[4] = {qA.a, qA.b, qB.a, qB.b};
            ull kd[4] = {dup2(kv.x), dup2(kv.y), dup2(kv.z), dup2(kv.w)};
#pragma unroll
            for (int ri = 0; ri < 4; ri++)
#pragma unroll
                for (int j = 0; j < 4; j++)
                    dfma(sc2[ri][j], qp[ri], kd[j]);
        }
        float sc[8][4];
#pragma unroll
        for (int ri = 0; ri < 4; ri++)
#pragma unroll
            for (int j = 0; j < 4; j++)
                unpk(sc2[ri][j], sc[2 * ri][j], sc[2 * ri + 1][j]);

        // Online softmax per s-row; reduce across the 16 tx lanes.
        float corr[8];
#pragma unroll
        for (int i = 0; i < 8; i++) {
            float tm = fmaxf(fmaxf(sc[i][0], sc[i][1]), fmaxf(sc[i][2], sc[i][3]));
#pragma unroll
            for (int off = 8; off >= 1; off >>= 1)
                tm = fmaxf(tm, __shfl_xor_sync(0xffffffffu, tm, off));
            const float nm = fmaxf(m_i[i], tm);
            corr[i] = __expf(m_i[i] - nm);
            float pv[4], ps = 0.f;
#pragma unroll
            for (int j = 0; j < 4; j++) { pv[j] = __expf(sc[i][j] - nm); ps += pv[j]; }
            *(float4*)&Ps[row[i] * 68 + tx * 4] =
                make_float4(pv[0], pv[1], pv[2], pv[3]);
#pragma unroll
            for (int off = 8; off >= 1; off >>= 1)
                ps += __shfl_xor_sync(0xffffffffu, ps, off);
            l_i[i] = l_i[i] * corr[i] + ps;
            m_i[i] = nm;
        }
        __syncthreads();

        // O accumulate: O[s][d] = O[s][d]*corr + sum_t P[s][t]*V[t][d]
#pragma unroll
        for (int i = 0; i < 8; i++) {
            ull cd = dup2(corr[i]);
            dmul(accO2[i][0], cd);
            dmul(accO2[i][1], cd);
        }

        const int d4 = tx * 4;
#pragma unroll 2
        for (int kk = 0; kk < 64; kk += 4) {
            U2 v0 = *(const U2*)&Vst[(kk + 0) * 68 + d4];
            U2 v1 = *(const U2*)&Vst[(kk + 1) * 68 + d4];
            U2 v2 = *(const U2*)&Vst[(kk + 2) * 68 + d4];
            U2 v3 = *(const U2*)&Vst[(kk + 3) * 68 + d4];
#pragma unroll
            for (int i = 0; i < 8; i++) {
                float4 p = *(const float4*)&Ps[row[i] * 68 + kk];
                ull px = dup2(p.x), py = dup2(p.y), pz = dup2(p.z), pw = dup2(p.w);
                dfma(accO2[i][0], px, v0.a); dfma(accO2[i][1], px, v0.b);
                dfma(accO2[i][0], py, v1.a); dfma(accO2[i][1], py, v1.b);
                dfma(accO2[i][0], pz, v2.a); dfma(accO2[i][1], pz, v2.b);
                dfma(accO2[i][0], pw, v3.a); dfma(accO2[i][1], pw, v3.b);
            }
        }
        __syncthreads();
    }

    // Finalize: divide by l, write to hf[b*S+s][hh*64+d]
    float* out = g_hf + ((size_t)b * Ss + s0) * Cc + hh * HD;
#pragma unroll
    for (int i = 0; i < 8; i++) {
        const float inv = __fdividef(1.f, l_i[i]);
        float o0, o1, o2, o3;
        unpk(accO2[i][0], o0, o1);
        unpk(accO2[i][1], o2, o3);
        float4 r = make_float4(o0 * inv, o1 * inv, o2 * inv, o3 * inv);
        *(float4*)(out + (size_t)row[i] * Cc + tx * 4) = r;
    }
}

// ---------------------------------------------------------------------------
// INL step (NT GEMM + fused Euler/tanh epilogue), packed f32x2 FMA.
// hout[r,o] = hin[r,o] + 0.1*tanh(sum_c hin[r,c]*W[o,c] + bias[o])
// ---------------------------------------------------------------------------
__global__ void __launch_bounds__(256) inl_gemm(int src, const float* __restrict__ W,
                                                const float* __restrict__ bias) {
    const float* hin = src ? g_hf2 : g_hf;
    float* hout = src ? g_hf : g_hf2;

    __shared__ __align__(16) float As[8][128];
    __shared__ __align__(16) float Ws[8][128];
    const int n0 = blockIdx.x * 128;
    const int m0 = blockIdx.y * 128;
    const int tid = threadIdx.x;
    const int tx = tid & 15, ty = tid >> 4;
    const int a_m = tid >> 1;
    const int a_k = (tid & 1) * 4;

    const float* Aptr = hin + (size_t)(m0 + a_m) * Cc + a_k;
    const float* Bptr = W + (size_t)(n0 + a_m) * Cc + a_k;

    float4 pa = *(const float4*)Aptr;
    float4 pb = *(const float4*)Bptr;

    ull acc2[4][8] = {};

    for (int k0 = 0; k0 < Cc; k0 += 8) {
        As[a_k + 0][a_m] = pa.x;
        As[a_k + 1][a_m] = pa.y;
        As[a_k + 2][a_m] = pa.z;
        As[a_k + 3][a_m] = pa.w;
        Ws[a_k + 0][a_m] = pb.x;
        Ws[a_k + 1][a_m] = pb.y;
        Ws[a_k + 2][a_m] = pb.z;
        Ws[a_k + 3][a_m] = pb.w;
        __syncthreads();
        if (k0 + 8 < Cc) {
            pa = *(const float4*)(Aptr + k0 + 8);
            pb = *(const float4*)(Bptr + k0 + 8);
        }
#pragma unroll
        for (int kk = 0; kk < 8; kk++) {
            U2 aA = *(const U2*)&As[kk][ty * 4];
            U2 aB = *(const U2*)&As[kk][64 + ty * 4];
            float4 bx = *(const float4*)&Ws[kk][tx * 4];
            float4 by = *(const float4*)&Ws[kk][64 + tx * 4];
            ull ap[4] = {aA.a, aA.b, aB.a, aB.b};
            ull bd[8] = {dup2(bx.x), dup2(bx.y), dup2(bx.z), dup2(bx.w),
                         dup2(by.x), dup2(by.y), dup2(by.z), dup2(by.w)};
#pragma unroll
            for (int ri = 0; ri < 4; ri++)
#pragma unroll
                for (int j = 0; j < 8; j++)
                    dfma(acc2[ri][j], ap[ri], bd[j]);
        }
        __syncthreads();
    }

    float acc[8][8];
#pragma unroll
    for (int ri = 0; ri < 4; ri++)
#pragma unroll
        for (int j = 0; j < 8; j++)
            unpk(acc2[ri][j], acc[2 * ri][j], acc[2 * ri + 1][j]);

#pragma unroll
    for (int i = 0; i < 8; i++) {
        const size_t r = m0 + (i < 4 ? ty * 4 + i : 64 + ty * 4 + i - 4);
#pragma unroll
        for (int gj = 0; gj < 2; gj++) {
            const int c0 = n0 + gj * 64 + tx * 4;
            float4 prev = *(const float4*)(hin + r * Cc + c0);
            float4 o;
            o.x = prev.x + 0.1f * fast_tanh(acc[i][gj * 4 + 0] + bias[c0 + 0]);
            o.y = prev.y + 0.1f * fast_tanh(acc[i][gj * 4 + 1] + bias[c0 + 1]);
            o.z = prev.z + 0.1f * fast_tanh(acc[i][gj * 4 + 2] + bias[c0 + 2]);
            o.w = prev.w + 0.1f * fast_tanh(acc[i][gj * 4 + 3] + bias[c0 + 3]);
            *(float4*)(hout + r * Cc + c0) = o;
        }
    }
}

// ---------------------------------------------------------------------------
// Proj (NT GEMM + fused residual, transposed write), packed f32x2 FMA.
// out[b,o,s] = x[b,o,s] + sum_c hf2[b*S+s,c]*W[o,c] + bias[o]
// ---------------------------------------------------------------------------
__global__ void __launch_bounds__(256) proj_gemm(const float* __restrict__ W,
                                                 const float* __restrict__ bias,
                                                 const float* __restrict__ x,
                                                 float* __restrict__ out) {
    const float* hin = g_hf2;

    __shared__ __align__(16) float As[8][128];
    __shared__ __align__(16) float Ws[8][128];
    const int n0 = blockIdx.x * 128;
    const int m0 = blockIdx.y * 128;
    const int tid = threadIdx.x;
    const int tx = tid & 15, ty = tid >> 4;
    const int a_m = tid >> 1;
    const int a_k = (tid & 1) * 4;

    const float* Aptr = hin + (size_t)(m0 + a_m) * Cc + a_k;
    const float* Bptr = W + (size_t)(n0 + a_m) * Cc + a_k;

    float4 pa = *(const float4*)Aptr;
    float4 pb = *(const float4*)Bptr;

    ull acc2[4][8] = {};

    for (int k0 = 0; k0 < Cc; k0 += 8) {
        As[a_k + 0][a_m] = pa.x;
        As[a_k + 1][a_m] = pa.y;
        As[a_k + 2][a_m] = pa.z;
        As[a_k + 3][a_m] = pa.w;
        Ws[a_k + 0][a_m] = pb.x;
        Ws[a_k + 1][a_m] = pb.y;
        Ws[a_k + 2][a_m] = pb.z;
        Ws[a_k + 3][a_m] = pb.w;
        __syncthreads();
        if (k0 + 8 < Cc) {
            pa = *(const float4*)(Aptr + k0 + 8);
            pb = *(const float4*)(Bptr + k0 + 8);
        }
#pragma unroll
        for (int kk = 0; kk < 8; kk++) {
            U2 aA = *(const U2*)&As[kk][ty * 4];
            U2 aB = *(const U2*)&As[kk][64 + ty * 4];
            float4 bx = *(const float4*)&Ws[kk][tx * 4];
            float4 by = *(const float4*)&Ws[kk][64 + tx * 4];
            ull ap[4] = {aA.a, aA.b, aB.a, aB.b};
            ull bd[8] = {dup2(bx.x), dup2(bx.y), dup2(bx.z), dup2(bx.w),
                         dup2(by.x), dup2(by.y), dup2(by.z), dup2(by.w)};
#pragma unroll
            for (int ri = 0; ri < 4; ri++)
#pragma unroll
                for (int j = 0; j < 8; j++)
                    dfma(acc2[ri][j], ap[ri], bd[j]);
        }
        __syncthreads();
    }

    float acc[8][8];
#pragma unroll
    for (int ri = 0; ri < 4; ri++)
#pragma unroll
        for (int j = 0; j < 8; j++)
            unpk(acc2[ri][j], acc[2 * ri][j], acc[2 * ri + 1][j]);

    // Transposed epilogue: rows of this tile are (b, s); cols are o.
    const int b = m0 >> 10;   // 128 | 1024 so whole tile is one batch
#pragma unroll
    for (int gj = 0; gj < 2; gj++) {
#pragma unroll
        for (int j = 0; j < 4; j++) {
            const int o = n0 + gj * 64 + tx * 4 + j;
            const float bv = bias[o];
#pragma unroll
            for (int h = 0; h < 2; h++) {
                const int s_base = (m0 & 1023) + h * 64 + ty * 4;
                const size_t idx = ((size_t)b * Cc + o) * Ss + s_base;
                float4 xv = *(const float4*)(x + idx);
                float4 r = make_float4(xv.x + acc[h * 4 + 0][gj * 4 + j] + bv,
                                       xv.y + acc[h * 4 + 1][gj * 4 + j] + bv,
                                       xv.z + acc[h * 4 + 2][gj * 4 + j] + bv,
                                       xv.w + acc[h * 4 + 3][gj * 4 + j] + bv);
                *(float4*)(out + idx) = r;
            }
        }
    }
}

// ---------------------------------------------------------------------------
extern "C" void kernel_launch(void* const* d_in, const int* in_sizes, int n_in,
                              void* d_out, int out_size) {
    const float* x = (const float*)d_in[0];
    const float* gn_scale = (const float*)d_in[1];
    const float* gn_bias = (const float*)d_in[2];
    const float* qkv_w = (const float*)d_in[3];
    const float* qkv_b = (const float*)d_in[4];
    const float* proj_w = (const float*)d_in[5];
    const float* proj_b = (const float*)d_in[6];
    const float* inl_w = (const float*)d_in[7];
    const float* inl_b = (const float*)d_in[8];
    float* out = (float*)d_out;

    // 1. GroupNorm -> g_h
    gn_kernel<<<Bb * 8, 256>>>(x, gn_scale, gn_bias);

    // 2. QKV GEMM -> g_qkv
    qkv_gemm<<<dim3(Ss / 128, M3 / 128, Bb), 256>>>(qkv_w, qkv_b);

    // 3. Attention -> g_hf
    const int attn_smem =
        (64 * 128 + 64 * 64 + 64 * 68 + 128 * 68) * (int)sizeof(float);  // ~99 KB
    cudaFuncSetAttribute(attn_kernel,
                         cudaFuncAttributeMaxDynamicSharedMemorySize, attn_smem);
    attn_kernel<<<dim3(Ss / 128, Bb * NH), 256, attn_smem>>>();

    // 4. INL: 3 Euler steps (ping-pong g_hf <-> g_hf2), ends in g_hf2
    inl_gemm<<<dim3(Cc / 128, Bb * Ss / 128), 256>>>(0, inl_w, inl_b);
    inl_gemm<<<dim3(Cc / 128, Bb * Ss / 128), 256>>>(1, inl_w, inl_b);
    inl_gemm<<<dim3(Cc / 128, Bb * Ss / 128), 256>>>(0, inl_w, inl_b);

    // 5. Proj + residual -> d_out
    proj_gemm<<<dim3(Cc / 128, Bb * Ss / 128), 256>>>(proj_w, proj_b, x, out);
}

// round 7
// speedup vs baseline: 1.1728x; 1.1728x over previous
#include <cuda_runtime.h>
#include <cuda_bf16.h>
#include <math.h>

typedef __nv_bfloat16 bf16;

// Problem constants
constexpr int Bb = 8;
constexpr int Cc = 512;
constexpr int Ss = 1024;     // H*W
constexpr int M3 = 1536;     // 3*C
constexpr int NH = 8;
constexpr int HD = 64;

constexpr int PITCH = 40;    // smem row pitch in bf16 units (32 data + 8 pad)

// Scratch buffers (static device globals; allocation is forbidden)
__device__ __align__(16) bf16 g_h_hi[Bb * Cc * Ss];
__device__ __align__(16) bf16 g_h_lo[Bb * Cc * Ss];
__device__ float g_qkv[Bb * M3 * Ss];          // [b][o][s] fp32
__device__ float g_hf[Bb * Ss * Cc];           // ping fp32
__device__ float g_hf2[Bb * Ss * Cc];          // pong fp32
__device__ __align__(16) bf16 g_hfh0[Bb * Ss * Cc];  // hi of g_hf
__device__ __align__(16) bf16 g_hfl0[Bb * Ss * Cc];  // lo of g_hf
__device__ __align__(16) bf16 g_hfh1[Bb * Ss * Cc];  // hi of g_hf2
__device__ __align__(16) bf16 g_hfl1[Bb * Ss * Cc];  // lo of g_hf2
__device__ __align__(16) bf16 g_wq_hi[M3 * Cc];
__device__ __align__(16) bf16 g_wq_lo[M3 * Cc];
__device__ __align__(16) bf16 g_wi_hi[Cc * Cc];
__device__ __align__(16) bf16 g_wi_lo[Cc * Cc];
__device__ __align__(16) bf16 g_wp_hi[Cc * Cc];
__device__ __align__(16) bf16 g_wp_lo[Cc * Cc];

__device__ __forceinline__ float fast_tanh(float x) {
    x = fminf(fmaxf(x, -15.f), 15.f);
    float e = __expf(2.f * x);
    return __fdividef(e - 1.f, e + 1.f);
}

// Split a pair of fp32 into packed bf16 hi and lo words.
__device__ __forceinline__ void split2(float x, float y, unsigned& hi, unsigned& lo) {
    bf16 hx = __float2bfloat16(x), hy = __float2bfloat16(y);
    float rx = x - __bfloat162float(hx);
    float ry = y - __bfloat162float(hy);
    bf16 lx = __float2bfloat16(rx), ly = __float2bfloat16(ry);
    hi = ((unsigned)__bfloat16_as_ushort(hy) << 16) | (unsigned)__bfloat16_as_ushort(hx);
    lo = ((unsigned)__bfloat16_as_ushort(ly) << 16) | (unsigned)__bfloat16_as_ushort(lx);
}

__device__ __forceinline__ void mma_bf16(float* c, const unsigned* a, const unsigned* b) {
    asm("mma.sync.aligned.m16n8k16.row.col.f32.bf16.bf16.f32 "
        "{%0,%1,%2,%3}, {%4,%5,%6,%7}, {%8,%9}, {%0,%1,%2,%3};"
        : "+f"(c[0]), "+f"(c[1]), "+f"(c[2]), "+f"(c[3])
        : "r"(a[0]), "r"(a[1]), "r"(a[2]), "r"(a[3]), "r"(b[0]), "r"(b[1]));
}

// One k16 step: load frags from smem, issue 3-term split mma for a 64x32 warp tile.
__device__ __forceinline__ void frag_step(
    const bf16* sAhi, const bf16* sAlo, const bf16* sBhi, const bf16* sBlo,
    int wm, int wn, int lane, int ks, float acc[16][4]) {
    const int g = lane >> 2;
    const int c0 = ks * 16 + (lane & 3) * 2;
    unsigned ah[4][4], al[4][4], bh[4][2], bl[4][2];
#pragma unroll
    for (int i = 0; i < 4; i++) {
        const int r1 = (wm + i * 16 + g) * PITCH;
        const int r2 = r1 + 8 * PITCH;
        ah[i][0] = *(const unsigned*)&sAhi[r1 + c0];
        ah[i][1] = *(const unsigned*)&sAhi[r2 + c0];
        ah[i][2] = *(const unsigned*)&sAhi[r1 + c0 + 8];
        ah[i][3] = *(const unsigned*)&sAhi[r2 + c0 + 8];
        al[i][0] = *(const unsigned*)&sAlo[r1 + c0];
        al[i][1] = *(const unsigned*)&sAlo[r2 + c0];
        al[i][2] = *(const unsigned*)&sAlo[r1 + c0 + 8];
        al[i][3] = *(const unsigned*)&sAlo[r2 + c0 + 8];
    }
#pragma unroll
    for (int j = 0; j < 4; j++) {
        const int n = (wn + j * 8 + g) * PITCH;
        bh[j][0] = *(const unsigned*)&sBhi[n + c0];
        bh[j][1] = *(const unsigned*)&sBhi[n + c0 + 8];
        bl[j][0] = *(const unsigned*)&sBlo[n + c0];
        bl[j][1] = *(const unsigned*)&sBlo[n + c0 + 8];
    }
#pragma unroll
    for (int i = 0; i < 4; i++)
#pragma unroll
        for (int j = 0; j < 4; j++) {
            mma_bf16(acc[i * 4 + j], ah[i], bh[j]);
            mma_bf16(acc[i * 4 + j], ah[i], bl[j]);
            mma_bf16(acc[i * 4 + j], al[i], bh[j]);
        }
}

// ---------------------------------------------------------------------------
// Weight convert: fp32 -> bf16 hi/lo
// ---------------------------------------------------------------------------
__global__ void convw(const float* __restrict__ src, bf16* __restrict__ hi,
                      bf16* __restrict__ lo, int n) {
    int i = (blockIdx.x * 256 + threadIdx.x) * 4;
    if (i < n) {
        float4 v = *(const float4*)(src + i);
        uint2 uh, ul;
        split2(v.x, v.y, uh.x, ul.x);
        split2(v.z, v.w, uh.y, ul.y);
        *(uint2*)(hi + i) = uh;
        *(uint2*)(lo + i) = ul;
    }
}

// ---------------------------------------------------------------------------
// GroupNorm: one block per (b, group). Writes bf16 hi/lo of h, layout [b][c][s].
// ---------------------------------------------------------------------------
__global__ void gn_kernel(const float* __restrict__ x,
                          const float* __restrict__ scale,
                          const float* __restrict__ bias) {
    const int b = blockIdx.x >> 3;
    const int g = blockIdx.x & 7;
    const int N = 64 * Ss;  // 65536
    const size_t base = (size_t)b * Cc * Ss + (size_t)g * 64 * Ss;
    const float* xp = x + base;

    float s = 0.f, s2 = 0.f;
    for (int i = threadIdx.x * 4; i < N; i += 1024) {
        float4 v = *(const float4*)(xp + i);
        s += v.x + v.y + v.z + v.w;
        s2 += v.x * v.x + v.y * v.y + v.z * v.z + v.w * v.w;
    }
    __shared__ float rs[256], rs2[256];
    rs[threadIdx.x] = s; rs2[threadIdx.x] = s2;
    __syncthreads();
    for (int o = 128; o > 0; o >>= 1) {
        if (threadIdx.x < o) {
            rs[threadIdx.x] += rs[threadIdx.x + o];
            rs2[threadIdx.x] += rs2[threadIdx.x + o];
        }
        __syncthreads();
    }
    const float mean = rs[0] / N;
    float var = rs2[0] / N - mean * mean;
    var = fmaxf(var, 0.f);
    const float rstd = rsqrtf(var + 1e-5f);

    for (int i = threadIdx.x * 4; i < N; i += 1024) {
        int c = g * 64 + (i >> 10);
        const float a = rstd * scale[c];
        const float bb2 = bias[c] - mean * a;
        float4 v = *(const float4*)(xp + i);
        float4 r = make_float4(v.x * a + bb2, v.y * a + bb2,
                               v.z * a + bb2, v.w * a + bb2);
        uint2 uh, ul;
        split2(r.x, r.y, uh.x, ul.x);
        split2(r.z, r.w, uh.y, ul.y);
        *(uint2*)(g_h_hi + base + i) = uh;
        *(uint2*)(g_h_lo + base + i) = ul;
    }
}

// ---------------------------------------------------------------------------
// QKV GEMM (NN) via tensor cores, 3-term bf16 split.
// qkv[b,m,n] = sum_k W[m,k] * h[b,k,n] + bias[m]
// CTA tile 128x128, BK=32, 8 warps (2x4), warp tile 64x32.
// ---------------------------------------------------------------------------
__global__ void __launch_bounds__(256) qkv_mma(const float* __restrict__ bias) {
    __shared__ __align__(16) bf16 sAhi[128 * PITCH];
    __shared__ __align__(16) bf16 sAlo[128 * PITCH];
    __shared__ __align__(16) bf16 sBhi[128 * PITCH];
    __shared__ __align__(16) bf16 sBlo[128 * PITCH];

    const int b = blockIdx.z;
    const int n0 = blockIdx.x * 128;
    const int m0 = blockIdx.y * 128;
    const int tid = threadIdx.x;
    const int lane = tid & 31;
    const int wid = tid >> 5;
    const int wm = (wid >> 2) * 64, wn = (wid & 3) * 32;

    const bf16* Hhi = g_h_hi + (size_t)b * Cc * Ss;
    const bf16* Hlo = g_h_lo + (size_t)b * Cc * Ss;

    // A staging: thread -> row r, 16 k's at kq (two uint4 each for hi/lo)
    const int r = tid >> 1, kq = (tid & 1) * 16;
    const bf16* pAh = g_wq_hi + (size_t)(m0 + r) * Cc + kq;
    const bf16* pAl = g_wq_lo + (size_t)(m0 + r) * Cc + kq;

    float acc[16][4] = {};

    uint4 nAh0 = *(const uint4*)pAh, nAh1 = *(const uint4*)(pAh + 8);
    uint4 nAl0 = *(const uint4*)pAl, nAl1 = *(const uint4*)(pAl + 8);
    unsigned nh0[4], nh1[4], nl0[4], nl1[4];
#pragma unroll
    for (int q = 0; q < 4; q++) {
        int bi = tid + q * 256;
        int kb = bi >> 6, nb = bi & 63;
        const bf16* ph = Hhi + (size_t)(2 * kb) * Ss + n0 + 2 * nb;
        const bf16* pl = Hlo + (size_t)(2 * kb) * Ss + n0 + 2 * nb;
        nh0[q] = *(const unsigned*)ph; nh1[q] = *(const unsigned*)(ph + Ss);
        nl0[q] = *(const unsigned*)pl; nl1[q] = *(const unsigned*)(pl + Ss);
    }

    for (int k0 = 0; k0 < Cc; k0 += 32) {
        *(uint4*)&sAhi[r * PITCH + kq] = nAh0;
        *(uint4*)&sAhi[r * PITCH + kq + 8] = nAh1;
        *(uint4*)&sAlo[r * PITCH + kq] = nAl0;
        *(uint4*)&sAlo[r * PITCH + kq + 8] = nAl1;
#pragma unroll
        for (int q = 0; q < 4; q++) {
            int bi = tid + q * 256;
            int kb = bi >> 6, nb = bi & 63;
            *(unsigned*)&sBhi[(2 * nb) * PITCH + 2 * kb] = __byte_perm(nh0[q], nh1[q], 0x5410);
            *(unsigned*)&sBhi[(2 * nb + 1) * PITCH + 2 * kb] = __byte_perm(nh0[q], nh1[q], 0x7632);
            *(unsigned*)&sBlo[(2 * nb) * PITCH + 2 * kb] = __byte_perm(nl0[q], nl1[q], 0x5410);
            *(unsigned*)&sBlo[(2 * nb + 1) * PITCH + 2 * kb] = __byte_perm(nl0[q], nl1[q], 0x7632);
        }
        __syncthreads();
        if (k0 + 32 < Cc) {
            nAh0 = *(const uint4*)(pAh + k0 + 32);
            nAh1 = *(const uint4*)(pAh + k0 + 40);
            nAl0 = *(const uint4*)(pAl + k0 + 32);
            nAl1 = *(const uint4*)(pAl + k0 + 40);
#pragma unroll
            for (int q = 0; q < 4; q++) {
                int bi = tid + q * 256;
                int kb = bi >> 6, nb = bi & 63;
                const bf16* ph = Hhi + (size_t)(k0 + 32 + 2 * kb) * Ss + n0 + 2 * nb;
                const bf16* pl = Hlo + (size_t)(k0 + 32 + 2 * kb) * Ss + n0 + 2 * nb;
                nh0[q] = *(const unsigned*)ph; nh1[q] = *(const unsigned*)(ph + Ss);
                nl0[q] = *(const unsigned*)pl; nl1[q] = *(const unsigned*)(pl + Ss);
            }
        }
        frag_step(sAhi, sAlo, sBhi, sBlo, wm, wn, lane, 0, acc);
        frag_step(sAhi, sAlo, sBhi, sBlo, wm, wn, lane, 1, acc);
        __syncthreads();
    }

    // Epilogue: C[m][n] + bias[m] -> g_qkv[b][m][n]
    float* out = g_qkv + (size_t)b * M3 * Ss;
    const int g2 = lane >> 2, tq = (lane & 3) * 2;
#pragma unroll
    for (int i = 0; i < 4; i++) {
        const int m1 = m0 + wm + i * 16 + g2;
        const float bv1 = bias[m1], bv2 = bias[m1 + 8];
#pragma unroll
        for (int j = 0; j < 4; j++) {
            const int n = n0 + wn + j * 8 + tq;
            float* c = acc[i * 4 + j];
            *(float2*)(out + (size_t)m1 * Ss + n) = make_float2(c[0] + bv1, c[1] + bv1);
            *(float2*)(out + (size_t)(m1 + 8) * Ss + n) = make_float2(c[2] + bv2, c[3] + bv2);
        }
    }
}

// ---------------------------------------------------------------------------
// Attention (flash-style, fp32 scalar). Writes fp32 + bf16 hi/lo.
// ---------------------------------------------------------------------------
__global__ void attn_kernel() {
    extern __shared__ float sm[];
    float* Qs = sm;                  // [64 d][128 s]
    float* Ks = Qs + 64 * 128;       // [64 d][64 t]
    float* Vst = Ks + 64 * 64;       // [64 t][68]
    float* Ps = Vst + 64 * 68;       // [128 s][68]

    const int tid = threadIdx.x;
    const int tx = tid & 15, ty = tid >> 4;
    const int b = blockIdx.y >> 3;
    const int hh = blockIdx.y & 7;
    const int s0 = blockIdx.x * 128;

    const float* qk = g_qkv + (size_t)b * M3 * Ss;
    const float* Qg = qk + (size_t)(hh * HD) * Ss + s0;
    const float* Kg = qk + (size_t)(Cc + hh * HD) * Ss;
    const float* Vg = qk + (size_t)(2 * Cc + hh * HD) * Ss;

#pragma unroll
    for (int r = 0; r < 32; r++) {
        int idx = r * 256 + tid;
        int d = idx >> 7, ss = idx & 127;
        Qs[idx] = Qg[(size_t)d * Ss + ss] * 0.125f;
    }

    float m_i[8], l_i[8];
#pragma unroll
    for (int i = 0; i < 8; i++) { m_i[i] = -1e30f; l_i[i] = 0.f; }
    float accO[8][4] = {};

    int row[8];
#pragma unroll
    for (int i = 0; i < 8; i++)
        row[i] = (i < 4 ? ty * 4 + i : 64 + ty * 4 + i - 4);

    __syncthreads();

    for (int t0 = 0; t0 < Ss; t0 += 64) {
#pragma unroll
        for (int r = 0; r < 16; r++) {
            int idx = r * 256 + tid;
            int d = idx >> 6, tt = idx & 63;
            Ks[idx] = Kg[(size_t)d * Ss + t0 + tt];
            Vst[tt * 68 + d] = Vg[(size_t)d * Ss + t0 + tt];
        }
        __syncthreads();

        float sc[8][4] = {};
#pragma unroll 8
        for (int kk = 0; kk < 64; kk++) {
            float a8[8], b4[4];
            *(float4*)&a8[0] = *(const float4*)&Qs[kk * 128 + ty * 4];
            *(float4*)&a8[4] = *(const float4*)&Qs[kk * 128 + 64 + ty * 4];
            *(float4*)b4 = *(const float4*)&Ks[kk * 64 + tx * 4];
#pragma unroll
            for (int i = 0; i < 8; i++)
#pragma unroll
                for (int j = 0; j < 4; j++)
                    sc[i][j] += a8[i] * b4[j];
        }

        float corr[8];
#pragma unroll
        for (int i = 0; i < 8; i++) {
            float tm = fmaxf(fmaxf(sc[i][0], sc[i][1]), fmaxf(sc[i][2], sc[i][3]));
#pragma unroll
            for (int off = 8; off >= 1; off >>= 1)
                tm = fmaxf(tm, __shfl_xor_sync(0xffffffffu, tm, off));
            const float nm = fmaxf(m_i[i], tm);
            corr[i] = __expf(m_i[i] - nm);
            float pv[4], ps = 0.f;
#pragma unroll
            for (int j = 0; j < 4; j++) { pv[j] = __expf(sc[i][j] - nm); ps += pv[j]; }
            *(float4*)&Ps[row[i] * 68 + tx * 4] =
                make_float4(pv[0], pv[1], pv[2], pv[3]);
#pragma unroll
            for (int off = 8; off >= 1; off >>= 1)
                ps += __shfl_xor_sync(0xffffffffu, ps, off);
            l_i[i] = l_i[i] * corr[i] + ps;
            m_i[i] = nm;
        }
        __syncthreads();

#pragma unroll
        for (int i = 0; i < 8; i++)
#pragma unroll
            for (int j = 0; j < 4; j++) accO[i][j] *= corr[i];

        const int d4 = tx * 4;
#pragma unroll 2
        for (int kk = 0; kk < 64; kk += 4) {
            float4 v[4], p[8];
#pragma unroll
            for (int q = 0; q < 4; q++)
                v[q] = *(const float4*)&Vst[(kk + q) * 68 + d4];
#pragma unroll
            for (int i = 0; i < 8; i++)
                p[i] = *(const float4*)&Ps[row[i] * 68 + kk];
#pragma unroll
            for (int i = 0; i < 8; i++) {
                accO[i][0] += p[i].x * v[0].x + p[i].y * v[1].x + p[i].z * v[2].x + p[i].w * v[3].x;
                accO[i][1] += p[i].x * v[0].y + p[i].y * v[1].y + p[i].z * v[2].y + p[i].w * v[3].y;
                accO[i][2] += p[i].x * v[0].z + p[i].y * v[1].z + p[i].z * v[2].z + p[i].w * v[3].z;
                accO[i][3] += p[i].x * v[0].w + p[i].y * v[1].w + p[i].z * v[2].w + p[i].w * v[3].w;
            }
        }
        __syncthreads();
    }

    const size_t obase = ((size_t)b * Ss + s0) * Cc + hh * HD;
#pragma unroll
    for (int i = 0; i < 8; i++) {
        const float inv = __fdividef(1.f, l_i[i]);
        float4 r = make_float4(accO[i][0] * inv, accO[i][1] * inv,
                               accO[i][2] * inv, accO[i][3] * inv);
        const size_t idx = obase + (size_t)row[i] * Cc + tx * 4;
        *(float4*)(g_hf + idx) = r;
        uint2 uh, ul;
        split2(r.x, r.y, uh.x, ul.x);
        split2(r.z, r.w, uh.y, ul.y);
        *(uint2*)(g_hfh0 + idx) = uh;
        *(uint2*)(g_hfl0 + idx) = ul;
    }
}

// ---------------------------------------------------------------------------
// INL step (NT tensor-core GEMM + fused Euler/tanh epilogue):
// hout[r,o] = hin[r,o] + 0.1*tanh(sum_c hin[r,c]*W[o,c] + bias[o])
// ---------------------------------------------------------------------------
__global__ void __launch_bounds__(256) inl_mma(int src, const float* __restrict__ bias) {
    __shared__ __align__(16) bf16 sAhi[128 * PITCH];
    __shared__ __align__(16) bf16 sAlo[128 * PITCH];
    __shared__ __align__(16) bf16 sBhi[128 * PITCH];
    __shared__ __align__(16) bf16 sBlo[128 * PITCH];

    const float* hin = src ? g_hf2 : g_hf;
    float* hout = src ? g_hf : g_hf2;
    const bf16* Ahi = src ? g_hfh1 : g_hfh0;
    const bf16* Alo = src ? g_hfl1 : g_hfl0;
    bf16* outh = src ? g_hfh0 : g_hfh1;
    bf16* outl = src ? g_hfl0 : g_hfl1;

    const int n0 = blockIdx.x * 128;
    const int m0 = blockIdx.y * 128;
    const int tid = threadIdx.x;
    const int lane = tid & 31;
    const int wid = tid >> 5;
    const int wm = (wid >> 2) * 64, wn = (wid & 3) * 32;

    const int r = tid >> 1, kq = (tid & 1) * 16;
    const bf16* pAh = Ahi + (size_t)(m0 + r) * Cc + kq;
    const bf16* pAl = Alo + (size_t)(m0 + r) * Cc + kq;
    const bf16* pBh = g_wi_hi + (size_t)(n0 + r) * Cc + kq;
    const bf16* pBl = g_wi_lo + (size_t)(n0 + r) * Cc + kq;

    float acc[16][4] = {};

    uint4 nAh0 = *(const uint4*)pAh, nAh1 = *(const uint4*)(pAh + 8);
    uint4 nAl0 = *(const uint4*)pAl, nAl1 = *(const uint4*)(pAl + 8);
    uint4 nBh0 = *(const uint4*)pBh, nBh1 = *(const uint4*)(pBh + 8);
    uint4 nBl0 = *(const uint4*)pBl, nBl1 = *(const uint4*)(pBl + 8);

    for (int k0 = 0; k0 < Cc; k0 += 32) {
        *(uint4*)&sAhi[r * PITCH + kq] = nAh0;
        *(uint4*)&sAhi[r * PITCH + kq + 8] = nAh1;
        *(uint4*)&sAlo[r * PITCH + kq] = nAl0;
        *(uint4*)&sAlo[r * PITCH + kq + 8] = nAl1;
        *(uint4*)&sBhi[r * PITCH + kq] = nBh0;
        *(uint4*)&sBhi[r * PITCH + kq + 8] = nBh1;
        *(uint4*)&sBlo[r * PITCH + kq] = nBl0;
        *(uint4*)&sBlo[r * PITCH + kq + 8] = nBl1;
        __syncthreads();
        if (k0 + 32 < Cc) {
            nAh0 = *(const uint4*)(pAh + k0 + 32);
            nAh1 = *(const uint4*)(pAh + k0 + 40);
            nAl0 = *(const uint4*)(pAl + k0 + 32);
            nAl1 = *(const uint4*)(pAl + k0 + 40);
            nBh0 = *(const uint4*)(pBh + k0 + 32);
            nBh1 = *(const uint4*)(pBh + k0 + 40);
            nBl0 = *(const uint4*)(pBl + k0 + 32);
            nBl1 = *(const uint4*)(pBl + k0 + 40);
        }
        frag_step(sAhi, sAlo, sBhi, sBlo, wm, wn, lane, 0, acc);
        frag_step(sAhi, sAlo, sBhi, sBlo, wm, wn, lane, 1, acc);
        __syncthreads();
    }

    const int g2 = lane >> 2, tq = (lane & 3) * 2;
#pragma unroll
    for (int i = 0; i < 4; i++) {
        const int r1 = m0 + wm + i * 16 + g2;
#pragma unroll
        for (int j = 0; j < 4; j++) {
            const int o = n0 + wn + j * 8 + tq;
            const float b0 = bias[o], b1 = bias[o + 1];
            float* c = acc[i * 4 + j];
#pragma unroll
            for (int h = 0; h < 2; h++) {
                const size_t rr = (size_t)(r1 + h * 8) * Cc + o;
                float2 prev = *(const float2*)(hin + rr);
                float v0 = prev.x + 0.1f * fast_tanh(c[h * 2 + 0] + b0);
                float v1 = prev.y + 0.1f * fast_tanh(c[h * 2 + 1] + b1);
                *(float2*)(hout + rr) = make_float2(v0, v1);
                unsigned uh, ul;
                split2(v0, v1, uh, ul);
                *(unsigned*)(outh + rr) = uh;
                *(unsigned*)(outl + rr) = ul;
            }
        }
    }
}

// ---------------------------------------------------------------------------
// Proj (NT tensor-core GEMM + fused residual, transposed write):
// out[b,o,s] = x[b,o,s] + sum_c hf2[b*S+s,c]*W[o,c] + bias[o]
// ---------------------------------------------------------------------------
__global__ void __launch_bounds__(256) proj_mma(const float* __restrict__ bias,
                                                const float* __restrict__ x,
                                                float* __restrict__ out) {
    __shared__ __align__(16) bf16 sAhi[128 * PITCH];
    __shared__ __align__(16) bf16 sAlo[128 * PITCH];
    __shared__ __align__(16) bf16 sBhi[128 * PITCH];
    __shared__ __align__(16) bf16 sBlo[128 * PITCH];

    const int n0 = blockIdx.x * 128;
    const int m0 = blockIdx.y * 128;
    const int tid = threadIdx.x;
    const int lane = tid & 31;
    const int wid = tid >> 5;
    const int wm = (wid >> 2) * 64, wn = (wid & 3) * 32;

    const int r = tid >> 1, kq = (tid & 1) * 16;
    const bf16* pAh = g_hfh1 + (size_t)(m0 + r) * Cc + kq;
    const bf16* pAl = g_hfl1 + (size_t)(m0 + r) * Cc + kq;
    const bf16* pBh = g_wp_hi + (size_t)(n0 + r) * Cc + kq;
    const bf16* pBl = g_wp_lo + (size_t)(n0 + r) * Cc + kq;

    float acc[16][4] = {};

    uint4 nAh0 = *(const uint4*)pAh, nAh1 = *(const uint4*)(pAh + 8);
    uint4 nAl0 = *(const uint4*)pAl, nAl1 = *(const uint4*)(pAl + 8);
    uint4 nBh0 = *(const uint4*)pBh, nBh1 = *(const uint4*)(pBh + 8);
    uint4 nBl0 = *(const uint4*)pBl, nBl1 = *(const uint4*)(pBl + 8);

    for (int k0 = 0; k0 < Cc; k0 += 32) {
        *(uint4*)&sAhi[r * PITCH + kq] = nAh0;
        *(uint4*)&sAhi[r * PITCH + kq + 8] = nAh1;
        *(uint4*)&sAlo[r * PITCH + kq] = nAl0;
        *(uint4*)&sAlo[r * PITCH + kq + 8] = nAl1;
        *(uint4*)&sBhi[r * PITCH + kq] = nBh0;
        *(uint4*)&sBhi[r * PITCH + kq + 8] = nBh1;
        *(uint4*)&sBlo[r * PITCH + kq] = nBl0;
        *(uint4*)&sBlo[r * PITCH + kq + 8] = nBl1;
        __syncthreads();
        if (k0 + 32 < Cc) {
            nAh0 = *(const uint4*)(pAh + k0 + 32);
            nAh1 = *(const uint4*)(pAh + k0 + 40);
            nAl0 = *(const uint4*)(pAl + k0 + 32);
            nAl1 = *(const uint4*)(pAl + k0 + 40);
            nBh0 = *(const uint4*)(pBh + k0 + 32);
            nBh1 = *(const uint4*)(pBh + k0 + 40);
            nBl0 = *(const uint4*)(pBl + k0 + 32);
            nBl1 = *(const uint4*)(pBl + k0 + 40);
        }
        frag_step(sAhi, sAlo, sBhi, sBlo, wm, wn, lane, 0, acc);
        frag_step(sAhi, sAlo, sBhi, sBlo, wm, wn, lane, 1, acc);
        __syncthreads();
    }

    // Epilogue: rows are (b, s) pairs; cols are o. out[b][o][s] = x + C + bias
    const int g2 = lane >> 2, tq = (lane & 3) * 2;
    const int b = m0 >> 10;  // 128 | 1024: tile within one batch
#pragma unroll
    for (int i = 0; i < 4; i++) {
        const int s1 = (m0 & 1023) + wm + i * 16 + g2;
#pragma unroll
        for (int j = 0; j < 4; j++) {
            const int o = n0 + wn + j * 8 + tq;
            const float b0 = bias[o], b1 = bias[o + 1];
            float* c = acc[i * 4 + j];
#pragma unroll
            for (int h = 0; h < 2; h++) {
                const int s = s1 + h * 8;
                const size_t i0 = ((size_t)b * Cc + o) * Ss + s;
                const size_t i1 = i0 + Ss;  // o+1
                out[i0] = x[i0] + c[h * 2 + 0] + b0;
                out[i1] = x[i1] + c[h * 2 + 1] + b1;
            }
        }
    }
}

// ---------------------------------------------------------------------------
extern "C" void kernel_launch(void* const* d_in, const int* in_sizes, int n_in,
                              void* d_out, int out_size) {
    const float* x = (const float*)d_in[0];
    const float* gn_scale = (const float*)d_in[1];
    const float* gn_bias = (const float*)d_in[2];
    const float* qkv_w = (const float*)d_in[3];
    const float* qkv_b = (const float*)d_in[4];
    const float* proj_w = (const float*)d_in[5];
    const float* proj_b = (const float*)d_in[6];
    const float* inl_w = (const float*)d_in[7];
    const float* inl_b = (const float*)d_in[8];
    float* out = (float*)d_out;

    // 0. Convert weights to bf16 hi/lo
    bf16 *wq_hi, *wq_lo, *wi_hi, *wi_lo, *wp_hi, *wp_lo;
    cudaGetSymbolAddress((void**)&wq_hi, g_wq_hi);
    cudaGetSymbolAddress((void**)&wq_lo, g_wq_lo);
    cudaGetSymbolAddress((void**)&wi_hi, g_wi_hi);
    cudaGetSymbolAddress((void**)&wi_lo, g_wi_lo);
    cudaGetSymbolAddress((void**)&wp_hi, g_wp_hi);
    cudaGetSymbolAddress((void**)&wp_lo, g_wp_lo);
    convw<<<(M3 * Cc) / 1024, 256>>>(qkv_w, wq_hi, wq_lo, M3 * Cc);
    convw<<<(Cc * Cc) / 1024, 256>>>(inl_w, wi_hi, wi_lo, Cc * Cc);
    convw<<<(Cc * Cc) / 1024, 256>>>(proj_w, wp_hi, wp_lo, Cc * Cc);

    // 1. GroupNorm -> g_h_hi/lo (bf16 split)
    gn_kernel<<<Bb * 8, 256>>>(x, gn_scale, gn_bias);

    // 2. QKV GEMM (tensor cores) -> g_qkv fp32
    qkv_mma<<<dim3(Ss / 128, M3 / 128, Bb), 256>>>(qkv_b);

    // 3. Attention -> g_hf fp32 + bf16 split
    const int attn_smem =
        (64 * 128 + 64 * 64 + 64 * 68 + 128 * 68) * (int)sizeof(float);  // ~99 KB
    cudaFuncSetAttribute(attn_kernel,
                         cudaFuncAttributeMaxDynamicSharedMemorySize, attn_smem);
    attn_kernel<<<dim3(Ss / 128, Bb * NH), 256, attn_smem>>>();

    // 4. INL: 3 Euler steps (ping-pong), ends in g_hf2 + g_hfh1/g_hfl1
    inl_mma<<<dim3(Cc / 128, Bb * Ss / 128), 256>>>(0, inl_b);
    inl_mma<<<dim3(Cc / 128, Bb * Ss / 128), 256>>>(1, inl_b);
    inl_mma<<<dim3(Cc / 128, Bb * Ss / 128), 256>>>(0, inl_b);

    // 5. Proj + residual -> d_out
    proj_mma<<<dim3(Cc / 128, Bb * Ss / 128), 256>>>(proj_b, x, out);
}

// round 8
// speedup vs baseline: 1.4825x; 1.2641x over previous
#include <cuda_runtime.h>
#include <cuda_bf16.h>
#include <math.h>

typedef __nv_bfloat16 bf16;

// Problem constants
constexpr int Bb = 8;
constexpr int Cc = 512;
constexpr int Ss = 1024;     // H*W
constexpr int M3 = 1536;     // 3*C
constexpr int NH = 8;
constexpr int HD = 64;

constexpr int PITCH = 40;    // dense-GEMM smem row pitch (32 data + 8 pad)
constexpr int APITCH = 72;   // attention smem row pitch (64 data + 8 pad)

// Scratch buffers (static device globals; allocation is forbidden)
__device__ __align__(16) bf16 g_h_hi[Bb * Cc * Ss];
__device__ __align__(16) bf16 g_h_lo[Bb * Cc * Ss];
__device__ float g_qkv[Bb * M3 * Ss];          // [b][o][s] fp32
__device__ float g_hf[Bb * Ss * Cc];           // ping fp32
__device__ float g_hf2[Bb * Ss * Cc];          // pong fp32
__device__ __align__(16) bf16 g_hfh0[Bb * Ss * Cc];
__device__ __align__(16) bf16 g_hfl0[Bb * Ss * Cc];
__device__ __align__(16) bf16 g_hfh1[Bb * Ss * Cc];
__device__ __align__(16) bf16 g_hfl1[Bb * Ss * Cc];
__device__ __align__(16) bf16 g_wq_hi[M3 * Cc];
__device__ __align__(16) bf16 g_wq_lo[M3 * Cc];
__device__ __align__(16) bf16 g_wi_hi[Cc * Cc];
__device__ __align__(16) bf16 g_wi_lo[Cc * Cc];
__device__ __align__(16) bf16 g_wp_hi[Cc * Cc];
__device__ __align__(16) bf16 g_wp_lo[Cc * Cc];
// Attention operand layouts (split bf16)
__device__ __align__(16) bf16 g_qh[Bb * NH * Ss * HD];  // [bh][s][d], scaled
__device__ __align__(16) bf16 g_ql[Bb * NH * Ss * HD];
__device__ __align__(16) bf16 g_kh[Bb * NH * Ss * HD];  // [bh][t][d]
__device__ __align__(16) bf16 g_kl[Bb * NH * Ss * HD];
__device__ __align__(16) bf16 g_vh[Bb * NH * HD * Ss];  // [bh][d][t]
__device__ __align__(16) bf16 g_vl[Bb * NH * HD * Ss];
__device__ float g_gnp[512][2];                          // groupnorm partials

__device__ __forceinline__ float fast_tanh(float x) {
    x = fminf(fmaxf(x, -15.f), 15.f);
    float e = __expf(2.f * x);
    return __fdividef(e - 1.f, e + 1.f);
}

// Split a pair of fp32 into packed bf16 hi and lo words (elem0 in low half).
__device__ __forceinline__ void split2(float x, float y, unsigned& hi, unsigned& lo) {
    bf16 hx = __float2bfloat16(x), hy = __float2bfloat16(y);
    float rx = x - __bfloat162float(hx);
    float ry = y - __bfloat162float(hy);
    bf16 lx = __float2bfloat16(rx), ly = __float2bfloat16(ry);
    hi = ((unsigned)__bfloat16_as_ushort(hy) << 16) | (unsigned)__bfloat16_as_ushort(hx);
    lo = ((unsigned)__bfloat16_as_ushort(ly) << 16) | (unsigned)__bfloat16_as_ushort(lx);
}

__device__ __forceinline__ void mma_bf16(float* c, const unsigned* a, const unsigned* b) {
    asm("mma.sync.aligned.m16n8k16.row.col.f32.bf16.bf16.f32 "
        "{%0,%1,%2,%3}, {%4,%5,%6,%7}, {%8,%9}, {%0,%1,%2,%3};"
        : "+f"(c[0]), "+f"(c[1]), "+f"(c[2]), "+f"(c[3])
        : "r"(a[0]), "r"(a[1]), "r"(a[2]), "r"(a[3]), "r"(b[0]), "r"(b[1]));
}

// One k16 step for the dense GEMMs (validated in Round 7).
__device__ __forceinline__ void frag_step(
    const bf16* sAhi, const bf16* sAlo, const bf16* sBhi, const bf16* sBlo,
    int wm, int wn, int lane, int ks, float acc[16][4]) {
    const int g = lane >> 2;
    const int c0 = ks * 16 + (lane & 3) * 2;
    unsigned ah[4][4], al[4][4], bh[4][2], bl[4][2];
#pragma unroll
    for (int i = 0; i < 4; i++) {
        const int r1 = (wm + i * 16 + g) * PITCH;
        const int r2 = r1 + 8 * PITCH;
        ah[i][0] = *(const unsigned*)&sAhi[r1 + c0];
        ah[i][1] = *(const unsigned*)&sAhi[r2 + c0];
        ah[i][2] = *(const unsigned*)&sAhi[r1 + c0 + 8];
        ah[i][3] = *(const unsigned*)&sAhi[r2 + c0 + 8];
        al[i][0] = *(const unsigned*)&sAlo[r1 + c0];
        al[i][1] = *(const unsigned*)&sAlo[r2 + c0];
        al[i][2] = *(const unsigned*)&sAlo[r1 + c0 + 8];
        al[i][3] = *(const unsigned*)&sAlo[r2 + c0 + 8];
    }
#pragma unroll
    for (int j = 0; j < 4; j++) {
        const int n = (wn + j * 8 + g) * PITCH;
        bh[j][0] = *(const unsigned*)&sBhi[n + c0];
        bh[j][1] = *(const unsigned*)&sBhi[n + c0 + 8];
        bl[j][0] = *(const unsigned*)&sBlo[n + c0];
        bl[j][1] = *(const unsigned*)&sBlo[n + c0 + 8];
    }
#pragma unroll
    for (int i = 0; i < 4; i++)
#pragma unroll
        for (int j = 0; j < 4; j++) {
            mma_bf16(acc[i * 4 + j], ah[i], bh[j]);
            mma_bf16(acc[i * 4 + j], ah[i], bl[j]);
            mma_bf16(acc[i * 4 + j], al[i], bh[j]);
        }
}

// ---------------------------------------------------------------------------
// Weight convert: fp32 -> bf16 hi/lo
// ---------------------------------------------------------------------------
__global__ void convw(const float* __restrict__ src, bf16* __restrict__ hi,
                      bf16* __restrict__ lo, int n) {
    int i = (blockIdx.x * 256 + threadIdx.x) * 4;
    if (i < n) {
        float4 v = *(const float4*)(src + i);
        uint2 uh, ul;
        split2(v.x, v.y, uh.x, ul.x);
        split2(v.z, v.w, uh.y, ul.y);
        *(uint2*)(hi + i) = uh;
        *(uint2*)(lo + i) = ul;
    }
}

// ---------------------------------------------------------------------------
// GroupNorm phase 1: partial sums. grid 512 = (group 64) x (slice 8).
// ---------------------------------------------------------------------------
__global__ void gn_stats(const float* __restrict__ x) {
    const int grp = blockIdx.x >> 3;
    const int slice = blockIdx.x & 7;
    const float* xp = x + (size_t)grp * 65536 + slice * 8192;
    float s = 0.f, s2 = 0.f;
#pragma unroll
    for (int r = 0; r < 8; r++) {
        float4 v = *(const float4*)(xp + (threadIdx.x + r * 256) * 4);
        s += v.x + v.y + v.z + v.w;
        s2 += v.x * v.x + v.y * v.y + v.z * v.z + v.w * v.w;
    }
    __shared__ float rs[256], rs2[256];
    rs[threadIdx.x] = s; rs2[threadIdx.x] = s2;
    __syncthreads();
    for (int o = 128; o > 0; o >>= 1) {
        if (threadIdx.x < o) {
            rs[threadIdx.x] += rs[threadIdx.x + o];
            rs2[threadIdx.x] += rs2[threadIdx.x + o];
        }
        __syncthreads();
    }
    if (threadIdx.x == 0) {
        g_gnp[blockIdx.x][0] = rs[0];
        g_gnp[blockIdx.x][1] = rs2[0];
    }
}

// ---------------------------------------------------------------------------
// GroupNorm phase 2: finalize + apply, writes bf16 hi/lo. grid 512.
// ---------------------------------------------------------------------------
__global__ void gn_apply(const float* __restrict__ x,
                         const float* __restrict__ scale,
                         const float* __restrict__ bias) {
    const int grp = blockIdx.x >> 3;
    const int slice = blockIdx.x & 7;
    float s = 0.f, s2 = 0.f;
#pragma unroll
    for (int p = 0; p < 8; p++) { s += g_gnp[grp * 8 + p][0]; s2 += g_gnp[grp * 8 + p][1]; }
    const float mean = s / 65536.f;
    float var = s2 / 65536.f - mean * mean;
    var = fmaxf(var, 0.f);
    const float rstd = rsqrtf(var + 1e-5f);

    const size_t base = (size_t)grp * 65536 + slice * 8192;
    const int cbase = (grp & 7) * 64 + slice * 8;  // 8192 elems = 8 channels
#pragma unroll
    for (int r = 0; r < 8; r++) {
        const int k = (threadIdx.x + r * 256) * 4;
        const int c = cbase + (k >> 10);
        const float a = rstd * scale[c];
        const float bb2 = bias[c] - mean * a;
        float4 v = *(const float4*)(x + base + k);
        float4 o = make_float4(v.x * a + bb2, v.y * a + bb2,
                               v.z * a + bb2, v.w * a + bb2);
        uint2 uh, ul;
        split2(o.x, o.y, uh.x, ul.x);
        split2(o.z, o.w, uh.y, ul.y);
        *(uint2*)(g_h_hi + base + k) = uh;
        *(uint2*)(g_h_lo + base + k) = ul;
    }
}

// ---------------------------------------------------------------------------
// QKV GEMM (NN) via tensor cores (validated Round 7).
// ---------------------------------------------------------------------------
__global__ void __launch_bounds__(256) qkv_mma(const float* __restrict__ bias) {
    __shared__ __align__(16) bf16 sAhi[128 * PITCH];
    __shared__ __align__(16) bf16 sAlo[128 * PITCH];
    __shared__ __align__(16) bf16 sBhi[128 * PITCH];
    __shared__ __align__(16) bf16 sBlo[128 * PITCH];

    const int b = blockIdx.z;
    const int n0 = blockIdx.x * 128;
    const int m0 = blockIdx.y * 128;
    const int tid = threadIdx.x;
    const int lane = tid & 31;
    const int wid = tid >> 5;
    const int wm = (wid >> 2) * 64, wn = (wid & 3) * 32;

    const bf16* Hhi = g_h_hi + (size_t)b * Cc * Ss;
    const bf16* Hlo = g_h_lo + (size_t)b * Cc * Ss;

    const int r = tid >> 1, kq = (tid & 1) * 16;
    const bf16* pAh = g_wq_hi + (size_t)(m0 + r) * Cc + kq;
    const bf16* pAl = g_wq_lo + (size_t)(m0 + r) * Cc + kq;

    float acc[16][4] = {};

    uint4 nAh0 = *(const uint4*)pAh, nAh1 = *(const uint4*)(pAh + 8);
    uint4 nAl0 = *(const uint4*)pAl, nAl1 = *(const uint4*)(pAl + 8);
    unsigned nh0[4], nh1[4], nl0[4], nl1[4];
#pragma unroll
    for (int q = 0; q < 4; q++) {
        int bi = tid + q * 256;
        int kb = bi >> 6, nb = bi & 63;
        const bf16* ph = Hhi + (size_t)(2 * kb) * Ss + n0 + 2 * nb;
        const bf16* pl = Hlo + (size_t)(2 * kb) * Ss + n0 + 2 * nb;
        nh0[q] = *(const unsigned*)ph; nh1[q] = *(const unsigned*)(ph + Ss);
        nl0[q] = *(const unsigned*)pl; nl1[q] = *(const unsigned*)(pl + Ss);
    }

    for (int k0 = 0; k0 < Cc; k0 += 32) {
        *(uint4*)&sAhi[r * PITCH + kq] = nAh0;
        *(uint4*)&sAhi[r * PITCH + kq + 8] = nAh1;
        *(uint4*)&sAlo[r * PITCH + kq] = nAl0;
        *(uint4*)&sAlo[r * PITCH + kq + 8] = nAl1;
#pragma unroll
        for (int q = 0; q < 4; q++) {
            int bi = tid + q * 256;
            int kb = bi >> 6, nb = bi & 63;
            *(unsigned*)&sBhi[(2 * nb) * PITCH + 2 * kb] = __byte_perm(nh0[q], nh1[q], 0x5410);
            *(unsigned*)&sBhi[(2 * nb + 1) * PITCH + 2 * kb] = __byte_perm(nh0[q], nh1[q], 0x7632);
            *(unsigned*)&sBlo[(2 * nb) * PITCH + 2 * kb] = __byte_perm(nl0[q], nl1[q], 0x5410);
            *(unsigned*)&sBlo[(2 * nb + 1) * PITCH + 2 * kb] = __byte_perm(nl0[q], nl1[q], 0x7632);
        }
        __syncthreads();
        if (k0 + 32 < Cc) {
            nAh0 = *(const uint4*)(pAh + k0 + 32);
            nAh1 = *(const uint4*)(pAh + k0 + 40);
            nAl0 = *(const uint4*)(pAl + k0 + 32);
            nAl1 = *(const uint4*)(pAl + k0 + 40);
#pragma unroll
            for (int q = 0; q < 4; q++) {
                int bi = tid + q * 256;
                int kb = bi >> 6, nb = bi & 63;
                const bf16* ph = Hhi + (size_t)(k0 + 32 + 2 * kb) * Ss + n0 + 2 * nb;
                const bf16* pl = Hlo + (size_t)(k0 + 32 + 2 * kb) * Ss + n0 + 2 * nb;
                nh0[q] = *(const unsigned*)ph; nh1[q] = *(const unsigned*)(ph + Ss);
                nl0[q] = *(const unsigned*)pl; nl1[q] = *(const unsigned*)(pl + Ss);
            }
        }
        frag_step(sAhi, sAlo, sBhi, sBlo, wm, wn, lane, 0, acc);
        frag_step(sAhi, sAlo, sBhi, sBlo, wm, wn, lane, 1, acc);
        __syncthreads();
    }

    float* out = g_qkv + (size_t)b * M3 * Ss;
    const int g2 = lane >> 2, tq = (lane & 3) * 2;
#pragma unroll
    for (int i = 0; i < 4; i++) {
        const int m1 = m0 + wm + i * 16 + g2;
        const float bv1 = bias[m1], bv2 = bias[m1 + 8];
#pragma unroll
        for (int j = 0; j < 4; j++) {
            const int n = n0 + wn + j * 8 + tq;
            float* c = acc[i * 4 + j];
            *(float2*)(out + (size_t)m1 * Ss + n) = make_float2(c[0] + bv1, c[1] + bv1);
            *(float2*)(out + (size_t)(m1 + 8) * Ss + n) = make_float2(c[2] + bv2, c[3] + bv2);
        }
    }
}

// ---------------------------------------------------------------------------
// Q/K transpose+convert: [b][ch][s] fp32 -> [bh][s][d] bf16 hi/lo.
// grid (16 s-tiles, 64 bh, 2 {q,k}). Q scaled by 0.125.
// ---------------------------------------------------------------------------
__global__ void qk_conv() {
    __shared__ float tile[64][65];
    const int tid = threadIdx.x;
    const int bh = blockIdx.y, b = bh >> 3, hh = bh & 7;
    const int st = blockIdx.x * 64;
    const int isK = blockIdx.z;
    const float* src = g_qkv + (size_t)b * M3 * Ss +
                       (size_t)(isK * Cc + hh * HD) * Ss + st;
#pragma unroll
    for (int r = 0; r < 4; r++) {
        int idx = tid + r * 256;
        int d = idx >> 4, s4 = (idx & 15) * 4;
        float4 v = *(const float4*)(src + (size_t)d * Ss + s4);
        tile[d][s4 + 0] = v.x; tile[d][s4 + 1] = v.y;
        tile[d][s4 + 2] = v.z; tile[d][s4 + 3] = v.w;
    }
    __syncthreads();
    bf16* oh = (isK ? g_kh : g_qh) + ((size_t)bh * Ss + st) * HD;
    bf16* ol = (isK ? g_kl : g_ql) + ((size_t)bh * Ss + st) * HD;
    const float scl = isK ? 1.f : 0.125f;
#pragma unroll
    for (int r = 0; r < 8; r++) {
        int idx = tid + r * 256;
        int s = idx >> 5, dp = (idx & 31) * 2;
        float xx = tile[dp][s] * scl, yy = tile[dp + 1][s] * scl;
        unsigned h, l;
        split2(xx, yy, h, l);
        *(unsigned*)(oh + (size_t)s * HD + dp) = h;
        *(unsigned*)(ol + (size_t)s * HD + dp) = l;
    }
}

// ---------------------------------------------------------------------------
// V convert (layout preserved [bh][d][t]): fp32 -> bf16 hi/lo. grid 4096.
// ---------------------------------------------------------------------------
__global__ void v_conv() {
    int idx = (blockIdx.x * 256 + threadIdx.x) * 4;
    int b = idx >> 19;             // 512*1024 elems per batch
    int rem = idx & 524287;
    float4 v = *(const float4*)(g_qkv + (size_t)b * M3 * Ss + (size_t)2 * Cc * Ss + rem);
    uint2 uh, ul;
    split2(v.x, v.y, uh.x, ul.x);
    split2(v.z, v.w, uh.y, ul.y);
    *(uint2*)(g_vh + (size_t)b * 524288 + rem) = uh;
    *(uint2*)(g_vl + (size_t)b * 524288 + rem) = ul;
}

// ---------------------------------------------------------------------------
// Attention via tensor cores, 3-term bf16 split, flash-style online softmax.
// Grid (8 s-tiles, 64 bh), 256 threads = 8 warps; warp w owns s rows w*16..+15.
// ---------------------------------------------------------------------------
__global__ void __launch_bounds__(256) attn_mma() {
    __shared__ __align__(16) bf16 sKh[64 * APITCH];
    __shared__ __align__(16) bf16 sKl[64 * APITCH];
    __shared__ __align__(16) bf16 sVh[64 * APITCH];
    __shared__ __align__(16) bf16 sVl[64 * APITCH];

    const int tid = threadIdx.x, lane = tid & 31, w = tid >> 5;
    const int bh = blockIdx.y, b = bh >> 3, hh = bh & 7;
    const int s0 = blockIdx.x * 128;
    const int g = lane >> 2, q2 = (lane & 3) * 2;
    const int srow = s0 + w * 16;

    // Q fragments (A operand, row-major [s][d]), hi/lo, 4 k-slices of d
    unsigned qh[4][4], ql[4][4];
    {
        const bf16* Qh = g_qh + ((size_t)bh * Ss + srow) * HD;
        const bf16* Ql = g_ql + ((size_t)bh * Ss + srow) * HD;
#pragma unroll
        for (int ks = 0; ks < 4; ks++) {
            qh[ks][0] = *(const unsigned*)(Qh + (size_t)g * HD + ks * 16 + q2);
            qh[ks][1] = *(const unsigned*)(Qh + (size_t)(g + 8) * HD + ks * 16 + q2);
            qh[ks][2] = *(const unsigned*)(Qh + (size_t)g * HD + ks * 16 + q2 + 8);
            qh[ks][3] = *(const unsigned*)(Qh + (size_t)(g + 8) * HD + ks * 16 + q2 + 8);
            ql[ks][0] = *(const unsigned*)(Ql + (size_t)g * HD + ks * 16 + q2);
            ql[ks][1] = *(const unsigned*)(Ql + (size_t)(g + 8) * HD + ks * 16 + q2);
            ql[ks][2] = *(const unsigned*)(Ql + (size_t)g * HD + ks * 16 + q2 + 8);
            ql[ks][3] = *(const unsigned*)(Ql + (size_t)(g + 8) * HD + ks * 16 + q2 + 8);
        }
    }

    const bf16* Kh = g_kh + (size_t)bh * Ss * HD;
    const bf16* Kl = g_kl + (size_t)bh * Ss * HD;
    const bf16* Vh = g_vh + (size_t)bh * HD * Ss;
    const bf16* Vl = g_vl + (size_t)bh * HD * Ss;

    float m0 = -1e30f, m1 = -1e30f, l0 = 0.f, l1 = 0.f;
    float O[8][4] = {};

    for (int t0 = 0; t0 < Ss; t0 += 64) {
        // Stage K [t][d] and V [d][t] (hi/lo)
#pragma unroll
        for (int r = 0; r < 2; r++) {
            int idx = tid + r * 256;
            int row = idx >> 3, c8 = (idx & 7) * 8;
            *(uint4*)&sKh[row * APITCH + c8] = *(const uint4*)(Kh + (size_t)(t0 + row) * HD + c8);
            *(uint4*)&sKl[row * APITCH + c8] = *(const uint4*)(Kl + (size_t)(t0 + row) * HD + c8);
            *(uint4*)&sVh[row * APITCH + c8] = *(const uint4*)(Vh + (size_t)row * Ss + t0 + c8);
            *(uint4*)&sVl[row * APITCH + c8] = *(const uint4*)(Vl + (size_t)row * Ss + t0 + c8);
        }
        __syncthreads();

        // Scores: 16 s x 64 t per warp; 8 n-blocks of 8 t-cols
        float sc[8][4] = {};
#pragma unroll
        for (int ks = 0; ks < 4; ks++) {
#pragma unroll
            for (int j = 0; j < 8; j++) {
                const int nrow = (j * 8 + g) * APITCH + ks * 16 + q2;
                unsigned kbh[2] = {*(const unsigned*)&sKh[nrow],
                                   *(const unsigned*)&sKh[nrow + 8]};
                unsigned kbl[2] = {*(const unsigned*)&sKl[nrow],
                                   *(const unsigned*)&sKl[nrow + 8]};
                mma_bf16(sc[j], qh[ks], kbh);
                mma_bf16(sc[j], qh[ks], kbl);
                mma_bf16(sc[j], ql[ks], kbh);
            }
        }

        // Online softmax: lane rows are g (c0,c1) and g+8 (c2,c3)
        float mx0 = -1e30f, mx1 = -1e30f;
#pragma unroll
        for (int j = 0; j < 8; j++) {
            mx0 = fmaxf(mx0, fmaxf(sc[j][0], sc[j][1]));
            mx1 = fmaxf(mx1, fmaxf(sc[j][2], sc[j][3]));
        }
        mx0 = fmaxf(mx0, __shfl_xor_sync(0xffffffffu, mx0, 1));
        mx0 = fmaxf(mx0, __shfl_xor_sync(0xffffffffu, mx0, 2));
        mx1 = fmaxf(mx1, __shfl_xor_sync(0xffffffffu, mx1, 1));
        mx1 = fmaxf(mx1, __shfl_xor_sync(0xffffffffu, mx1, 2));
        const float nm0 = fmaxf(m0, mx0), nm1 = fmaxf(m1, mx1);
        const float cr0 = __expf(m0 - nm0), cr1 = __expf(m1 - nm1);
        m0 = nm0; m1 = nm1;

        unsigned ph[4][4], pl[4][4];
        float ss0 = 0.f, ss1 = 0.f;
#pragma unroll
        for (int j = 0; j < 8; j++) {
            float p0 = __expf(sc[j][0] - m0), p1 = __expf(sc[j][1] - m0);
            float p2 = __expf(sc[j][2] - m1), p3 = __expf(sc[j][3] - m1);
            ss0 += p0 + p1; ss1 += p2 + p3;
            const int kt = j >> 1;
            if ((j & 1) == 0) {
                split2(p0, p1, ph[kt][0], pl[kt][0]);
                split2(p2, p3, ph[kt][1], pl[kt][1]);
            } else {
                split2(p0, p1, ph[kt][2], pl[kt][2]);
                split2(p2, p3, ph[kt][3], pl[kt][3]);
            }
        }
        ss0 += __shfl_xor_sync(0xffffffffu, ss0, 1);
        ss0 += __shfl_xor_sync(0xffffffffu, ss0, 2);
        ss1 += __shfl_xor_sync(0xffffffffu, ss1, 1);
        ss1 += __shfl_xor_sync(0xffffffffu, ss1, 2);
        l0 = l0 * cr0 + ss0;
        l1 = l1 * cr1 + ss1;

        // Correct O, then O += P @ V
#pragma unroll
        for (int jd = 0; jd < 8; jd++) {
            O[jd][0] *= cr0; O[jd][1] *= cr0;
            O[jd][2] *= cr1; O[jd][3] *= cr1;
        }
#pragma unroll
        for (int kt = 0; kt < 4; kt++) {
#pragma unroll
            for (int jd = 0; jd < 8; jd++) {
                const int nrow = (jd * 8 + g) * APITCH + kt * 16 + q2;
                unsigned vbh[2] = {*(const unsigned*)&sVh[nrow],
                                   *(const unsigned*)&sVh[nrow + 8]};
                unsigned vbl[2] = {*(const unsigned*)&sVl[nrow],
                                   *(const unsigned*)&sVl[nrow + 8]};
                mma_bf16(O[jd], ph[kt], vbh);
                mma_bf16(O[jd], ph[kt], vbl);
                mma_bf16(O[jd], pl[kt], vbh);
            }
        }
        __syncthreads();
    }

    // Finalize: O/l, write fp32 + bf16 split to hf[b*S+s][hh*64+d]
    const float inv0 = __fdividef(1.f, l0), inv1 = __fdividef(1.f, l1);
    const size_t base = ((size_t)b * Ss + srow) * Cc + hh * HD;
#pragma unroll
    for (int jd = 0; jd < 8; jd++) {
        const int d = jd * 8 + q2;
        float a0 = O[jd][0] * inv0, a1 = O[jd][1] * inv0;
        float a2 = O[jd][2] * inv1, a3 = O[jd][3] * inv1;
        const size_t i0 = base + (size_t)g * Cc + d;
        const size_t i1 = base + (size_t)(g + 8) * Cc + d;
        *(float2*)(g_hf + i0) = make_float2(a0, a1);
        *(float2*)(g_hf + i1) = make_float2(a2, a3);
        unsigned h, l;
        split2(a0, a1, h, l);
        *(unsigned*)(g_hfh0 + i0) = h;
        *(unsigned*)(g_hfl0 + i0) = l;
        split2(a2, a3, h, l);
        *(unsigned*)(g_hfh0 + i1) = h;
        *(unsigned*)(g_hfl0 + i1) = l;
    }
}

// ---------------------------------------------------------------------------
// INL step (NT tensor-core GEMM + fused Euler/tanh epilogue).
// ---------------------------------------------------------------------------
__global__ void __launch_bounds__(256) inl_mma(int src, const float* __restrict__ bias) {
    __shared__ __align__(16) bf16 sAhi[128 * PITCH];
    __shared__ __align__(16) bf16 sAlo[128 * PITCH];
    __shared__ __align__(16) bf16 sBhi[128 * PITCH];
    __shared__ __align__(16) bf16 sBlo[128 * PITCH];

    const float* hin = src ? g_hf2 : g_hf;
    float* hout = src ? g_hf : g_hf2;
    const bf16* Ahi = src ? g_hfh1 : g_hfh0;
    const bf16* Alo = src ? g_hfl1 : g_hfl0;
    bf16* outh = src ? g_hfh0 : g_hfh1;
    bf16* outl = src ? g_hfl0 : g_hfl1;

    const int n0 = blockIdx.x * 128;
    const int m0 = blockIdx.y * 128;
    const int tid = threadIdx.x;
    const int lane = tid & 31;
    const int wid = tid >> 5;
    const int wm = (wid >> 2) * 64, wn = (wid & 3) * 32;

    const int r = tid >> 1, kq = (tid & 1) * 16;
    const bf16* pAh = Ahi + (size_t)(m0 + r) * Cc + kq;
    const bf16* pAl = Alo + (size_t)(m0 + r) * Cc + kq;
    const bf16* pBh = g_wi_hi + (size_t)(n0 + r) * Cc + kq;
    const bf16* pBl = g_wi_lo + (size_t)(n0 + r) * Cc + kq;

    float acc[16][4] = {};

    uint4 nAh0 = *(const uint4*)pAh, nAh1 = *(const uint4*)(pAh + 8);
    uint4 nAl0 = *(const uint4*)pAl, nAl1 = *(const uint4*)(pAl + 8);
    uint4 nBh0 = *(const uint4*)pBh, nBh1 = *(const uint4*)(pBh + 8);
    uint4 nBl0 = *(const uint4*)pBl, nBl1 = *(const uint4*)(pBl + 8);

    for (int k0 = 0; k0 < Cc; k0 += 32) {
        *(uint4*)&sAhi[r * PITCH + kq] = nAh0;
        *(uint4*)&sAhi[r * PITCH + kq + 8] = nAh1;
        *(uint4*)&sAlo[r * PITCH + kq] = nAl0;
        *(uint4*)&sAlo[r * PITCH + kq + 8] = nAl1;
        *(uint4*)&sBhi[r * PITCH + kq] = nBh0;
        *(uint4*)&sBhi[r * PITCH + kq + 8] = nBh1;
        *(uint4*)&sBlo[r * PITCH + kq] = nBl0;
        *(uint4*)&sBlo[r * PITCH + kq + 8] = nBl1;
        __syncthreads();
        if (k0 + 32 < Cc) {
            nAh0 = *(const uint4*)(pAh + k0 + 32);
            nAh1 = *(const uint4*)(pAh + k0 + 40);
            nAl0 = *(const uint4*)(pAl + k0 + 32);
            nAl1 = *(const uint4*)(pAl + k0 + 40);
            nBh0 = *(const uint4*)(pBh + k0 + 32);
            nBh1 = *(const uint4*)(pBh + k0 + 40);
            nBl0 = *(const uint4*)(pBl + k0 + 32);
            nBl1 = *(const uint4*)(pBl + k0 + 40);
        }
        frag_step(sAhi, sAlo, sBhi, sBlo, wm, wn, lane, 0, acc);
        frag_step(sAhi, sAlo, sBhi, sBlo, wm, wn, lane, 1, acc);
        __syncthreads();
    }

    const int g2 = lane >> 2, tq = (lane & 3) * 2;
#pragma unroll
    for (int i = 0; i < 4; i++) {
        const int r1 = m0 + wm + i * 16 + g2;
#pragma unroll
        for (int j = 0; j < 4; j++) {
            const int o = n0 + wn + j * 8 + tq;
            const float b0 = bias[o], b1 = bias[o + 1];
            float* c = acc[i * 4 + j];
#pragma unroll
            for (int h = 0; h < 2; h++) {
                const size_t rr = (size_t)(r1 + h * 8) * Cc + o;
                float2 prev = *(const float2*)(hin + rr);
                float v0 = prev.x + 0.1f * fast_tanh(c[h * 2 + 0] + b0);
                float v1 = prev.y + 0.1f * fast_tanh(c[h * 2 + 1] + b1);
                *(float2*)(hout + rr) = make_float2(v0, v1);
                unsigned uh, ul;
                split2(v0, v1, uh, ul);
                *(unsigned*)(outh + rr) = uh;
                *(unsigned*)(outl + rr) = ul;
            }
        }
    }
}

// ---------------------------------------------------------------------------
// Proj (NT tensor-core GEMM + fused residual, transposed write).
// ---------------------------------------------------------------------------
__global__ void __launch_bounds__(256) proj_mma(const float* __restrict__ bias,
                                                const float* __restrict__ x,
                                                float* __restrict__ out) {
    __shared__ __align__(16) bf16 sAhi[128 * PITCH];
    __shared__ __align__(16) bf16 sAlo[128 * PITCH];
    __shared__ __align__(16) bf16 sBhi[128 * PITCH];
    __shared__ __align__(16) bf16 sBlo[128 * PITCH];

    const int n0 = blockIdx.x * 128;
    const int m0 = blockIdx.y * 128;
    const int tid = threadIdx.x;
    const int lane = tid & 31;
    const int wid = tid >> 5;
    const int wm = (wid >> 2) * 64, wn = (wid & 3) * 32;

    const int r = tid >> 1, kq = (tid & 1) * 16;
    const bf16* pAh = g_hfh1 + (size_t)(m0 + r) * Cc + kq;
    const bf16* pAl = g_hfl1 + (size_t)(m0 + r) * Cc + kq;
    const bf16* pBh = g_wp_hi + (size_t)(n0 + r) * Cc + kq;
    const bf16* pBl = g_wp_lo + (size_t)(n0 + r) * Cc + kq;

    float acc[16][4] = {};

    uint4 nAh0 = *(const uint4*)pAh, nAh1 = *(const uint4*)(pAh + 8);
    uint4 nAl0 = *(const uint4*)pAl, nAl1 = *(const uint4*)(pAl + 8);
    uint4 nBh0 = *(const uint4*)pBh, nBh1 = *(const uint4*)(pBh + 8);
    uint4 nBl0 = *(const uint4*)pBl, nBl1 = *(const uint4*)(pBl + 8);

    for (int k0 = 0; k0 < Cc; k0 += 32) {
        *(uint4*)&sAhi[r * PITCH + kq] = nAh0;
        *(uint4*)&sAhi[r * PITCH + kq + 8] = nAh1;
        *(uint4*)&sAlo[r * PITCH + kq] = nAl0;
        *(uint4*)&sAlo[r * PITCH + kq + 8] = nAl1;
        *(uint4*)&sBhi[r * PITCH + kq] = nBh0;
        *(uint4*)&sBhi[r * PITCH + kq + 8] = nBh1;
        *(uint4*)&sBlo[r * PITCH + kq] = nBl0;
        *(uint4*)&sBlo[r * PITCH + kq + 8] = nBl1;
        __syncthreads();
        if (k0 + 32 < Cc) {
            nAh0 = *(const uint4*)(pAh + k0 + 32);
            nAh1 = *(const uint4*)(pAh + k0 + 40);
            nAl0 = *(const uint4*)(pAl + k0 + 32);
            nAl1 = *(const uint4*)(pAl + k0 + 40);
            nBh0 = *(const uint4*)(pBh + k0 + 32);
            nBh1 = *(const uint4*)(pBh + k0 + 40);
            nBl0 = *(const uint4*)(pBl + k0 + 32);
            nBl1 = *(const uint4*)(pBl + k0 + 40);
        }
        frag_step(sAhi, sAlo, sBhi, sBlo, wm, wn, lane, 0, acc);
        frag_step(sAhi, sAlo, sBhi, sBlo, wm, wn, lane, 1, acc);
        __syncthreads();
    }

    const int g2 = lane >> 2, tq = (lane & 3) * 2;
    const int b = m0 >> 10;
#pragma unroll
    for (int i = 0; i < 4; i++) {
        const int s1 = (m0 & 1023) + wm + i * 16 + g2;
#pragma unroll
        for (int j = 0; j < 4; j++) {
            const int o = n0 + wn + j * 8 + tq;
            const float b0 = bias[o], b1 = bias[o + 1];
            float* c = acc[i * 4 + j];
#pragma unroll
            for (int h = 0; h < 2; h++) {
                const int s = s1 + h * 8;
                const size_t i0 = ((size_t)b * Cc + o) * Ss + s;
                const size_t i1 = i0 + Ss;
                out[i0] = x[i0] + c[h * 2 + 0] + b0;
                out[i1] = x[i1] + c[h * 2 + 1] + b1;
            }
        }
    }
}

// ---------------------------------------------------------------------------
extern "C" void kernel_launch(void* const* d_in, const int* in_sizes, int n_in,
                              void* d_out, int out_size) {
    const float* x = (const float*)d_in[0];
    const float* gn_scale = (const float*)d_in[1];
    const float* gn_bias = (const float*)d_in[2];
    const float* qkv_w = (const float*)d_in[3];
    const float* qkv_b = (const float*)d_in[4];
    const float* proj_w = (const float*)d_in[5];
    const float* proj_b = (const float*)d_in[6];
    const float* inl_w = (const float*)d_in[7];
    const float* inl_b = (const float*)d_in[8];
    float* out = (float*)d_out;

    // 0. Convert weights to bf16 hi/lo
    bf16 *wq_hi, *wq_lo, *wi_hi, *wi_lo, *wp_hi, *wp_lo;
    cudaGetSymbolAddress((void**)&wq_hi, g_wq_hi);
    cudaGetSymbolAddress((void**)&wq_lo, g_wq_lo);
    cudaGetSymbolAddress((void**)&wi_hi, g_wi_hi);
    cudaGetSymbolAddress((void**)&wi_lo, g_wi_lo);
    cudaGetSymbolAddress((void**)&wp_hi, g_wp_hi);
    cudaGetSymbolAddress((void**)&wp_lo, g_wp_lo);
    convw<<<(M3 * Cc) / 1024, 256>>>(qkv_w, wq_hi, wq_lo, M3 * Cc);
    convw<<<(Cc * Cc) / 1024, 256>>>(inl_w, wi_hi, wi_lo, Cc * Cc);
    convw<<<(Cc * Cc) / 1024, 256>>>(proj_w, wp_hi, wp_lo, Cc * Cc);

    // 1. GroupNorm (2-phase) -> g_h_hi/lo
    gn_stats<<<512, 256>>>(x);
    gn_apply<<<512, 256>>>(x, gn_scale, gn_bias);

    // 2. QKV GEMM (tensor cores) -> g_qkv fp32
    qkv_mma<<<dim3(Ss / 128, M3 / 128, Bb), 256>>>(qkv_b);

    // 2b. Attention operand conversion
    qk_conv<<<dim3(16, 64, 2), 256>>>();
    v_conv<<<4096, 256>>>();

    // 3. Attention (tensor cores) -> g_hf fp32 + bf16 split
    attn_mma<<<dim3(Ss / 128, Bb * NH), 256>>>();

    // 4. INL: 3 Euler steps (ping-pong), ends in g_hf2 + g_hfh1/g_hfl1
    inl_mma<<<dim3(Cc / 128, Bb * Ss / 128), 256>>>(0, inl_b);
    inl_mma<<<dim3(Cc / 128, Bb * Ss / 128), 256>>>(1, inl_b);
    inl_mma<<<dim3(Cc / 128, Bb * Ss / 128), 256>>>(0, inl_b);

    // 5. Proj + residual -> d_out
    proj_mma<<<dim3(Cc / 128, Bb * Ss / 128), 256>>>(proj_b, x, out);
}

// round 9
// speedup vs baseline: 1.6664x; 1.1240x over previous
#include <cuda_runtime.h>
#include <cuda_bf16.h>
#include <math.h>

typedef __nv_bfloat16 bf16;

// Problem constants
constexpr int Bb = 8;
constexpr int Cc = 512;
constexpr int Ss = 1024;     // H*W
constexpr int M3 = 1536;     // 3*C
constexpr int NH = 8;
constexpr int HD = 64;

constexpr int PITCH = 40;    // dense-GEMM smem row pitch (32 data + 8 pad), 80B = 16B-aligned
constexpr int APITCH = 72;   // attention smem row pitch (64 data + 8 pad), 144B = 16B-aligned

// Scratch buffers (static device globals; allocation is forbidden)
__device__ __align__(16) bf16 g_h_hi[Bb * Cc * Ss];
__device__ __align__(16) bf16 g_h_lo[Bb * Cc * Ss];
__device__ float g_qkv[Bb * M3 * Ss];                // fp32, only q/k thirds used
__device__ __align__(16) bf16 g_hfh0[Bb * Ss * Cc];  // hf ping (hi)
__device__ __align__(16) bf16 g_hfl0[Bb * Ss * Cc];  // hf ping (lo)
__device__ __align__(16) bf16 g_hfh1[Bb * Ss * Cc];  // hf pong (hi)
__device__ __align__(16) bf16 g_hfl1[Bb * Ss * Cc];  // hf pong (lo)
__device__ __align__(16) bf16 g_wq_hi[M3 * Cc];
__device__ __align__(16) bf16 g_wq_lo[M3 * Cc];
__device__ __align__(16) bf16 g_wi_hi[Cc * Cc];
__device__ __align__(16) bf16 g_wi_lo[Cc * Cc];
__device__ __align__(16) bf16 g_wp_hi[Cc * Cc];
__device__ __align__(16) bf16 g_wp_lo[Cc * Cc];
// Attention operand layouts (split bf16)
__device__ __align__(16) bf16 g_qh[Bb * NH * Ss * HD];  // [bh][s][d], scaled
__device__ __align__(16) bf16 g_ql[Bb * NH * Ss * HD];
__device__ __align__(16) bf16 g_kh[Bb * NH * Ss * HD];  // [bh][t][d]
__device__ __align__(16) bf16 g_kl[Bb * NH * Ss * HD];
__device__ __align__(16) bf16 g_vh[Bb * NH * HD * Ss];  // [bh][d][t]
__device__ __align__(16) bf16 g_vl[Bb * NH * HD * Ss];
__device__ float g_gnp[512][2];                          // groupnorm partials

__device__ __forceinline__ float fast_tanh(float x) {
    x = fminf(fmaxf(x, -15.f), 15.f);
    float e = __expf(2.f * x);
    return __fdividef(e - 1.f, e + 1.f);
}

// Split a pair of fp32 into packed bf16 hi and lo words (elem0 in low half).
__device__ __forceinline__ void split2(float x, float y, unsigned& hi, unsigned& lo) {
    bf16 hx = __float2bfloat16(x), hy = __float2bfloat16(y);
    float rx = x - __bfloat162float(hx);
    float ry = y - __bfloat162float(hy);
    bf16 lx = __float2bfloat16(rx), ly = __float2bfloat16(ry);
    hi = ((unsigned)__bfloat16_as_ushort(hy) << 16) | (unsigned)__bfloat16_as_ushort(hx);
    lo = ((unsigned)__bfloat16_as_ushort(ly) << 16) | (unsigned)__bfloat16_as_ushort(lx);
}

// Reconstruct fp32 pair from packed bf16 hi/lo words.
__device__ __forceinline__ float2 join2(unsigned h, unsigned l) {
    float x = __bfloat162float(__ushort_as_bfloat16((unsigned short)(h & 0xffffu)))
            + __bfloat162float(__ushort_as_bfloat16((unsigned short)(l & 0xffffu)));
    float y = __bfloat162float(__ushort_as_bfloat16((unsigned short)(h >> 16)))
            + __bfloat162float(__ushort_as_bfloat16((unsigned short)(l >> 16)));
    return make_float2(x, y);
}

__device__ __forceinline__ void mma_bf16(float* c, const unsigned* a, const unsigned* b) {
    asm("mma.sync.aligned.m16n8k16.row.col.f32.bf16.bf16.f32 "
        "{%0,%1,%2,%3}, {%4,%5,%6,%7}, {%8,%9}, {%0,%1,%2,%3};"
        : "+f"(c[0]), "+f"(c[1]), "+f"(c[2]), "+f"(c[3])
        : "r"(a[0]), "r"(a[1]), "r"(a[2]), "r"(a[3]), "r"(b[0]), "r"(b[1]));
}

__device__ __forceinline__ unsigned smem_u32(const void* p) {
    return (unsigned)__cvta_generic_to_shared(p);
}
__device__ __forceinline__ void ldsm_x4(unsigned& r0, unsigned& r1, unsigned& r2,
                                        unsigned& r3, unsigned a) {
    asm volatile("ldmatrix.sync.aligned.m8n8.x4.shared.b16 {%0,%1,%2,%3}, [%4];"
                 : "=r"(r0), "=r"(r1), "=r"(r2), "=r"(r3) : "r"(a));
}
__device__ __forceinline__ void ldsm_x2(unsigned& r0, unsigned& r1, unsigned a) {
    asm volatile("ldmatrix.sync.aligned.m8n8.x2.shared.b16 {%0,%1}, [%2];"
                 : "=r"(r0), "=r"(r1) : "r"(a));
}

// Per-lane ldmatrix byte offsets (bf16-unit offsets; multiply by 2 at use).
// A (x4): lanes 0-7 rows, 8-15 rows+8, 16-23 rows/col+8, 24-31 rows+8/col+8.
__device__ __forceinline__ int a_lane_off(int lane, int pitch) {
    return ((lane & 7) + ((lane >> 3) & 1) * 8) * pitch + ((lane >> 4) & 1) * 8;
}
// B (x2): lanes 0-7 rows (k 0-7 tile), 8-15 rows (k 8-15 tile).
__device__ __forceinline__ int b_lane_off(int lane, int pitch) {
    return (lane & 7) * pitch + ((lane >> 3) & 1) * 8;
}

// One k16 step for the dense GEMMs: ldmatrix fragment loads + 3-term split mma.
__device__ __forceinline__ void frag_step(
    unsigned uAhi, unsigned uAlo, unsigned uBhi, unsigned uBlo,
    int aoff, int boff, int wm, int wn, int ks, float acc[16][4]) {
    unsigned ah[4][4], al[4][4], bh[4][2], bl[4][2];
#pragma unroll
    for (int i = 0; i < 4; i++) {
        const unsigned off = 2u * ((wm + i * 16) * PITCH + ks * 16 + aoff);
        ldsm_x4(ah[i][0], ah[i][1], ah[i][2], ah[i][3], uAhi + off);
        ldsm_x4(al[i][0], al[i][1], al[i][2], al[i][3], uAlo + off);
    }
#pragma unroll
    for (int j = 0; j < 4; j++) {
        const unsigned off = 2u * ((wn + j * 8) * PITCH + ks * 16 + boff);
        ldsm_x2(bh[j][0], bh[j][1], uBhi + off);
        ldsm_x2(bl[j][0], bl[j][1], uBlo + off);
    }
#pragma unroll
    for (int i = 0; i < 4; i++)
#pragma unroll
        for (int j = 0; j < 4; j++) {
            mma_bf16(acc[i * 4 + j], ah[i], bh[j]);
            mma_bf16(acc[i * 4 + j], ah[i], bl[j]);
            mma_bf16(acc[i * 4 + j], al[i], bh[j]);
        }
}

// ---------------------------------------------------------------------------
// Weight convert: fp32 -> bf16 hi/lo
// ---------------------------------------------------------------------------
__global__ void convw(const float* __restrict__ src, bf16* __restrict__ hi,
                      bf16* __restrict__ lo, int n) {
    int i = (blockIdx.x * 256 + threadIdx.x) * 4;
    if (i < n) {
        float4 v = *(const float4*)(src + i);
        uint2 uh, ul;
        split2(v.x, v.y, uh.x, ul.x);
        split2(v.z, v.w, uh.y, ul.y);
        *(uint2*)(hi + i) = uh;
        *(uint2*)(lo + i) = ul;
    }
}

// ---------------------------------------------------------------------------
// GroupNorm phase 1: partial sums. grid 512 = (group 64) x (slice 8).
// ---------------------------------------------------------------------------
__global__ void gn_stats(const float* __restrict__ x) {
    const int grp = blockIdx.x >> 3;
    const int slice = blockIdx.x & 7;
    const float* xp = x + (size_t)grp * 65536 + slice * 8192;
    float s = 0.f, s2 = 0.f;
#pragma unroll
    for (int r = 0; r < 8; r++) {
        float4 v = *(const float4*)(xp + (threadIdx.x + r * 256) * 4);
        s += v.x + v.y + v.z + v.w;
        s2 += v.x * v.x + v.y * v.y + v.z * v.z + v.w * v.w;
    }
    __shared__ float rs[256], rs2[256];
    rs[threadIdx.x] = s; rs2[threadIdx.x] = s2;
    __syncthreads();
    for (int o = 128; o > 0; o >>= 1) {
        if (threadIdx.x < o) {
            rs[threadIdx.x] += rs[threadIdx.x + o];
            rs2[threadIdx.x] += rs2[threadIdx.x + o];
        }
        __syncthreads();
    }
    if (threadIdx.x == 0) {
        g_gnp[blockIdx.x][0] = rs[0];
        g_gnp[blockIdx.x][1] = rs2[0];
    }
}

// ---------------------------------------------------------------------------
// GroupNorm phase 2: finalize + apply, writes bf16 hi/lo. grid 512.
// ---------------------------------------------------------------------------
__global__ void gn_apply(const float* __restrict__ x,
                         const float* __restrict__ scale,
                         const float* __restrict__ bias) {
    const int grp = blockIdx.x >> 3;
    const int slice = blockIdx.x & 7;
    float s = 0.f, s2 = 0.f;
#pragma unroll
    for (int p = 0; p < 8; p++) { s += g_gnp[grp * 8 + p][0]; s2 += g_gnp[grp * 8 + p][1]; }
    const float mean = s / 65536.f;
    float var = s2 / 65536.f - mean * mean;
    var = fmaxf(var, 0.f);
    const float rstd = rsqrtf(var + 1e-5f);

    const size_t base = (size_t)grp * 65536 + slice * 8192;
    const int cbase = (grp & 7) * 64 + slice * 8;
#pragma unroll
    for (int r = 0; r < 8; r++) {
        const int k = (threadIdx.x + r * 256) * 4;
        const int c = cbase + (k >> 10);
        const float a = rstd * scale[c];
        const float bb2 = bias[c] - mean * a;
        float4 v = *(const float4*)(x + base + k);
        float4 o = make_float4(v.x * a + bb2, v.y * a + bb2,
                               v.z * a + bb2, v.w * a + bb2);
        uint2 uh, ul;
        split2(o.x, o.y, uh.x, ul.x);
        split2(o.z, o.w, uh.y, ul.y);
        *(uint2*)(g_h_hi + base + k) = uh;
        *(uint2*)(g_h_lo + base + k) = ul;
    }
}

// ---------------------------------------------------------------------------
// QKV GEMM (NN) via tensor cores. V third written directly as split bf16.
// ---------------------------------------------------------------------------
__global__ void __launch_bounds__(256) qkv_mma(const float* __restrict__ bias) {
    __shared__ __align__(16) bf16 sAhi[128 * PITCH];
    __shared__ __align__(16) bf16 sAlo[128 * PITCH];
    __shared__ __align__(16) bf16 sBhi[128 * PITCH];
    __shared__ __align__(16) bf16 sBlo[128 * PITCH];

    const int b = blockIdx.z;
    const int n0 = blockIdx.x * 128;
    const int m0 = blockIdx.y * 128;
    const int tid = threadIdx.x;
    const int lane = tid & 31;
    const int wid = tid >> 5;
    const int wm = (wid >> 2) * 64, wn = (wid & 3) * 32;
    const int aoff = a_lane_off(lane, PITCH), boff = b_lane_off(lane, PITCH);
    const unsigned uAhi = smem_u32(sAhi), uAlo = smem_u32(sAlo);
    const unsigned uBhi = smem_u32(sBhi), uBlo = smem_u32(sBlo);

    const bf16* Hhi = g_h_hi + (size_t)b * Cc * Ss;
    const bf16* Hlo = g_h_lo + (size_t)b * Cc * Ss;

    const int r = tid >> 1, kq = (tid & 1) * 16;
    const bf16* pAh = g_wq_hi + (size_t)(m0 + r) * Cc + kq;
    const bf16* pAl = g_wq_lo + (size_t)(m0 + r) * Cc + kq;

    float acc[16][4] = {};

    uint4 nAh0 = *(const uint4*)pAh, nAh1 = *(const uint4*)(pAh + 8);
    uint4 nAl0 = *(const uint4*)pAl, nAl1 = *(const uint4*)(pAl + 8);
    unsigned nh0[4], nh1[4], nl0[4], nl1[4];
#pragma unroll
    for (int q = 0; q < 4; q++) {
        int bi = tid + q * 256;
        int kb = bi >> 6, nb = bi & 63;
        const bf16* ph = Hhi + (size_t)(2 * kb) * Ss + n0 + 2 * nb;
        const bf16* pl = Hlo + (size_t)(2 * kb) * Ss + n0 + 2 * nb;
        nh0[q] = *(const unsigned*)ph; nh1[q] = *(const unsigned*)(ph + Ss);
        nl0[q] = *(const unsigned*)pl; nl1[q] = *(const unsigned*)(pl + Ss);
    }

    for (int k0 = 0; k0 < Cc; k0 += 32) {
        *(uint4*)&sAhi[r * PITCH + kq] = nAh0;
        *(uint4*)&sAhi[r * PITCH + kq + 8] = nAh1;
        *(uint4*)&sAlo[r * PITCH + kq] = nAl0;
        *(uint4*)&sAlo[r * PITCH + kq + 8] = nAl1;
#pragma unroll
        for (int q = 0; q < 4; q++) {
            int bi = tid + q * 256;
            int kb = bi >> 6, nb = bi & 63;
            *(unsigned*)&sBhi[(2 * nb) * PITCH + 2 * kb] = __byte_perm(nh0[q], nh1[q], 0x5410);
            *(unsigned*)&sBhi[(2 * nb + 1) * PITCH + 2 * kb] = __byte_perm(nh0[q], nh1[q], 0x7632);
            *(unsigned*)&sBlo[(2 * nb) * PITCH + 2 * kb] = __byte_perm(nl0[q], nl1[q], 0x5410);
            *(unsigned*)&sBlo[(2 * nb + 1) * PITCH + 2 * kb] = __byte_perm(nl0[q], nl1[q], 0x7632);
        }
        __syncthreads();
        if (k0 + 32 < Cc) {
            nAh0 = *(const uint4*)(pAh + k0 + 32);
            nAh1 = *(const uint4*)(pAh + k0 + 40);
            nAl0 = *(const uint4*)(pAl + k0 + 32);
            nAl1 = *(const uint4*)(pAl + k0 + 40);
#pragma unroll
            for (int q = 0; q < 4; q++) {
                int bi = tid + q * 256;
                int kb = bi >> 6, nb = bi & 63;
                const bf16* ph = Hhi + (size_t)(k0 + 32 + 2 * kb) * Ss + n0 + 2 * nb;
                const bf16* pl = Hlo + (size_t)(k0 + 32 + 2 * kb) * Ss + n0 + 2 * nb;
                nh0[q] = *(const unsigned*)ph; nh1[q] = *(const unsigned*)(ph + Ss);
                nl0[q] = *(const unsigned*)pl; nl1[q] = *(const unsigned*)(pl + Ss);
            }
        }
        frag_step(uAhi, uAlo, uBhi, uBlo, aoff, boff, wm, wn, 0, acc);
        frag_step(uAhi, uAlo, uBhi, uBlo, aoff, boff, wm, wn, 1, acc);
        __syncthreads();
    }

    const int g2 = lane >> 2, tq = (lane & 3) * 2;
    if (m0 < 1024) {
        // Q/K thirds: fp32 out for qk_conv
        float* out = g_qkv + (size_t)b * M3 * Ss;
#pragma unroll
        for (int i = 0; i < 4; i++) {
            const int m1 = m0 + wm + i * 16 + g2;
            const float bv1 = bias[m1], bv2 = bias[m1 + 8];
#pragma unroll
            for (int j = 0; j < 4; j++) {
                const int n = n0 + wn + j * 8 + tq;
                float* c = acc[i * 4 + j];
                *(float2*)(out + (size_t)m1 * Ss + n) = make_float2(c[0] + bv1, c[1] + bv1);
                *(float2*)(out + (size_t)(m1 + 8) * Ss + n) = make_float2(c[2] + bv2, c[3] + bv2);
            }
        }
    } else {
        // V third: split bf16 directly into [bh*64+d][t] = [(m-1024)][n]
#pragma unroll
        for (int i = 0; i < 4; i++) {
            const int m1 = m0 + wm + i * 16 + g2;
            const float bv1 = bias[m1], bv2 = bias[m1 + 8];
#pragma unroll
            for (int j = 0; j < 4; j++) {
                const int n = n0 + wn + j * 8 + tq;
                float* c = acc[i * 4 + j];
                const size_t i0 = (size_t)b * 524288 + (size_t)(m1 - 1024) * Ss + n;
                const size_t i1 = (size_t)b * 524288 + (size_t)(m1 - 1024 + 8) * Ss + n;
                unsigned h, l;
                split2(c[0] + bv1, c[1] + bv1, h, l);
                *(unsigned*)(g_vh + i0) = h;
                *(unsigned*)(g_vl + i0) = l;
                split2(c[2] + bv2, c[3] + bv2, h, l);
                *(unsigned*)(g_vh + i1) = h;
                *(unsigned*)(g_vl + i1) = l;
            }
        }
    }
}

// ---------------------------------------------------------------------------
// Q/K transpose+convert: [b][ch][s] fp32 -> [bh][s][d] bf16 hi/lo.
// ---------------------------------------------------------------------------
__global__ void qk_conv() {
    __shared__ float tile[64][65];
    const int tid = threadIdx.x;
    const int bh = blockIdx.y, b = bh >> 3, hh = bh & 7;
    const int st = blockIdx.x * 64;
    const int isK = blockIdx.z;
    const float* src = g_qkv + (size_t)b * M3 * Ss +
                       (size_t)(isK * Cc + hh * HD) * Ss + st;
#pragma unroll
    for (int r = 0; r < 4; r++) {
        int idx = tid + r * 256;
        int d = idx >> 4, s4 = (idx & 15) * 4;
        float4 v = *(const float4*)(src + (size_t)d * Ss + s4);
        tile[d][s4 + 0] = v.x; tile[d][s4 + 1] = v.y;
        tile[d][s4 + 2] = v.z; tile[d][s4 + 3] = v.w;
    }
    __syncthreads();
    bf16* oh = (isK ? g_kh : g_qh) + ((size_t)bh * Ss + st) * HD;
    bf16* ol = (isK ? g_kl : g_ql) + ((size_t)bh * Ss + st) * HD;
    const float scl = isK ? 1.f : 0.125f;
#pragma unroll
    for (int r = 0; r < 8; r++) {
        int idx = tid + r * 256;
        int s = idx >> 5, dp = (idx & 31) * 2;
        float xx = tile[dp][s] * scl, yy = tile[dp + 1][s] * scl;
        unsigned h, l;
        split2(xx, yy, h, l);
        *(unsigned*)(oh + (size_t)s * HD + dp) = h;
        *(unsigned*)(ol + (size_t)s * HD + dp) = l;
    }
}

// ---------------------------------------------------------------------------
// Attention via tensor cores, 3-term bf16 split, flash-style online softmax.
// ---------------------------------------------------------------------------
__global__ void __launch_bounds__(256) attn_mma() {
    __shared__ __align__(16) bf16 sKh[64 * APITCH];
    __shared__ __align__(16) bf16 sKl[64 * APITCH];
    __shared__ __align__(16) bf16 sVh[64 * APITCH];
    __shared__ __align__(16) bf16 sVl[64 * APITCH];

    const int tid = threadIdx.x, lane = tid & 31, w = tid >> 5;
    const int bh = blockIdx.y, b = bh >> 3, hh = bh & 7;
    const int s0 = blockIdx.x * 128;
    const int g = lane >> 2, q2 = (lane & 3) * 2;
    const int srow = s0 + w * 16;
    const int boffA = b_lane_off(lane, APITCH);
    const unsigned uKh = smem_u32(sKh), uKl = smem_u32(sKl);
    const unsigned uVh = smem_u32(sVh), uVl = smem_u32(sVl);

    // Q fragments (A operand, row-major [s][d]), hi/lo, 4 k-slices of d
    unsigned qh[4][4], ql[4][4];
    {
        const bf16* Qh = g_qh + ((size_t)bh * Ss + srow) * HD;
        const bf16* Ql = g_ql + ((size_t)bh * Ss + srow) * HD;
#pragma unroll
        for (int ks = 0; ks < 4; ks++) {
            qh[ks][0] = *(const unsigned*)(Qh + (size_t)g * HD + ks * 16 + q2);
            qh[ks][1] = *(const unsigned*)(Qh + (size_t)(g + 8) * HD + ks * 16 + q2);
            qh[ks][2] = *(const unsigned*)(Qh + (size_t)g * HD + ks * 16 + q2 + 8);
            qh[ks][3] = *(const unsigned*)(Qh + (size_t)(g + 8) * HD + ks * 16 + q2 + 8);
            ql[ks][0] = *(const unsigned*)(Ql + (size_t)g * HD + ks * 16 + q2);
            ql[ks][1] = *(const unsigned*)(Ql + (size_t)(g + 8) * HD + ks * 16 + q2);
            ql[ks][2] = *(const unsigned*)(Ql + (size_t)g * HD + ks * 16 + q2 + 8);
            ql[ks][3] = *(const unsigned*)(Ql + (size_t)(g + 8) * HD + ks * 16 + q2 + 8);
        }
    }

    const bf16* Kh = g_kh + (size_t)bh * Ss * HD;
    const bf16* Kl = g_kl + (size_t)bh * Ss * HD;
    const bf16* Vh = g_vh + (size_t)bh * HD * Ss;
    const bf16* Vl = g_vl + (size_t)bh * HD * Ss;

    float m0 = -1e30f, m1 = -1e30f, l0 = 0.f, l1 = 0.f;
    float O[8][4] = {};

    for (int t0 = 0; t0 < Ss; t0 += 64) {
        // Stage K [t][d] and V [d][t] (hi/lo)
#pragma unroll
        for (int r = 0; r < 2; r++) {
            int idx = tid + r * 256;
            int row = idx >> 3, c8 = (idx & 7) * 8;
            *(uint4*)&sKh[row * APITCH + c8] = *(const uint4*)(Kh + (size_t)(t0 + row) * HD + c8);
            *(uint4*)&sKl[row * APITCH + c8] = *(const uint4*)(Kl + (size_t)(t0 + row) * HD + c8);
            *(uint4*)&sVh[row * APITCH + c8] = *(const uint4*)(Vh + (size_t)row * Ss + t0 + c8);
            *(uint4*)&sVl[row * APITCH + c8] = *(const uint4*)(Vl + (size_t)row * Ss + t0 + c8);
        }
        __syncthreads();

        // Scores: 16 s x 64 t per warp
        float sc[8][4] = {};
#pragma unroll
        for (int ks = 0; ks < 4; ks++) {
#pragma unroll
            for (int j = 0; j < 8; j++) {
                const unsigned off = 2u * (j * 8 * APITCH + ks * 16 + boffA);
                unsigned kbh[2], kbl[2];
                ldsm_x2(kbh[0], kbh[1], uKh + off);
                ldsm_x2(kbl[0], kbl[1], uKl + off);
                mma_bf16(sc[j], qh[ks], kbh);
                mma_bf16(sc[j], qh[ks], kbl);
                mma_bf16(sc[j], ql[ks], kbh);
            }
        }

        // Online softmax: lane rows g (c0,c1) and g+8 (c2,c3)
        float mx0 = -1e30f, mx1 = -1e30f;
#pragma unroll
        for (int j = 0; j < 8; j++) {
            mx0 = fmaxf(mx0, fmaxf(sc[j][0], sc[j][1]));
            mx1 = fmaxf(mx1, fmaxf(sc[j][2], sc[j][3]));
        }
        mx0 = fmaxf(mx0, __shfl_xor_sync(0xffffffffu, mx0, 1));
        mx0 = fmaxf(mx0, __shfl_xor_sync(0xffffffffu, mx0, 2));
        mx1 = fmaxf(mx1, __shfl_xor_sync(0xffffffffu, mx1, 1));
        mx1 = fmaxf(mx1, __shfl_xor_sync(0xffffffffu, mx1, 2));
        const float nm0 = fmaxf(m0, mx0), nm1 = fmaxf(m1, mx1);
        const float cr0 = __expf(m0 - nm0), cr1 = __expf(m1 - nm1);
        m0 = nm0; m1 = nm1;

        unsigned ph[4][4], pl[4][4];
        float ss0 = 0.f, ss1 = 0.f;
#pragma unroll
        for (int j = 0; j < 8; j++) {
            float p0 = __expf(sc[j][0] - m0), p1 = __expf(sc[j][1] - m0);
            float p2 = __expf(sc[j][2] - m1), p3 = __expf(sc[j][3] - m1);
            ss0 += p0 + p1; ss1 += p2 + p3;
            const int kt = j >> 1;
            if ((j & 1) == 0) {
                split2(p0, p1, ph[kt][0], pl[kt][0]);
                split2(p2, p3, ph[kt][1], pl[kt][1]);
            } else {
                split2(p0, p1, ph[kt][2], pl[kt][2]);
                split2(p2, p3, ph[kt][3], pl[kt][3]);
            }
        }
        ss0 += __shfl_xor_sync(0xffffffffu, ss0, 1);
        ss0 += __shfl_xor_sync(0xffffffffu, ss0, 2);
        ss1 += __shfl_xor_sync(0xffffffffu, ss1, 1);
        ss1 += __shfl_xor_sync(0xffffffffu, ss1, 2);
        l0 = l0 * cr0 + ss0;
        l1 = l1 * cr1 + ss1;

        // Correct O, then O += P @ V
#pragma unroll
        for (int jd = 0; jd < 8; jd++) {
            O[jd][0] *= cr0; O[jd][1] *= cr0;
            O[jd][2] *= cr1; O[jd][3] *= cr1;
        }
#pragma unroll
        for (int kt = 0; kt < 4; kt++) {
#pragma unroll
            for (int jd = 0; jd < 8; jd++) {
                const unsigned off = 2u * (jd * 8 * APITCH + kt * 16 + boffA);
                unsigned vbh[2], vbl[2];
                ldsm_x2(vbh[0], vbh[1], uVh + off);
                ldsm_x2(vbl[0], vbl[1], uVl + off);
                mma_bf16(O[jd], ph[kt], vbh);
                mma_bf16(O[jd], ph[kt], vbl);
                mma_bf16(O[jd], pl[kt], vbh);
            }
        }
        __syncthreads();
    }

    // Finalize: O/l, write bf16 split to hf[b*S+s][hh*64+d]
    const float inv0 = __fdividef(1.f, l0), inv1 = __fdividef(1.f, l1);
    const size_t base = ((size_t)b * Ss + srow) * Cc + hh * HD;
#pragma unroll
    for (int jd = 0; jd < 8; jd++) {
        const int d = jd * 8 + q2;
        float a0 = O[jd][0] * inv0, a1 = O[jd][1] * inv0;
        float a2 = O[jd][2] * inv1, a3 = O[jd][3] * inv1;
        const size_t i0 = base + (size_t)g * Cc + d;
        const size_t i1 = base + (size_t)(g + 8) * Cc + d;
        unsigned h, l;
        split2(a0, a1, h, l);
        *(unsigned*)(g_hfh0 + i0) = h;
        *(unsigned*)(g_hfl0 + i0) = l;
        split2(a2, a3, h, l);
        *(unsigned*)(g_hfh0 + i1) = h;
        *(unsigned*)(g_hfl0 + i1) = l;
    }
}

// ---------------------------------------------------------------------------
// INL step (NT tensor-core GEMM + fused Euler/tanh epilogue).
// prev is reconstructed from the split input (hi + lo).
// ---------------------------------------------------------------------------
__global__ void __launch_bounds__(256) inl_mma(int src, const float* __restrict__ bias) {
    __shared__ __align__(16) bf16 sAhi[128 * PITCH];
    __shared__ __align__(16) bf16 sAlo[128 * PITCH];
    __shared__ __align__(16) bf16 sBhi[128 * PITCH];
    __shared__ __align__(16) bf16 sBlo[128 * PITCH];

    const bf16* Ahi = src ? g_hfh1 : g_hfh0;
    const bf16* Alo = src ? g_hfl1 : g_hfl0;
    bf16* outh = src ? g_hfh0 : g_hfh1;
    bf16* outl = src ? g_hfl0 : g_hfl1;

    const int n0 = blockIdx.x * 128;
    const int m0 = blockIdx.y * 128;
    const int tid = threadIdx.x;
    const int lane = tid & 31;
    const int wid = tid >> 5;
    const int wm = (wid >> 2) * 64, wn = (wid & 3) * 32;
    const int aoff = a_lane_off(lane, PITCH), boff = b_lane_off(lane, PITCH);
    const unsigned uAhi = smem_u32(sAhi), uAlo = smem_u32(sAlo);
    const unsigned uBhi = smem_u32(sBhi), uBlo = smem_u32(sBlo);

    const int r = tid >> 1, kq = (tid & 1) * 16;
    const bf16* pAh = Ahi + (size_t)(m0 + r) * Cc + kq;
    const bf16* pAl = Alo + (size_t)(m0 + r) * Cc + kq;
    const bf16* pBh = g_wi_hi + (size_t)(n0 + r) * Cc + kq;
    const bf16* pBl = g_wi_lo + (size_t)(n0 + r) * Cc + kq;

    float acc[16][4] = {};

    uint4 nAh0 = *(const uint4*)pAh, nAh1 = *(const uint4*)(pAh + 8);
    uint4 nAl0 = *(const uint4*)pAl, nAl1 = *(const uint4*)(pAl + 8);
    uint4 nBh0 = *(const uint4*)pBh, nBh1 = *(const uint4*)(pBh + 8);
    uint4 nBl0 = *(const uint4*)pBl, nBl1 = *(const uint4*)(pBl + 8);

    for (int k0 = 0; k0 < Cc; k0 += 32) {
        *(uint4*)&sAhi[r * PITCH + kq] = nAh0;
        *(uint4*)&sAhi[r * PITCH + kq + 8] = nAh1;
        *(uint4*)&sAlo[r * PITCH + kq] = nAl0;
        *(uint4*)&sAlo[r * PITCH + kq + 8] = nAl1;
        *(uint4*)&sBhi[r * PITCH + kq] = nBh0;
        *(uint4*)&sBhi[r * PITCH + kq + 8] = nBh1;
        *(uint4*)&sBlo[r * PITCH + kq] = nBl0;
        *(uint4*)&sBlo[r * PITCH + kq + 8] = nBl1;
        __syncthreads();
        if (k0 + 32 < Cc) {
            nAh0 = *(const uint4*)(pAh + k0 + 32);
            nAh1 = *(const uint4*)(pAh + k0 + 40);
            nAl0 = *(const uint4*)(pAl + k0 + 32);
            nAl1 = *(const uint4*)(pAl + k0 + 40);
            nBh0 = *(const uint4*)(pBh + k0 + 32);
            nBh1 = *(const uint4*)(pBh + k0 + 40);
            nBl0 = *(const uint4*)(pBl + k0 + 32);
            nBl1 = *(const uint4*)(pBl + k0 + 40);
        }
        frag_step(uAhi, uAlo, uBhi, uBlo, aoff, boff, wm, wn, 0, acc);
        frag_step(uAhi, uAlo, uBhi, uBlo, aoff, boff, wm, wn, 1, acc);
        __syncthreads();
    }

    const int g2 = lane >> 2, tq = (lane & 3) * 2;
#pragma unroll
    for (int i = 0; i < 4; i++) {
        const int r1 = m0 + wm + i * 16 + g2;
#pragma unroll
        for (int j = 0; j < 4; j++) {
            const int o = n0 + wn + j * 8 + tq;
            const float b0 = bias[o], b1 = bias[o + 1];
            float* c = acc[i * 4 + j];
#pragma unroll
            for (int h = 0; h < 2; h++) {
                const size_t rr = (size_t)(r1 + h * 8) * Cc + o;
                float2 prev = join2(*(const unsigned*)(Ahi + rr),
                                    *(const unsigned*)(Alo + rr));
                float v0 = prev.x + 0.1f * fast_tanh(c[h * 2 + 0] + b0);
                float v1 = prev.y + 0.1f * fast_tanh(c[h * 2 + 1] + b1);
                unsigned uh, ul;
                split2(v0, v1, uh, ul);
                *(unsigned*)(outh + rr) = uh;
                *(unsigned*)(outl + rr) = ul;
            }
        }
    }
}

// ---------------------------------------------------------------------------
// Proj (NT tensor-core GEMM + fused residual, transposed write).
// ---------------------------------------------------------------------------
__global__ void __launch_bounds__(256) proj_mma(const float* __restrict__ bias,
                                                const float* __restrict__ x,
                                                float* __restrict__ out) {
    __shared__ __align__(16) bf16 sAhi[128 * PITCH];
    __shared__ __align__(16) bf16 sAlo[128 * PITCH];
    __shared__ __align__(16) bf16 sBhi[128 * PITCH];
    __shared__ __align__(16) bf16 sBlo[128 * PITCH];

    const int n0 = blockIdx.x * 128;
    const int m0 = blockIdx.y * 128;
    const int tid = threadIdx.x;
    const int lane = tid & 31;
    const int wid = tid >> 5;
    const int wm = (wid >> 2) * 64, wn = (wid & 3) * 32;
    const int aoff = a_lane_off(lane, PITCH), boff = b_lane_off(lane, PITCH);
    const unsigned uAhi = smem_u32(sAhi), uAlo = smem_u32(sAlo);
    const unsigned uBhi = smem_u32(sBhi), uBlo = smem_u32(sBlo);

    const int r = tid >> 1, kq = (tid & 1) * 16;
    const bf16* pAh = g_hfh1 + (size_t)(m0 + r) * Cc + kq;
    const bf16* pAl = g_hfl1 + (size_t)(m0 + r) * Cc + kq;
    const bf16* pBh = g_wp_hi + (size_t)(n0 + r) * Cc + kq;
    const bf16* pBl = g_wp_lo + (size_t)(n0 + r) * Cc + kq;

    float acc[16][4] = {};

    uint4 nAh0 = *(const uint4*)pAh, nAh1 = *(const uint4*)(pAh + 8);
    uint4 nAl0 = *(const uint4*)pAl, nAl1 = *(const uint4*)(pAl + 8);
    uint4 nBh0 = *(const uint4*)pBh, nBh1 = *(const uint4*)(pBh + 8);
    uint4 nBl0 = *(const uint4*)pBl, nBl1 = *(const uint4*)(pBl + 8);

    for (int k0 = 0; k0 < Cc; k0 += 32) {
        *(uint4*)&sAhi[r * PITCH + kq] = nAh0;
        *(uint4*)&sAhi[r * PITCH + kq + 8] = nAh1;
        *(uint4*)&sAlo[r * PITCH + kq] = nAl0;
        *(uint4*)&sAlo[r * PITCH + kq + 8] = nAl1;
        *(uint4*)&sBhi[r * PITCH + kq] = nBh0;
        *(uint4*)&sBhi[r * PITCH + kq + 8] = nBh1;
        *(uint4*)&sBlo[r * PITCH + kq] = nBl0;
        *(uint4*)&sBlo[r * PITCH + kq + 8] = nBl1;
        __syncthreads();
        if (k0 + 32 < Cc) {
            nAh0 = *(const uint4*)(pAh + k0 + 32);
            nAh1 = *(const uint4*)(pAh + k0 + 40);
            nAl0 = *(const uint4*)(pAl + k0 + 32);
            nAl1 = *(const uint4*)(pAl + k0 + 40);
            nBh0 = *(const uint4*)(pBh + k0 + 32);
            nBh1 = *(const uint4*)(pBh + k0 + 40);
            nBl0 = *(const uint4*)(pBl + k0 + 32);
            nBl1 = *(const uint4*)(pBl + k0 + 40);
        }
        frag_step(uAhi, uAlo, uBhi, uBlo, aoff, boff, wm, wn, 0, acc);
        frag_step(uAhi, uAlo, uBhi, uBlo, aoff, boff, wm, wn, 1, acc);
        __syncthreads();
    }

    const int g2 = lane >> 2, tq = (lane & 3) * 2;
    const int b = m0 >> 10;
#pragma unroll
    for (int i = 0; i < 4; i++) {
        const int s1 = (m0 & 1023) + wm + i * 16 + g2;
#pragma unroll
        for (int j = 0; j < 4; j++) {
            const int o = n0 + wn + j * 8 + tq;
            const float b0 = bias[o], b1 = bias[o + 1];
            float* c = acc[i * 4 + j];
#pragma unroll
            for (int h = 0; h < 2; h++) {
                const int s = s1 + h * 8;
                const size_t i0 = ((size_t)b * Cc + o) * Ss + s;
                const size_t i1 = i0 + Ss;
                out[i0] = x[i0] + c[h * 2 + 0] + b0;
                out[i1] = x[i1] + c[h * 2 + 1] + b1;
            }
        }
    }
}

// ---------------------------------------------------------------------------
extern "C" void kernel_launch(void* const* d_in, const int* in_sizes, int n_in,
                              void* d_out, int out_size) {
    const float* x = (const float*)d_in[0];
    const float* gn_scale = (const float*)d_in[1];
    const float* gn_bias = (const float*)d_in[2];
    const float* qkv_w = (const float*)d_in[3];
    const float* qkv_b = (const float*)d_in[4];
    const float* proj_w = (const float*)d_in[5];
    const float* proj_b = (const float*)d_in[6];
    const float* inl_w = (const float*)d_in[7];
    const float* inl_b = (const float*)d_in[8];
    float* out = (float*)d_out;

    // 0. Convert weights to bf16 hi/lo
    bf16 *wq_hi, *wq_lo, *wi_hi, *wi_lo, *wp_hi, *wp_lo;
    cudaGetSymbolAddress((void**)&wq_hi, g_wq_hi);
    cudaGetSymbolAddress((void**)&wq_lo, g_wq_lo);
    cudaGetSymbolAddress((void**)&wi_hi, g_wi_hi);
    cudaGetSymbolAddress((void**)&wi_lo, g_wi_lo);
    cudaGetSymbolAddress((void**)&wp_hi, g_wp_hi);
    cudaGetSymbolAddress((void**)&wp_lo, g_wp_lo);
    convw<<<(M3 * Cc) / 1024, 256>>>(qkv_w, wq_hi, wq_lo, M3 * Cc);
    convw<<<(Cc * Cc) / 1024, 256>>>(inl_w, wi_hi, wi_lo, Cc * Cc);
    convw<<<(Cc * Cc) / 1024, 256>>>(proj_w, wp_hi, wp_lo, Cc * Cc);

    // 1. GroupNorm (2-phase) -> g_h_hi/lo
    gn_stats<<<512, 256>>>(x);
    gn_apply<<<512, 256>>>(x, gn_scale, gn_bias);

    // 2. QKV GEMM (tensor cores) -> g_qkv fp32 (q/k) + g_vh/g_vl (v)
    qkv_mma<<<dim3(Ss / 128, M3 / 128, Bb), 256>>>(qkv_b);

    // 2b. Q/K transpose + convert
    qk_conv<<<dim3(16, 64, 2), 256>>>();

    // 3. Attention (tensor cores) -> g_hfh0/g_hfl0
    attn_mma<<<dim3(Ss / 128, Bb * NH), 256>>>();

    // 4. INL: 3 Euler steps (ping-pong split buffers), ends in g_hfh1/g_hfl1
    inl_mma<<<dim3(Cc / 128, Bb * Ss / 128), 256>>>(0, inl_b);
    inl_mma<<<dim3(Cc / 128, Bb * Ss / 128), 256>>>(1, inl_b);
    inl_mma<<<dim3(Cc / 128, Bb * Ss / 128), 256>>>(0, inl_b);

    // 5. Proj + residual -> d_out
    proj_mma<<<dim3(Cc / 128, Bb * Ss / 128), 256>>>(proj_b, x, out);
}

// round 12
// speedup vs baseline: 1.7874x; 1.0726x over previous
#include <cuda_runtime.h>
#include <cuda_bf16.h>
#include <math.h>

typedef __nv_bfloat16 bf16;

// Problem constants
constexpr int Bb = 8;
constexpr int Cc = 512;
constexpr int Ss = 1024;     // H*W
constexpr int M3 = 1536;     // 3*C
constexpr int NH = 8;
constexpr int HD = 64;

constexpr int PITCH = 40;    // dense-GEMM smem row pitch (32 data + 8 pad)
constexpr int APITCH = 72;   // attention smem row pitch (64 data + 8 pad)

constexpr int DB = 128 * PITCH;     // one dense array (bf16 units)
constexpr int DBUF = 4 * DB;        // one dense buffer (Ahi,Alo,Bhi,Blo)
constexpr int AB = 64 * APITCH;     // one attention array
constexpr int ABUF = 4 * AB;        // one attention buffer (Kh,Kl,Vh,Vl)
constexpr int DENSE_SMEM = 2 * DBUF * 2;  // bytes (81920)
constexpr int ATTN_SMEM = 2 * ABUF * 2;   // bytes (73728)

// Scratch buffers (static device globals; allocation is forbidden)
__device__ __align__(16) bf16 g_h_hi[Bb * Cc * Ss];
__device__ __align__(16) bf16 g_h_lo[Bb * Cc * Ss];
__device__ float g_qkv[Bb * M3 * Ss];                // fp32, only q/k thirds used
__device__ __align__(16) bf16 g_hfh0[Bb * Ss * Cc];
__device__ __align__(16) bf16 g_hfl0[Bb * Ss * Cc];
__device__ __align__(16) bf16 g_hfh1[Bb * Ss * Cc];
__device__ __align__(16) bf16 g_hfl1[Bb * Ss * Cc];
__device__ __align__(16) bf16 g_wq_hi[M3 * Cc];
__device__ __align__(16) bf16 g_wq_lo[M3 * Cc];
__device__ __align__(16) bf16 g_wi_hi[Cc * Cc];
__device__ __align__(16) bf16 g_wi_lo[Cc * Cc];
__device__ __align__(16) bf16 g_wp_hi[Cc * Cc];
__device__ __align__(16) bf16 g_wp_lo[Cc * Cc];
// Attention operand layouts (split bf16)
__device__ __align__(16) bf16 g_qh[Bb * NH * Ss * HD];  // [bh][s][d], scaled
__device__ __align__(16) bf16 g_ql[Bb * NH * Ss * HD];
__device__ __align__(16) bf16 g_kh[Bb * NH * Ss * HD];  // [bh][t][d]
__device__ __align__(16) bf16 g_kl[Bb * NH * Ss * HD];
__device__ __align__(16) bf16 g_vh[Bb * NH * HD * Ss];  // [bh][d][t]
__device__ __align__(16) bf16 g_vl[Bb * NH * HD * Ss];
__device__ float g_gnp[512][2];                          // groupnorm partials

__device__ __forceinline__ float fast_tanh(float x) {
    x = fminf(fmaxf(x, -15.f), 15.f);
    float e = __expf(2.f * x);
    return __fdividef(e - 1.f, e + 1.f);
}

__device__ __forceinline__ void split2(float x, float y, unsigned& hi, unsigned& lo) {
    bf16 hx = __float2bfloat16(x), hy = __float2bfloat16(y);
    float rx = x - __bfloat162float(hx);
    float ry = y - __bfloat162float(hy);
    bf16 lx = __float2bfloat16(rx), ly = __float2bfloat16(ry);
    hi = ((unsigned)__bfloat16_as_ushort(hy) << 16) | (unsigned)__bfloat16_as_ushort(hx);
    lo = ((unsigned)__bfloat16_as_ushort(ly) << 16) | (unsigned)__bfloat16_as_ushort(lx);
}

__device__ __forceinline__ float2 join2(unsigned h, unsigned l) {
    float x = __bfloat162float(__ushort_as_bfloat16((unsigned short)(h & 0xffffu)))
            + __bfloat162float(__ushort_as_bfloat16((unsigned short)(l & 0xffffu)));
    float y = __bfloat162float(__ushort_as_bfloat16((unsigned short)(h >> 16)))
            + __bfloat162float(__ushort_as_bfloat16((unsigned short)(l >> 16)));
    return make_float2(x, y);
}

__device__ __forceinline__ void mma_bf16(float* c, const unsigned* a, const unsigned* b) {
    asm("mma.sync.aligned.m16n8k16.row.col.f32.bf16.bf16.f32 "
        "{%0,%1,%2,%3}, {%4,%5,%6,%7}, {%8,%9}, {%0,%1,%2,%3};"
        : "+f"(c[0]), "+f"(c[1]), "+f"(c[2]), "+f"(c[3])
        : "r"(a[0]), "r"(a[1]), "r"(a[2]), "r"(a[3]), "r"(b[0]), "r"(b[1]));
}

__device__ __forceinline__ unsigned smem_u32(const void* p) {
    return (unsigned)__cvta_generic_to_shared(p);
}
__device__ __forceinline__ void ldsm_x4(unsigned& r0, unsigned& r1, unsigned& r2,
                                        unsigned& r3, unsigned a) {
    asm volatile("ldmatrix.sync.aligned.m8n8.x4.shared.b16 {%0,%1,%2,%3}, [%4];"
                 : "=r"(r0), "=r"(r1), "=r"(r2), "=r"(r3) : "r"(a));
}
__device__ __forceinline__ void ldsm_x2(unsigned& r0, unsigned& r1, unsigned a) {
    asm volatile("ldmatrix.sync.aligned.m8n8.x2.shared.b16 {%0,%1}, [%2];"
                 : "=r"(r0), "=r"(r1) : "r"(a));
}

// cp.async helpers (16B copies)
__device__ __forceinline__ void cp16(unsigned dst, const void* src) {
    asm volatile("cp.async.cg.shared.global [%0], [%1], 16;" :: "r"(dst), "l"(src));
}
__device__ __forceinline__ void cp_commit() {
    asm volatile("cp.async.commit_group;");
}
__device__ __forceinline__ void cp_wait1() {
    asm volatile("cp.async.wait_group 1;");
}

// Per-lane ldmatrix offsets (bf16 units).
__device__ __forceinline__ int a_lane_off(int lane, int pitch) {
    return ((lane & 7) + ((lane >> 3) & 1) * 8) * pitch + ((lane >> 4) & 1) * 8;
}
__device__ __forceinline__ int b_lane_off(int lane, int pitch) {
    return (lane & 7) * pitch + ((lane >> 3) & 1) * 8;
}

// One k16 step for the dense GEMMs.
__device__ __forceinline__ void frag_step(
    unsigned uAhi, unsigned uAlo, unsigned uBhi, unsigned uBlo,
    int aoff, int boff, int wm, int wn, int ks, float acc[16][4]) {
    unsigned ah[4][4], al[4][4], bh[4][2], bl[4][2];
#pragma unroll
    for (int i = 0; i < 4; i++) {
        const unsigned off = 2u * ((wm + i * 16) * PITCH + ks * 16 + aoff);
        ldsm_x4(ah[i][0], ah[i][1], ah[i][2], ah[i][3], uAhi + off);
        ldsm_x4(al[i][0], al[i][1], al[i][2], al[i][3], uAlo + off);
    }
#pragma unroll
    for (int j = 0; j < 4; j++) {
        const unsigned off = 2u * ((wn + j * 8) * PITCH + ks * 16 + boff);
        ldsm_x2(bh[j][0], bh[j][1], uBhi + off);
        ldsm_x2(bl[j][0], bl[j][1], uBlo + off);
    }
#pragma unroll
    for (int i = 0; i < 4; i++)
#pragma unroll
        for (int j = 0; j < 4; j++) {
            mma_bf16(acc[i * 4 + j], ah[i], bh[j]);
            mma_bf16(acc[i * 4 + j], ah[i], bl[j]);
            mma_bf16(acc[i * 4 + j], al[i], bh[j]);
        }
}

// ---------------------------------------------------------------------------
// Weight convert: fp32 -> bf16 hi/lo
// ---------------------------------------------------------------------------
__global__ void convw(const float* __restrict__ src, bf16* __restrict__ hi,
                      bf16* __restrict__ lo, int n) {
    int i = (blockIdx.x * 256 + threadIdx.x) * 4;
    if (i < n) {
        float4 v = *(const float4*)(src + i);
        uint2 uh, ul;
        split2(v.x, v.y, uh.x, ul.x);
        split2(v.z, v.w, uh.y, ul.y);
        *(uint2*)(hi + i) = uh;
        *(uint2*)(lo + i) = ul;
    }
}

// ---------------------------------------------------------------------------
// GroupNorm phase 1: partial sums. grid 512.
// ---------------------------------------------------------------------------
__global__ void gn_stats(const float* __restrict__ x) {
    const int grp = blockIdx.x >> 3;
    const int slice = blockIdx.x & 7;
    const float* xp = x + (size_t)grp * 65536 + slice * 8192;
    float s = 0.f, s2 = 0.f;
#pragma unroll
    for (int r = 0; r < 8; r++) {
        float4 v = *(const float4*)(xp + (threadIdx.x + r * 256) * 4);
        s += v.x + v.y + v.z + v.w;
        s2 += v.x * v.x + v.y * v.y + v.z * v.z + v.w * v.w;
    }
    __shared__ float rs[256], rs2[256];
    rs[threadIdx.x] = s; rs2[threadIdx.x] = s2;
    __syncthreads();
    for (int o = 128; o > 0; o >>= 1) {
        if (threadIdx.x < o) {
            rs[threadIdx.x] += rs[threadIdx.x + o];
            rs2[threadIdx.x] += rs2[threadIdx.x + o];
        }
        __syncthreads();
    }
    if (threadIdx.x == 0) {
        g_gnp[blockIdx.x][0] = rs[0];
        g_gnp[blockIdx.x][1] = rs2[0];
    }
}

// ---------------------------------------------------------------------------
// GroupNorm phase 2: finalize + apply. grid 512.
// ---------------------------------------------------------------------------
__global__ void gn_apply(const float* __restrict__ x,
                         const float* __restrict__ scale,
                         const float* __restrict__ bias) {
    const int grp = blockIdx.x >> 3;
    const int slice = blockIdx.x & 7;
    float s = 0.f, s2 = 0.f;
#pragma unroll
    for (int p = 0; p < 8; p++) { s += g_gnp[grp * 8 + p][0]; s2 += g_gnp[grp * 8 + p][1]; }
    const float mean = s / 65536.f;
    float var = s2 / 65536.f - mean * mean;
    var = fmaxf(var, 0.f);
    const float rstd = rsqrtf(var + 1e-5f);

    const size_t base = (size_t)grp * 65536 + slice * 8192;
    const int cbase = (grp & 7) * 64 + slice * 8;
#pragma unroll
    for (int r = 0; r < 8; r++) {
        const int k = (threadIdx.x + r * 256) * 4;
        const int c = cbase + (k >> 10);
        const float a = rstd * scale[c];
        const float bb2 = bias[c] - mean * a;
        float4 v = *(const float4*)(x + base + k);
        float4 o = make_float4(v.x * a + bb2, v.y * a + bb2,
                               v.z * a + bb2, v.w * a + bb2);
        uint2 uh, ul;
        split2(o.x, o.y, uh.x, ul.x);
        split2(o.z, o.w, uh.y, ul.y);
        *(uint2*)(g_h_hi + base + k) = uh;
        *(uint2*)(g_h_lo + base + k) = ul;
    }
}

// ---------------------------------------------------------------------------
// QKV GEMM (NN): A via cp.async double-buffer, B via register transpose.
// ---------------------------------------------------------------------------
__global__ void __launch_bounds__(256) qkv_mma(const float* __restrict__ bias) {
    extern __shared__ __align__(16) bf16 dsm[];
    const int b = blockIdx.z;
    const int n0 = blockIdx.x * 128;
    const int m0 = blockIdx.y * 128;
    const int tid = threadIdx.x;
    const int lane = tid & 31;
    const int wid = tid >> 5;
    const int wm = (wid >> 2) * 64, wn = (wid & 3) * 32;
    const int aoff = a_lane_off(lane, PITCH), boff = b_lane_off(lane, PITCH);
    const unsigned u0 = smem_u32(dsm);

    const bf16* Hhi = g_h_hi + (size_t)b * Cc * Ss;
    const bf16* Hlo = g_h_lo + (size_t)b * Cc * Ss;

    const int r = tid >> 1, kq = (tid & 1) * 16;
    const bf16* pAh = g_wq_hi + (size_t)(m0 + r) * Cc + kq;
    const bf16* pAl = g_wq_lo + (size_t)(m0 + r) * Cc + kq;
    const unsigned doff = 2u * (r * PITCH + kq);

    auto issueA = [&](int k0, int bi) {
        const unsigned base = u0 + (unsigned)bi * (DBUF * 2);
        cp16(base + doff, pAh + k0);
        cp16(base + doff + 16, pAh + k0 + 8);
        cp16(base + DB * 2 + doff, pAl + k0);
        cp16(base + DB * 2 + doff + 16, pAl + k0 + 8);
    };

    float acc[16][4] = {};

    // Prologue: B regs for k0=0; A cp.async two stages deep.
    unsigned nh0[4], nh1[4], nl0[4], nl1[4];
#pragma unroll
    for (int q = 0; q < 4; q++) {
        int bi = tid + q * 256;
        int kb = bi >> 6, nb = bi & 63;
        const bf16* ph = Hhi + (size_t)(2 * kb) * Ss + n0 + 2 * nb;
        const bf16* pl = Hlo + (size_t)(2 * kb) * Ss + n0 + 2 * nb;
        nh0[q] = *(const unsigned*)ph; nh1[q] = *(const unsigned*)(ph + Ss);
        nl0[q] = *(const unsigned*)pl; nl1[q] = *(const unsigned*)(pl + Ss);
    }
    issueA(0, 0); cp_commit();
    issueA(32, 1); cp_commit();

    for (int k0 = 0, it = 0; k0 < Cc; k0 += 32, ++it) {
        bf16* buf = dsm + (it & 1) * DBUF;
        bf16* sBhi = buf + 2 * DB;
        bf16* sBlo = buf + 3 * DB;
        // Store current B tile (transposed) into this buffer
#pragma unroll
        for (int q = 0; q < 4; q++) {
            int bi = tid + q * 256;
            int kb = bi >> 6, nb = bi & 63;
            *(unsigned*)&sBhi[(2 * nb) * PITCH + 2 * kb] = __byte_perm(nh0[q], nh1[q], 0x5410);
            *(unsigned*)&sBhi[(2 * nb + 1) * PITCH + 2 * kb] = __byte_perm(nh0[q], nh1[q], 0x7632);
            *(unsigned*)&sBlo[(2 * nb) * PITCH + 2 * kb] = __byte_perm(nl0[q], nl1[q], 0x5410);
            *(unsigned*)&sBlo[(2 * nb + 1) * PITCH + 2 * kb] = __byte_perm(nl0[q], nl1[q], 0x7632);
        }
        cp_wait1();
        __syncthreads();
        if (k0 + 32 < Cc) {
#pragma unroll
            for (int q = 0; q < 4; q++) {
                int bi = tid + q * 256;
                int kb = bi >> 6, nb = bi & 63;
                const bf16* ph = Hhi + (size_t)(k0 + 32 + 2 * kb) * Ss + n0 + 2 * nb;
                const bf16* pl = Hlo + (size_t)(k0 + 32 + 2 * kb) * Ss + n0 + 2 * nb;
                nh0[q] = *(const unsigned*)ph; nh1[q] = *(const unsigned*)(ph + Ss);
                nl0[q] = *(const unsigned*)pl; nl1[q] = *(const unsigned*)(pl + Ss);
            }
        }
        const unsigned ub = u0 + (it & 1) * (DBUF * 2);
        frag_step(ub, ub + DB * 2, ub + 2 * DB * 2, ub + 3 * DB * 2,
                  aoff, boff, wm, wn, 0, acc);
        frag_step(ub, ub + DB * 2, ub + 2 * DB * 2, ub + 3 * DB * 2,
                  aoff, boff, wm, wn, 1, acc);
        __syncthreads();
        if (k0 + 64 < Cc) issueA(k0 + 64, it & 1);
        cp_commit();
    }

    const int g2 = lane >> 2, tq = (lane & 3) * 2;
    if (m0 < 1024) {
        float* out = g_qkv + (size_t)b * M3 * Ss;
#pragma unroll
        for (int i = 0; i < 4; i++) {
            const int m1 = m0 + wm + i * 16 + g2;
            const float bv1 = bias[m1], bv2 = bias[m1 + 8];
#pragma unroll
            for (int j = 0; j < 4; j++) {
                const int n = n0 + wn + j * 8 + tq;
                float* c = acc[i * 4 + j];
                *(float2*)(out + (size_t)m1 * Ss + n) = make_float2(c[0] + bv1, c[1] + bv1);
                *(float2*)(out + (size_t)(m1 + 8) * Ss + n) = make_float2(c[2] + bv2, c[3] + bv2);
            }
        }
    } else {
#pragma unroll
        for (int i = 0; i < 4; i++) {
            const int m1 = m0 + wm + i * 16 + g2;
            const float bv1 = bias[m1], bv2 = bias[m1 + 8];
#pragma unroll
            for (int j = 0; j < 4; j++) {
                const int n = n0 + wn + j * 8 + tq;
                float* c = acc[i * 4 + j];
                const size_t i0 = (size_t)b * 524288 + (size_t)(m1 - 1024) * Ss + n;
                const size_t i1 = (size_t)b * 524288 + (size_t)(m1 - 1024 + 8) * Ss + n;
                unsigned h, l;
                split2(c[0] + bv1, c[1] + bv1, h, l);
                *(unsigned*)(g_vh + i0) = h;
                *(unsigned*)(g_vl + i0) = l;
                split2(c[2] + bv2, c[3] + bv2, h, l);
                *(unsigned*)(g_vh + i1) = h;
                *(unsigned*)(g_vl + i1) = l;
            }
        }
    }
}

// ---------------------------------------------------------------------------
// Q/K transpose+convert: [b][ch][s] fp32 -> [bh][s][d] bf16 hi/lo.
// ---------------------------------------------------------------------------
__global__ void qk_conv() {
    __shared__ float tile[64][65];
    const int tid = threadIdx.x;
    const int bh = blockIdx.y, b = bh >> 3, hh = bh & 7;
    const int st = blockIdx.x * 64;
    const int isK = blockIdx.z;
    const float* src = g_qkv + (size_t)b * M3 * Ss +
                       (size_t)(isK * Cc + hh * HD) * Ss + st;
#pragma unroll
    for (int r = 0; r < 4; r++) {
        int idx = tid + r * 256;
        int d = idx >> 4, s4 = (idx & 15) * 4;
        float4 v = *(const float4*)(src + (size_t)d * Ss + s4);
        tile[d][s4 + 0] = v.x; tile[d][s4 + 1] = v.y;
        tile[d][s4 + 2] = v.z; tile[d][s4 + 3] = v.w;
    }
    __syncthreads();
    bf16* oh = (isK ? g_kh : g_qh) + ((size_t)bh * Ss + st) * HD;
    bf16* ol = (isK ? g_kl : g_ql) + ((size_t)bh * Ss + st) * HD;
    const float scl = isK ? 1.f : 0.125f;
#pragma unroll
    for (int r = 0; r < 8; r++) {
        int idx = tid + r * 256;
        int s = idx >> 5, dp = (idx & 31) * 2;
        float xx = tile[dp][s] * scl, yy = tile[dp + 1][s] * scl;
        unsigned h, l;
        split2(xx, yy, h, l);
        *(unsigned*)(oh + (size_t)s * HD + dp) = h;
        *(unsigned*)(ol + (size_t)s * HD + dp) = l;
    }
}

// ---------------------------------------------------------------------------
// Attention via tensor cores, cp.async double-buffered K/V staging.
// ---------------------------------------------------------------------------
__global__ void __launch_bounds__(256) attn_mma() {
    extern __shared__ __align__(16) bf16 asm_[];
    const int tid = threadIdx.x, lane = tid & 31, w = tid >> 5;
    const int bh = blockIdx.y, b = bh >> 3, hh = bh & 7;
    const int s0 = blockIdx.x * 128;
    const int g = lane >> 2, q2 = (lane & 3) * 2;
    const int srow = s0 + w * 16;
    const int boffA = b_lane_off(lane, APITCH);
    const unsigned u0 = smem_u32(asm_);

    // Q fragments
    unsigned qh[4][4], ql[4][4];
    {
        const bf16* Qh = g_qh + ((size_t)bh * Ss + srow) * HD;
        const bf16* Ql = g_ql + ((size_t)bh * Ss + srow) * HD;
#pragma unroll
        for (int ks = 0; ks < 4; ks++) {
            qh[ks][0] = *(const unsigned*)(Qh + (size_t)g * HD + ks * 16 + q2);
            qh[ks][1] = *(const unsigned*)(Qh + (size_t)(g + 8) * HD + ks * 16 + q2);
            qh[ks][2] = *(const unsigned*)(Qh + (size_t)g * HD + ks * 16 + q2 + 8);
            qh[ks][3] = *(const unsigned*)(Qh + (size_t)(g + 8) * HD + ks * 16 + q2 + 8);
            ql[ks][0] = *(const unsigned*)(Ql + (size_t)g * HD + ks * 16 + q2);
            ql[ks][1] = *(const unsigned*)(Ql + (size_t)(g + 8) * HD + ks * 16 + q2);
            ql[ks][2] = *(const unsigned*)(Ql + (size_t)g * HD + ks * 16 + q2 + 8);
            ql[ks][3] = *(const unsigned*)(Ql + (size_t)(g + 8) * HD + ks * 16 + q2 + 8);
        }
    }

    const bf16* Kh = g_kh + (size_t)bh * Ss * HD;
    const bf16* Kl = g_kl + (size_t)bh * Ss * HD;
    const bf16* Vh = g_vh + (size_t)bh * HD * Ss;
    const bf16* Vl = g_vl + (size_t)bh * HD * Ss;

    // cp.async staging coords: 2 rows per thread
    const int row0 = tid >> 3, c8 = (tid & 7) * 8;
    auto issue = [&](int t0, int bi) {
        const unsigned base = u0 + (unsigned)bi * (ABUF * 2);
#pragma unroll
        for (int rr = 0; rr < 2; rr++) {
            const int row = row0 + rr * 32;
            const unsigned d = 2u * (row * APITCH + c8);
            cp16(base + d, Kh + (size_t)(t0 + row) * HD + c8);
            cp16(base + AB * 2 + d, Kl + (size_t)(t0 + row) * HD + c8);
            cp16(base + 2 * AB * 2 + d, Vh + (size_t)row * Ss + t0 + c8);
            cp16(base + 3 * AB * 2 + d, Vl + (size_t)row * Ss + t0 + c8);
        }
    };

    issue(0, 0); cp_commit();
    issue(64, 1); cp_commit();

    float m0 = -1e30f, m1 = -1e30f, l0 = 0.f, l1 = 0.f;
    float O[8][4] = {};

    for (int t0 = 0, it = 0; t0 < Ss; t0 += 64, ++it) {
        cp_wait1();
        __syncthreads();
        const unsigned ub = u0 + (it & 1) * (ABUF * 2);
        const unsigned uKh = ub, uKl = ub + AB * 2;
        const unsigned uVh = ub + 2 * AB * 2, uVl = ub + 3 * AB * 2;

        // Scores
        float sc[8][4] = {};
#pragma unroll
        for (int ks = 0; ks < 4; ks++) {
#pragma unroll
            for (int j = 0; j < 8; j++) {
                const unsigned off = 2u * (j * 8 * APITCH + ks * 16 + boffA);
                unsigned kbh[2], kbl[2];
                ldsm_x2(kbh[0], kbh[1], uKh + off);
                ldsm_x2(kbl[0], kbl[1], uKl + off);
                mma_bf16(sc[j], qh[ks], kbh);
                mma_bf16(sc[j], qh[ks], kbl);
                mma_bf16(sc[j], ql[ks], kbh);
            }
        }

        // Online softmax
        float mx0 = -1e30f, mx1 = -1e30f;
#pragma unroll
        for (int j = 0; j < 8; j++) {
            mx0 = fmaxf(mx0, fmaxf(sc[j][0], sc[j][1]));
            mx1 = fmaxf(mx1, fmaxf(sc[j][2], sc[j][3]));
        }
        mx0 = fmaxf(mx0, __shfl_xor_sync(0xffffffffu, mx0, 1));
        mx0 = fmaxf(mx0, __shfl_xor_sync(0xffffffffu, mx0, 2));
        mx1 = fmaxf(mx1, __shfl_xor_sync(0xffffffffu, mx1, 1));
        mx1 = fmaxf(mx1, __shfl_xor_sync(0xffffffffu, mx1, 2));
        const float nm0 = fmaxf(m0, mx0), nm1 = fmaxf(m1, mx1);
        const float cr0 = __expf(m0 - nm0), cr1 = __expf(m1 - nm1);
        m0 = nm0; m1 = nm1;

        unsigned ph[4][4], pl[4][4];
        float ss0 = 0.f, ss1 = 0.f;
#pragma unroll
        for (int j = 0; j < 8; j++) {
            float p0 = __expf(sc[j][0] - m0), p1 = __expf(sc[j][1] - m0);
            float p2 = __expf(sc[j][2] - m1), p3 = __expf(sc[j][3] - m1);
            ss0 += p0 + p1; ss1 += p2 + p3;
            const int kt = j >> 1;
            if ((j & 1) == 0) {
                split2(p0, p1, ph[kt][0], pl[kt][0]);
                split2(p2, p3, ph[kt][1], pl[kt][1]);
            } else {
                split2(p0, p1, ph[kt][2], pl[kt][2]);
                split2(p2, p3, ph[kt][3], pl[kt][3]);
            }
        }
        ss0 += __shfl_xor_sync(0xffffffffu, ss0, 1);
        ss0 += __shfl_xor_sync(0xffffffffu, ss0, 2);
        ss1 += __shfl_xor_sync(0xffffffffu, ss1, 1);
        ss1 += __shfl_xor_sync(0xffffffffu, ss1, 2);
        l0 = l0 * cr0 + ss0;
        l1 = l1 * cr1 + ss1;

#pragma unroll
        for (int jd = 0; jd < 8; jd++) {
            O[jd][0] *= cr0; O[jd][1] *= cr0;
            O[jd][2] *= cr1; O[jd][3] *= cr1;
        }
#pragma unroll
        for (int kt = 0; kt < 4; kt++) {
#pragma unroll
            for (int jd = 0; jd < 8; jd++) {
                const unsigned off = 2u * (jd * 8 * APITCH + kt * 16 + boffA);
                unsigned vbh[2], vbl[2];
                ldsm_x2(vbh[0], vbh[1], uVh + off);
                ldsm_x2(vbl[0], vbl[1], uVl + off);
                mma_bf16(O[jd], ph[kt], vbh);
                mma_bf16(O[jd], ph[kt], vbl);
                mma_bf16(O[jd], pl[kt], vbh);
            }
        }
        __syncthreads();
        if (t0 + 128 < Ss) issue(t0 + 128, it & 1);
        cp_commit();
    }

    // Finalize
    const float inv0 = __fdividef(1.f, l0), inv1 = __fdividef(1.f, l1);
    const size_t base = ((size_t)b * Ss + srow) * Cc + hh * HD;
#pragma unroll
    for (int jd = 0; jd < 8; jd++) {
        const int d = jd * 8 + q2;
        float a0 = O[jd][0] * inv0, a1 = O[jd][1] * inv0;
        float a2 = O[jd][2] * inv1, a3 = O[jd][3] * inv1;
        const size_t i0 = base + (size_t)g * Cc + d;
        const size_t i1 = base + (size_t)(g + 8) * Cc + d;
        unsigned h, l;
        split2(a0, a1, h, l);
        *(unsigned*)(g_hfh0 + i0) = h;
        *(unsigned*)(g_hfl0 + i0) = l;
        split2(a2, a3, h, l);
        *(unsigned*)(g_hfh0 + i1) = h;
        *(unsigned*)(g_hfl0 + i1) = l;
    }
}

// ---------------------------------------------------------------------------
// INL step: cp.async double-buffered NT GEMM + fused Euler/tanh epilogue.
// ---------------------------------------------------------------------------
__global__ void __launch_bounds__(256) inl_mma(int src, const float* __restrict__ bias) {
    extern __shared__ __align__(16) bf16 dsm[];
    const bf16* Ahi = src ? g_hfh1 : g_hfh0;
    const bf16* Alo = src ? g_hfl1 : g_hfl0;
    bf16* outh = src ? g_hfh0 : g_hfh1;
    bf16* outl = src ? g_hfl0 : g_hfl1;

    const int n0 = blockIdx.x * 128;
    const int m0 = blockIdx.y * 128;
    const int tid = threadIdx.x;
    const int lane = tid & 31;
    const int wid = tid >> 5;
    const int wm = (wid >> 2) * 64, wn = (wid & 3) * 32;
    const int aoff = a_lane_off(lane, PITCH), boff = b_lane_off(lane, PITCH);
    const unsigned u0 = smem_u32(dsm);

    const int r = tid >> 1, kq = (tid & 1) * 16;
    const bf16* pAh = Ahi + (size_t)(m0 + r) * Cc + kq;
    const bf16* pAl = Alo + (size_t)(m0 + r) * Cc + kq;
    const bf16* pBh = g_wi_hi + (size_t)(n0 + r) * Cc + kq;
    const bf16* pBl = g_wi_lo + (size_t)(n0 + r) * Cc + kq;
    const unsigned doff = 2u * (r * PITCH + kq);

    auto issue = [&](int k0, int bi) {
        const unsigned base = u0 + (unsigned)bi * (DBUF * 2);
        cp16(base + doff, pAh + k0);
        cp16(base + doff + 16, pAh + k0 + 8);
        cp16(base + DB * 2 + doff, pAl + k0);
        cp16(base + DB * 2 + doff + 16, pAl + k0 + 8);
        cp16(base + 2 * DB * 2 + doff, pBh + k0);
        cp16(base + 2 * DB * 2 + doff + 16, pBh + k0 + 8);
        cp16(base + 3 * DB * 2 + doff, pBl + k0);
        cp16(base + 3 * DB * 2 + doff + 16, pBl + k0 + 8);
    };

    issue(0, 0); cp_commit();
    issue(32, 1); cp_commit();

    float acc[16][4] = {};
    for (int k0 = 0, it = 0; k0 < Cc; k0 += 32, ++it) {
        cp_wait1();
        __syncthreads();
        const unsigned ub = u0 + (it & 1) * (DBUF * 2);
        frag_step(ub, ub + DB * 2, ub + 2 * DB * 2, ub + 3 * DB * 2,
                  aoff, boff, wm, wn, 0, acc);
        frag_step(ub, ub + DB * 2, ub + 2 * DB * 2, ub + 3 * DB * 2,
                  aoff, boff, wm, wn, 1, acc);
        __syncthreads();
        if (k0 + 64 < Cc) issue(k0 + 64, it & 1);
        cp_commit();
    }

    const int g2 = lane >> 2, tq = (lane & 3) * 2;
#pragma unroll
    for (int i = 0; i < 4; i++) {
        const int r1 = m0 + wm + i * 16 + g2;
#pragma unroll
        for (int j = 0; j < 4; j++) {
            const int o = n0 + wn + j * 8 + tq;
            const float b0 = bias[o], b1 = bias[o + 1];
            float* c = acc[i * 4 + j];
#pragma unroll
            for (int h = 0; h < 2; h++) {
                const size_t rr = (size_t)(r1 + h * 8) * Cc + o;
                float2 prev = join2(*(const unsigned*)(Ahi + rr),
                                    *(const unsigned*)(Alo + rr));
                float v0 = prev.x + 0.1f * fast_tanh(c[h * 2 + 0] + b0);
                float v1 = prev.y + 0.1f * fast_tanh(c[h * 2 + 1] + b1);
                unsigned uh, ul;
                split2(v0, v1, uh, ul);
                *(unsigned*)(outh + rr) = uh;
                *(unsigned*)(outl + rr) = ul;
            }
        }
    }
}

// ---------------------------------------------------------------------------
// Proj: cp.async double-buffered NT GEMM + fused residual, transposed write.
// ---------------------------------------------------------------------------
__global__ void __launch_bounds__(256) proj_mma(const float* __restrict__ bias,
                                                const float* __restrict__ x,
                                                float* __restrict__ out) {
    extern __shared__ __align__(16) bf16 dsm[];
    const int n0 = blockIdx.x * 128;
    const int m0 = blockIdx.y * 128;
    const int tid = threadIdx.x;
    const int lane = tid & 31;
    const int wid = tid >> 5;
    const int wm = (wid >> 2) * 64, wn = (wid & 3) * 32;
    const int aoff = a_lane_off(lane, PITCH), boff = b_lane_off(lane, PITCH);
    const unsigned u0 = smem_u32(dsm);

    const int r = tid >> 1, kq = (tid & 1) * 16;
    const bf16* pAh = g_hfh1 + (size_t)(m0 + r) * Cc + kq;
    const bf16* pAl = g_hfl1 + (size_t)(m0 + r) * Cc + kq;
    const bf16* pBh = g_wp_hi + (size_t)(n0 + r) * Cc + kq;
    const bf16* pBl = g_wp_lo + (size_t)(n0 + r) * Cc + kq;
    const unsigned doff = 2u * (r * PITCH + kq);

    auto issue = [&](int k0, int bi) {
        const unsigned base = u0 + (unsigned)bi * (DBUF * 2);
        cp16(base + doff, pAh + k0);
        cp16(base + doff + 16, pAh + k0 + 8);
        cp16(base + DB * 2 + doff, pAl + k0);
        cp16(base + DB * 2 + doff + 16, pAl + k0 + 8);
        cp16(base + 2 * DB * 2 + doff, pBh + k0);
        cp16(base + 2 * DB * 2 + doff + 16, pBh + k0 + 8);
        cp16(base + 3 * DB * 2 + doff, pBl + k0);
        cp16(base + 3 * DB * 2 + doff + 16, pBl + k0 + 8);
    };

    issue(0, 0); cp_commit();
    issue(32, 1); cp_commit();

    float acc[16][4] = {};
    for (int k0 = 0, it = 0; k0 < Cc; k0 += 32, ++it) {
        cp_wait1();
        __syncthreads();
        const unsigned ub = u0 + (it & 1) * (DBUF * 2);
        frag_step(ub, ub + DB * 2, ub + 2 * DB * 2, ub + 3 * DB * 2,
                  aoff, boff, wm, wn, 0, acc);
        frag_step(ub, ub + DB * 2, ub + 2 * DB * 2, ub + 3 * DB * 2,
                  aoff, boff, wm, wn, 1, acc);
        __syncthreads();
        if (k0 + 64 < Cc) issue(k0 + 64, it & 1);
        cp_commit();
    }

    const int g2 = lane >> 2, tq = (lane & 3) * 2;
    const int b = m0 >> 10;
#pragma unroll
    for (int i = 0; i < 4; i++) {
        const int s1 = (m0 & 1023) + wm + i * 16 + g2;
#pragma unroll
        for (int j = 0; j < 4; j++) {
            const int o = n0 + wn + j * 8 + tq;
            const float b0 = bias[o], b1 = bias[o + 1];
            float* c = acc[i * 4 + j];
#pragma unroll
            for (int h = 0; h < 2; h++) {
                const int s = s1 + h * 8;
                const size_t i0 = ((size_t)b * Cc + o) * Ss + s;
                const size_t i1 = i0 + Ss;
                out[i0] = x[i0] + c[h * 2 + 0] + b0;
                out[i1] = x[i1] + c[h * 2 + 1] + b1;
            }
        }
    }
}

// ---------------------------------------------------------------------------
extern "C" void kernel_launch(void* const* d_in, const int* in_sizes, int n_in,
                              void* d_out, int out_size) {
    const float* x = (const float*)d_in[0];
    const float* gn_scale = (const float*)d_in[1];
    const float* gn_bias = (const float*)d_in[2];
    const float* qkv_w = (const float*)d_in[3];
    const float* qkv_b = (const float*)d_in[4];
    const float* proj_w = (const float*)d_in[5];
    const float* proj_b = (const float*)d_in[6];
    const float* inl_w = (const float*)d_in[7];
    const float* inl_b = (const float*)d_in[8];
    float* out = (float*)d_out;

    static bool attr_set = false;
    if (!attr_set) {
        cudaFuncSetAttribute(qkv_mma, cudaFuncAttributeMaxDynamicSharedMemorySize, DENSE_SMEM);
        cudaFuncSetAttribute(inl_mma, cudaFuncAttributeMaxDynamicSharedMemorySize, DENSE_SMEM);
        cudaFuncSetAttribute(proj_mma, cudaFuncAttributeMaxDynamicSharedMemorySize, DENSE_SMEM);
        cudaFuncSetAttribute(attn_mma, cudaFuncAttributeMaxDynamicSharedMemorySize, ATTN_SMEM);
        attr_set = true;
    }

    // 0. Convert weights to bf16 hi/lo
    bf16 *wq_hi, *wq_lo, *wi_hi, *wi_lo, *wp_hi, *wp_lo;
    cudaGetSymbolAddress((void**)&wq_hi, g_wq_hi);
    cudaGetSymbolAddress((void**)&wq_lo, g_wq_lo);
    cudaGetSymbolAddress((void**)&wi_hi, g_wi_hi);
    cudaGetSymbolAddress((void**)&wi_lo, g_wi_lo);
    cudaGetSymbolAddress((void**)&wp_hi, g_wp_hi);
    cudaGetSymbolAddress((void**)&wp_lo, g_wp_lo);
    convw<<<(M3 * Cc) / 1024, 256>>>(qkv_w, wq_hi, wq_lo, M3 * Cc);
    convw<<<(Cc * Cc) / 1024, 256>>>(inl_w, wi_hi, wi_lo, Cc * Cc);
    convw<<<(Cc * Cc) / 1024, 256>>>(proj_w, wp_hi, wp_lo, Cc * Cc);

    // 1. GroupNorm (2-phase) -> g_h_hi/lo
    gn_stats<<<512, 256>>>(x);
    gn_apply<<<512, 256>>>(x, gn_scale, gn_bias);

    // 2. QKV GEMM -> g_qkv fp32 (q/k) + g_vh/g_vl (v)
    qkv_mma<<<dim3(Ss / 128, M3 / 128, Bb), 256, DENSE_SMEM>>>(qkv_b);

    // 2b. Q/K transpose + convert
    qk_conv<<<dim3(16, 64, 2), 256>>>();

    // 3. Attention -> g_hfh0/g_hfl0
    attn_mma<<<dim3(Ss / 128, Bb * NH), 256, ATTN_SMEM>>>();

    // 4. INL: 3 Euler steps (ping-pong split buffers), ends in g_hfh1/g_hfl1
    inl_mma<<<dim3(Cc / 128, Bb * Ss / 128), 256, DENSE_SMEM>>>(0, inl_b);
    inl_mma<<<dim3(Cc / 128, Bb * Ss / 128), 256, DENSE_SMEM>>>(1, inl_b);
    inl_mma<<<dim3(Cc / 128, Bb * Ss / 128), 256, DENSE_SMEM>>>(0, inl_b);

    // 5. Proj + residual -> d_out
    proj_mma<<<dim3(Cc / 128, Bb * Ss / 128), 256, DENSE_SMEM>>>(proj_b, x, out);
}

// round 13
// speedup vs baseline: 2.4997x; 1.3985x over previous
#include <cuda_runtime.h>
#include <cuda_fp16.h>
#include <math.h>

typedef __half f16;

// Problem constants
constexpr int Bb = 8;
constexpr int Cc = 512;
constexpr int Ss = 1024;     // H*W
constexpr int M3 = 1536;     // 3*C
constexpr int NH = 8;
constexpr int HD = 64;

constexpr int PITCH = 40;    // dense-GEMM smem row pitch (32 data + 8 pad)
constexpr int APITCH = 72;   // attention smem row pitch (64 data + 8 pad)

constexpr int DB = 128 * PITCH;     // one dense array (f16 units)
constexpr int DBUF = 3 * DB;        // one dense buffer (A, Bhi, Blo)
constexpr int AB = 64 * APITCH;     // one attention array
constexpr int ABUF = 4 * AB;        // one attention buffer (Kh,Kl,Vh,Vl)
constexpr int DENSE_SMEM = 2 * DBUF * 2;  // bytes (61440)
constexpr int ATTN_SMEM = 2 * ABUF * 2;   // bytes (73728)

// Scratch buffers (static device globals; allocation is forbidden)
__device__ __align__(16) f16 g_h_hi[Bb * Cc * Ss];
__device__ __align__(16) f16 g_h_lo[Bb * Cc * Ss];
__device__ float g_qkv[Bb * M3 * Ss];                // fp32, only q/k thirds used
__device__ __align__(16) f16 g_hfh0[Bb * Ss * Cc];
__device__ __align__(16) f16 g_hfl0[Bb * Ss * Cc];
__device__ __align__(16) f16 g_hfh1[Bb * Ss * Cc];
__device__ __align__(16) f16 g_hfl1[Bb * Ss * Cc];
__device__ __align__(16) f16 g_wq_hi[M3 * Cc];
__device__ __align__(16) f16 g_wi_hi[Cc * Cc];
__device__ __align__(16) f16 g_wi_lo[Cc * Cc];
__device__ __align__(16) f16 g_wp_hi[Cc * Cc];
__device__ __align__(16) f16 g_wp_lo[Cc * Cc];
// Attention operand layouts (f16)
__device__ __align__(16) f16 g_qh[Bb * NH * Ss * HD];   // [bh][s][d], scaled, hi only
__device__ __align__(16) f16 g_kh[Bb * NH * Ss * HD];   // [bh][t][d]
__device__ __align__(16) f16 g_kl[Bb * NH * Ss * HD];
__device__ __align__(16) f16 g_vh[Bb * NH * HD * Ss];   // [bh][d][t]
__device__ __align__(16) f16 g_vl[Bb * NH * HD * Ss];
__device__ float g_gnp[512][2];                          // groupnorm partials

__device__ __forceinline__ float fast_tanh(float x) {
    x = fminf(fmaxf(x, -15.f), 15.f);
    float e = __expf(2.f * x);
    return __fdividef(e - 1.f, e + 1.f);
}

// fp16 split: pack pair to hi and lo words (elem0 in low half).
__device__ __forceinline__ void split2h(float x, float y, unsigned& hi, unsigned& lo) {
    f16 hx = __float2half_rn(x), hy = __float2half_rn(y);
    float rx = x - __half2float(hx);
    float ry = y - __half2float(hy);
    f16 lx = __float2half_rn(rx), ly = __float2half_rn(ry);
    hi = ((unsigned)__half_as_ushort(hy) << 16) | (unsigned)__half_as_ushort(hx);
    lo = ((unsigned)__half_as_ushort(ly) << 16) | (unsigned)__half_as_ushort(lx);
}

// Pack pair of fp32 to fp16x2 (x low, y high).
__device__ __forceinline__ unsigned packh2(float x, float y) {
    unsigned u;
    asm("cvt.rn.f16x2.f32 %0, %1, %2;" : "=r"(u) : "f"(y), "f"(x));
    return u;
}

// Reconstruct fp32 pair from packed fp16 hi/lo words.
__device__ __forceinline__ float2 join2h(unsigned h, unsigned l) {
    float x = __half2float(__ushort_as_half((unsigned short)(h & 0xffffu)))
            + __half2float(__ushort_as_half((unsigned short)(l & 0xffffu)));
    float y = __half2float(__ushort_as_half((unsigned short)(h >> 16)))
            + __half2float(__ushort_as_half((unsigned short)(l >> 16)));
    return make_float2(x, y);
}

__device__ __forceinline__ void mma_f16(float* c, const unsigned* a, const unsigned* b) {
    asm("mma.sync.aligned.m16n8k16.row.col.f32.f16.f16.f32 "
        "{%0,%1,%2,%3}, {%4,%5,%6,%7}, {%8,%9}, {%0,%1,%2,%3};"
        : "+f"(c[0]), "+f"(c[1]), "+f"(c[2]), "+f"(c[3])
        : "r"(a[0]), "r"(a[1]), "r"(a[2]), "r"(a[3]), "r"(b[0]), "r"(b[1]));
}

__device__ __forceinline__ unsigned smem_u32(const void* p) {
    return (unsigned)__cvta_generic_to_shared(p);
}
__device__ __forceinline__ void ldsm_x4(unsigned& r0, unsigned& r1, unsigned& r2,
                                        unsigned& r3, unsigned a) {
    asm volatile("ldmatrix.sync.aligned.m8n8.x4.shared.b16 {%0,%1,%2,%3}, [%4];"
                 : "=r"(r0), "=r"(r1), "=r"(r2), "=r"(r3) : "r"(a));
}
__device__ __forceinline__ void ldsm_x2(unsigned& r0, unsigned& r1, unsigned a) {
    asm volatile("ldmatrix.sync.aligned.m8n8.x2.shared.b16 {%0,%1}, [%2];"
                 : "=r"(r0), "=r"(r1) : "r"(a));
}

// cp.async helpers (16B copies)
__device__ __forceinline__ void cp16(unsigned dst, const void* src) {
    asm volatile("cp.async.cg.shared.global [%0], [%1], 16;" :: "r"(dst), "l"(src));
}
__device__ __forceinline__ void cp_commit() {
    asm volatile("cp.async.commit_group;");
}
__device__ __forceinline__ void cp_wait1() {
    asm volatile("cp.async.wait_group 1;");
}

// Per-lane ldmatrix offsets (f16 units).
__device__ __forceinline__ int a_lane_off(int lane, int pitch) {
    return ((lane & 7) + ((lane >> 3) & 1) * 8) * pitch + ((lane >> 4) & 1) * 8;
}
__device__ __forceinline__ int b_lane_off(int lane, int pitch) {
    return (lane & 7) * pitch + ((lane >> 3) & 1) * 8;
}

// One k16 step for the dense GEMMs: A hi-only, B 2-term split.
__device__ __forceinline__ void frag_step(
    unsigned uA, unsigned uBhi, unsigned uBlo,
    int aoff, int boff, int wm, int wn, int ks, float acc[16][4]) {
    unsigned a[4][4], bh[4][2], bl[4][2];
#pragma unroll
    for (int i = 0; i < 4; i++) {
        const unsigned off = 2u * ((wm + i * 16) * PITCH + ks * 16 + aoff);
        ldsm_x4(a[i][0], a[i][1], a[i][2], a[i][3], uA + off);
    }
#pragma unroll
    for (int j = 0; j < 4; j++) {
        const unsigned off = 2u * ((wn + j * 8) * PITCH + ks * 16 + boff);
        ldsm_x2(bh[j][0], bh[j][1], uBhi + off);
        ldsm_x2(bl[j][0], bl[j][1], uBlo + off);
    }
#pragma unroll
    for (int i = 0; i < 4; i++)
#pragma unroll
        for (int j = 0; j < 4; j++) {
            mma_f16(acc[i * 4 + j], a[i], bh[j]);
            mma_f16(acc[i * 4 + j], a[i], bl[j]);
        }
}

// ---------------------------------------------------------------------------
// Weight converts
// ---------------------------------------------------------------------------
__global__ void convw_hi(const float* __restrict__ src, f16* __restrict__ hi, int n) {
    int i = (blockIdx.x * 256 + threadIdx.x) * 4;
    if (i < n) {
        float4 v = *(const float4*)(src + i);
        uint2 uh;
        uh.x = packh2(v.x, v.y);
        uh.y = packh2(v.z, v.w);
        *(uint2*)(hi + i) = uh;
    }
}
__global__ void convw(const float* __restrict__ src, f16* __restrict__ hi,
                      f16* __restrict__ lo, int n) {
    int i = (blockIdx.x * 256 + threadIdx.x) * 4;
    if (i < n) {
        float4 v = *(const float4*)(src + i);
        uint2 uh, ul;
        split2h(v.x, v.y, uh.x, ul.x);
        split2h(v.z, v.w, uh.y, ul.y);
        *(uint2*)(hi + i) = uh;
        *(uint2*)(lo + i) = ul;
    }
}

// ---------------------------------------------------------------------------
// GroupNorm phase 1: partial sums. grid 512.
// ---------------------------------------------------------------------------
__global__ void gn_stats(const float* __restrict__ x) {
    const int grp = blockIdx.x >> 3;
    const int slice = blockIdx.x & 7;
    const float* xp = x + (size_t)grp * 65536 + slice * 8192;
    float s = 0.f, s2 = 0.f;
#pragma unroll
    for (int r = 0; r < 8; r++) {
        float4 v = *(const float4*)(xp + (threadIdx.x + r * 256) * 4);
        s += v.x + v.y + v.z + v.w;
        s2 += v.x * v.x + v.y * v.y + v.z * v.z + v.w * v.w;
    }
    __shared__ float rs[256], rs2[256];
    rs[threadIdx.x] = s; rs2[threadIdx.x] = s2;
    __syncthreads();
    for (int o = 128; o > 0; o >>= 1) {
        if (threadIdx.x < o) {
            rs[threadIdx.x] += rs[threadIdx.x + o];
            rs2[threadIdx.x] += rs2[threadIdx.x + o];
        }
        __syncthreads();
    }
    if (threadIdx.x == 0) {
        g_gnp[blockIdx.x][0] = rs[0];
        g_gnp[blockIdx.x][1] = rs2[0];
    }
}

// ---------------------------------------------------------------------------
// GroupNorm phase 2: finalize + apply. grid 512.
// ---------------------------------------------------------------------------
__global__ void gn_apply(const float* __restrict__ x,
                         const float* __restrict__ scale,
                         const float* __restrict__ bias) {
    const int grp = blockIdx.x >> 3;
    const int slice = blockIdx.x & 7;
    float s = 0.f, s2 = 0.f;
#pragma unroll
    for (int p = 0; p < 8; p++) { s += g_gnp[grp * 8 + p][0]; s2 += g_gnp[grp * 8 + p][1]; }
    const float mean = s / 65536.f;
    float var = s2 / 65536.f - mean * mean;
    var = fmaxf(var, 0.f);
    const float rstd = rsqrtf(var + 1e-5f);

    const size_t base = (size_t)grp * 65536 + slice * 8192;
    const int cbase = (grp & 7) * 64 + slice * 8;
#pragma unroll
    for (int r = 0; r < 8; r++) {
        const int k = (threadIdx.x + r * 256) * 4;
        const int c = cbase + (k >> 10);
        const float a = rstd * scale[c];
        const float bb2 = bias[c] - mean * a;
        float4 v = *(const float4*)(x + base + k);
        float4 o = make_float4(v.x * a + bb2, v.y * a + bb2,
                               v.z * a + bb2, v.w * a + bb2);
        uint2 uh, ul;
        split2h(o.x, o.y, uh.x, ul.x);
        split2h(o.z, o.w, uh.y, ul.y);
        *(uint2*)(g_h_hi + base + k) = uh;
        *(uint2*)(g_h_lo + base + k) = ul;
    }
}

// ---------------------------------------------------------------------------
// QKV GEMM (NN): A = W (hi only, cp.async), B = h (hi+lo, register transpose).
// ---------------------------------------------------------------------------
__global__ void __launch_bounds__(256) qkv_mma(const float* __restrict__ bias) {
    extern __shared__ __align__(16) f16 dsm[];
    const int b = blockIdx.z;
    const int n0 = blockIdx.x * 128;
    const int m0 = blockIdx.y * 128;
    const int tid = threadIdx.x;
    const int lane = tid & 31;
    const int wid = tid >> 5;
    const int wm = (wid >> 2) * 64, wn = (wid & 3) * 32;
    const int aoff = a_lane_off(lane, PITCH), boff = b_lane_off(lane, PITCH);
    const unsigned u0 = smem_u32(dsm);

    const f16* Hhi = g_h_hi + (size_t)b * Cc * Ss;
    const f16* Hlo = g_h_lo + (size_t)b * Cc * Ss;

    const int r = tid >> 1, kq = (tid & 1) * 16;
    const f16* pA = g_wq_hi + (size_t)(m0 + r) * Cc + kq;
    const unsigned doff = 2u * (r * PITCH + kq);

    auto issueA = [&](int k0, int bi) {
        const unsigned base = u0 + (unsigned)bi * (DBUF * 2);
        cp16(base + doff, pA + k0);
        cp16(base + doff + 16, pA + k0 + 8);
    };

    float acc[16][4] = {};

    unsigned nh0[4], nh1[4], nl0[4], nl1[4];
#pragma unroll
    for (int q = 0; q < 4; q++) {
        int bi = tid + q * 256;
        int kb = bi >> 6, nb = bi & 63;
        const f16* ph = Hhi + (size_t)(2 * kb) * Ss + n0 + 2 * nb;
        const f16* pl = Hlo + (size_t)(2 * kb) * Ss + n0 + 2 * nb;
        nh0[q] = *(const unsigned*)ph; nh1[q] = *(const unsigned*)(ph + Ss);
        nl0[q] = *(const unsigned*)pl; nl1[q] = *(const unsigned*)(pl + Ss);
    }
    issueA(0, 0); cp_commit();
    issueA(32, 1); cp_commit();

    for (int k0 = 0, it = 0; k0 < Cc; k0 += 32, ++it) {
        f16* buf = dsm + (it & 1) * DBUF;
        f16* sBhi = buf + DB;
        f16* sBlo = buf + 2 * DB;
#pragma unroll
        for (int q = 0; q < 4; q++) {
            int bi = tid + q * 256;
            int kb = bi >> 6, nb = bi & 63;
            *(unsigned*)&sBhi[(2 * nb) * PITCH + 2 * kb] = __byte_perm(nh0[q], nh1[q], 0x5410);
            *(unsigned*)&sBhi[(2 * nb + 1) * PITCH + 2 * kb] = __byte_perm(nh0[q], nh1[q], 0x7632);
            *(unsigned*)&sBlo[(2 * nb) * PITCH + 2 * kb] = __byte_perm(nl0[q], nl1[q], 0x5410);
            *(unsigned*)&sBlo[(2 * nb + 1) * PITCH + 2 * kb] = __byte_perm(nl0[q], nl1[q], 0x7632);
        }
        cp_wait1();
        __syncthreads();
        if (k0 + 32 < Cc) {
#pragma unroll
            for (int q = 0; q < 4; q++) {
                int bi = tid + q * 256;
                int kb = bi >> 6, nb = bi & 63;
                const f16* ph = Hhi + (size_t)(k0 + 32 + 2 * kb) * Ss + n0 + 2 * nb;
                const f16* pl = Hlo + (size_t)(k0 + 32 + 2 * kb) * Ss + n0 + 2 * nb;
                nh0[q] = *(const unsigned*)ph; nh1[q] = *(const unsigned*)(ph + Ss);
                nl0[q] = *(const unsigned*)pl; nl1[q] = *(const unsigned*)(pl + Ss);
            }
        }
        const unsigned ub = u0 + (it & 1) * (DBUF * 2);
        frag_step(ub, ub + DB * 2, ub + 2 * DB * 2, aoff, boff, wm, wn, 0, acc);
        frag_step(ub, ub + DB * 2, ub + 2 * DB * 2, aoff, boff, wm, wn, 1, acc);
        __syncthreads();
        if (k0 + 64 < Cc) issueA(k0 + 64, it & 1);
        cp_commit();
    }

    const int g2 = lane >> 2, tq = (lane & 3) * 2;
    if (m0 < 1024) {
        float* out = g_qkv + (size_t)b * M3 * Ss;
#pragma unroll
        for (int i = 0; i < 4; i++) {
            const int m1 = m0 + wm + i * 16 + g2;
            const float bv1 = bias[m1], bv2 = bias[m1 + 8];
#pragma unroll
            for (int j = 0; j < 4; j++) {
                const int n = n0 + wn + j * 8 + tq;
                float* c = acc[i * 4 + j];
                *(float2*)(out + (size_t)m1 * Ss + n) = make_float2(c[0] + bv1, c[1] + bv1);
                *(float2*)(out + (size_t)(m1 + 8) * Ss + n) = make_float2(c[2] + bv2, c[3] + bv2);
            }
        }
    } else {
#pragma unroll
        for (int i = 0; i < 4; i++) {
            const int m1 = m0 + wm + i * 16 + g2;
            const float bv1 = bias[m1], bv2 = bias[m1 + 8];
#pragma unroll
            for (int j = 0; j < 4; j++) {
                const int n = n0 + wn + j * 8 + tq;
                float* c = acc[i * 4 + j];
                const size_t i0 = (size_t)b * 524288 + (size_t)(m1 - 1024) * Ss + n;
                const size_t i1 = (size_t)b * 524288 + (size_t)(m1 - 1024 + 8) * Ss + n;
                unsigned h, l;
                split2h(c[0] + bv1, c[1] + bv1, h, l);
                *(unsigned*)(g_vh + i0) = h;
                *(unsigned*)(g_vl + i0) = l;
                split2h(c[2] + bv2, c[3] + bv2, h, l);
                *(unsigned*)(g_vh + i1) = h;
                *(unsigned*)(g_vl + i1) = l;
            }
        }
    }
}

// ---------------------------------------------------------------------------
// Q/K transpose+convert: Q -> hi only (scaled), K -> hi+lo.
// ---------------------------------------------------------------------------
__global__ void qk_conv() {
    __shared__ float tile[64][65];
    const int tid = threadIdx.x;
    const int bh = blockIdx.y, b = bh >> 3, hh = bh & 7;
    const int st = blockIdx.x * 64;
    const int isK = blockIdx.z;
    const float* src = g_qkv + (size_t)b * M3 * Ss +
                       (size_t)(isK * Cc + hh * HD) * Ss + st;
#pragma unroll
    for (int r = 0; r < 4; r++) {
        int idx = tid + r * 256;
        int d = idx >> 4, s4 = (idx & 15) * 4;
        float4 v = *(const float4*)(src + (size_t)d * Ss + s4);
        tile[d][s4 + 0] = v.x; tile[d][s4 + 1] = v.y;
        tile[d][s4 + 2] = v.z; tile[d][s4 + 3] = v.w;
    }
    __syncthreads();
    if (isK) {
        f16* oh = g_kh + ((size_t)bh * Ss + st) * HD;
        f16* ol = g_kl + ((size_t)bh * Ss + st) * HD;
#pragma unroll
        for (int r = 0; r < 8; r++) {
            int idx = tid + r * 256;
            int s = idx >> 5, dp = (idx & 31) * 2;
            unsigned h, l;
            split2h(tile[dp][s], tile[dp + 1][s], h, l);
            *(unsigned*)(oh + (size_t)s * HD + dp) = h;
            *(unsigned*)(ol + (size_t)s * HD + dp) = l;
        }
    } else {
        f16* oh = g_qh + ((size_t)bh * Ss + st) * HD;
#pragma unroll
        for (int r = 0; r < 8; r++) {
            int idx = tid + r * 256;
            int s = idx >> 5, dp = (idx & 31) * 2;
            *(unsigned*)(oh + (size_t)s * HD + dp) =
                packh2(tile[dp][s] * 0.125f, tile[dp + 1][s] * 0.125f);
        }
    }
}

// ---------------------------------------------------------------------------
// Attention: Q hi-only, K/V 2-term split, cp.async double-buffered.
// ---------------------------------------------------------------------------
__global__ void __launch_bounds__(256) attn_mma() {
    extern __shared__ __align__(16) f16 asm_[];
    const int tid = threadIdx.x, lane = tid & 31, w = tid >> 5;
    const int bh = blockIdx.y, b = bh >> 3, hh = bh & 7;
    const int s0 = blockIdx.x * 128;
    const int g = lane >> 2, q2 = (lane & 3) * 2;
    const int srow = s0 + w * 16;
    const int boffA = b_lane_off(lane, APITCH);
    const unsigned u0 = smem_u32(asm_);

    // Q fragments (hi only)
    unsigned qh[4][4];
    {
        const f16* Qh = g_qh + ((size_t)bh * Ss + srow) * HD;
#pragma unroll
        for (int ks = 0; ks < 4; ks++) {
            qh[ks][0] = *(const unsigned*)(Qh + (size_t)g * HD + ks * 16 + q2);
            qh[ks][1] = *(const unsigned*)(Qh + (size_t)(g + 8) * HD + ks * 16 + q2);
            qh[ks][2] = *(const unsigned*)(Qh + (size_t)g * HD + ks * 16 + q2 + 8);
            qh[ks][3] = *(const unsigned*)(Qh + (size_t)(g + 8) * HD + ks * 16 + q2 + 8);
        }
    }

    const f16* Kh = g_kh + (size_t)bh * Ss * HD;
    const f16* Kl = g_kl + (size_t)bh * Ss * HD;
    const f16* Vh = g_vh + (size_t)bh * HD * Ss;
    const f16* Vl = g_vl + (size_t)bh * HD * Ss;

    const int row0 = tid >> 3, c8 = (tid & 7) * 8;
    auto issue = [&](int t0, int bi) {
        const unsigned base = u0 + (unsigned)bi * (ABUF * 2);
#pragma unroll
        for (int rr = 0; rr < 2; rr++) {
            const int row = row0 + rr * 32;
            const unsigned d = 2u * (row * APITCH + c8);
            cp16(base + d, Kh + (size_t)(t0 + row) * HD + c8);
            cp16(base + AB * 2 + d, Kl + (size_t)(t0 + row) * HD + c8);
            cp16(base + 2 * AB * 2 + d, Vh + (size_t)row * Ss + t0 + c8);
            cp16(base + 3 * AB * 2 + d, Vl + (size_t)row * Ss + t0 + c8);
        }
    };

    issue(0, 0); cp_commit();
    issue(64, 1); cp_commit();

    float m0 = -1e30f, m1 = -1e30f, l0 = 0.f, l1 = 0.f;
    float O[8][4] = {};

    for (int t0 = 0, it = 0; t0 < Ss; t0 += 64, ++it) {
        cp_wait1();
        __syncthreads();
        const unsigned ub = u0 + (it & 1) * (ABUF * 2);
        const unsigned uKh = ub, uKl = ub + AB * 2;
        const unsigned uVh = ub + 2 * AB * 2, uVl = ub + 3 * AB * 2;

        // Scores: 2-term (drop Q residual)
        float sc[8][4] = {};
#pragma unroll
        for (int ks = 0; ks < 4; ks++) {
#pragma unroll
            for (int j = 0; j < 8; j++) {
                const unsigned off = 2u * (j * 8 * APITCH + ks * 16 + boffA);
                unsigned kbh[2], kbl[2];
                ldsm_x2(kbh[0], kbh[1], uKh + off);
                ldsm_x2(kbl[0], kbl[1], uKl + off);
                mma_f16(sc[j], qh[ks], kbh);
                mma_f16(sc[j], qh[ks], kbl);
            }
        }

        // Online softmax
        float mx0 = -1e30f, mx1 = -1e30f;
#pragma unroll
        for (int j = 0; j < 8; j++) {
            mx0 = fmaxf(mx0, fmaxf(sc[j][0], sc[j][1]));
            mx1 = fmaxf(mx1, fmaxf(sc[j][2], sc[j][3]));
        }
        mx0 = fmaxf(mx0, __shfl_xor_sync(0xffffffffu, mx0, 1));
        mx0 = fmaxf(mx0, __shfl_xor_sync(0xffffffffu, mx0, 2));
        mx1 = fmaxf(mx1, __shfl_xor_sync(0xffffffffu, mx1, 1));
        mx1 = fmaxf(mx1, __shfl_xor_sync(0xffffffffu, mx1, 2));
        const float nm0 = fmaxf(m0, mx0), nm1 = fmaxf(m1, mx1);
        const float cr0 = __expf(m0 - nm0), cr1 = __expf(m1 - nm1);
        m0 = nm0; m1 = nm1;

        unsigned ph[4][4];
        float ss0 = 0.f, ss1 = 0.f;
#pragma unroll
        for (int j = 0; j < 8; j++) {
            float p0 = __expf(sc[j][0] - m0), p1 = __expf(sc[j][1] - m0);
            float p2 = __expf(sc[j][2] - m1), p3 = __expf(sc[j][3] - m1);
            ss0 += p0 + p1; ss1 += p2 + p3;
            const int kt = j >> 1;
            if ((j & 1) == 0) {
                ph[kt][0] = packh2(p0, p1);
                ph[kt][1] = packh2(p2, p3);
            } else {
                ph[kt][2] = packh2(p0, p1);
                ph[kt][3] = packh2(p2, p3);
            }
        }
        ss0 += __shfl_xor_sync(0xffffffffu, ss0, 1);
        ss0 += __shfl_xor_sync(0xffffffffu, ss0, 2);
        ss1 += __shfl_xor_sync(0xffffffffu, ss1, 1);
        ss1 += __shfl_xor_sync(0xffffffffu, ss1, 2);
        l0 = l0 * cr0 + ss0;
        l1 = l1 * cr1 + ss1;

#pragma unroll
        for (int jd = 0; jd < 8; jd++) {
            O[jd][0] *= cr0; O[jd][1] *= cr0;
            O[jd][2] *= cr1; O[jd][3] *= cr1;
        }
#pragma unroll
        for (int kt = 0; kt < 4; kt++) {
#pragma unroll
            for (int jd = 0; jd < 8; jd++) {
                const unsigned off = 2u * (jd * 8 * APITCH + kt * 16 + boffA);
                unsigned vbh[2], vbl[2];
                ldsm_x2(vbh[0], vbh[1], uVh + off);
                ldsm_x2(vbl[0], vbl[1], uVl + off);
                mma_f16(O[jd], ph[kt], vbh);
                mma_f16(O[jd], ph[kt], vbl);
            }
        }
        __syncthreads();
        if (t0 + 128 < Ss) issue(t0 + 128, it & 1);
        cp_commit();
    }

    // Finalize
    const float inv0 = __fdividef(1.f, l0), inv1 = __fdividef(1.f, l1);
    const size_t base = ((size_t)b * Ss + srow) * Cc + hh * HD;
#pragma unroll
    for (int jd = 0; jd < 8; jd++) {
        const int d = jd * 8 + q2;
        float a0 = O[jd][0] * inv0, a1 = O[jd][1] * inv0;
        float a2 = O[jd][2] * inv1, a3 = O[jd][3] * inv1;
        const size_t i0 = base + (size_t)g * Cc + d;
        const size_t i1 = base + (size_t)(g + 8) * Cc + d;
        unsigned h, l;
        split2h(a0, a1, h, l);
        *(unsigned*)(g_hfh0 + i0) = h;
        *(unsigned*)(g_hfl0 + i0) = l;
        split2h(a2, a3, h, l);
        *(unsigned*)(g_hfh0 + i1) = h;
        *(unsigned*)(g_hfl0 + i1) = l;
    }
}

// ---------------------------------------------------------------------------
// INL step: A = hf (hi only in MMA), B = W (hi+lo). Fused Euler/tanh epilogue.
// ---------------------------------------------------------------------------
__global__ void __launch_bounds__(256) inl_mma(int src, const float* __restrict__ bias) {
    extern __shared__ __align__(16) f16 dsm[];
    const f16* Ahi = src ? g_hfh1 : g_hfh0;
    const f16* Alo = src ? g_hfl1 : g_hfl0;
    f16* outh = src ? g_hfh0 : g_hfh1;
    f16* outl = src ? g_hfl0 : g_hfl1;

    const int n0 = blockIdx.x * 128;
    const int m0 = blockIdx.y * 128;
    const int tid = threadIdx.x;
    const int lane = tid & 31;
    const int wid = tid >> 5;
    const int wm = (wid >> 2) * 64, wn = (wid & 3) * 32;
    const int aoff = a_lane_off(lane, PITCH), boff = b_lane_off(lane, PITCH);
    const unsigned u0 = smem_u32(dsm);

    const int r = tid >> 1, kq = (tid & 1) * 16;
    const f16* pA = Ahi + (size_t)(m0 + r) * Cc + kq;
    const f16* pBh = g_wi_hi + (size_t)(n0 + r) * Cc + kq;
    const f16* pBl = g_wi_lo + (size_t)(n0 + r) * Cc + kq;
    const unsigned doff = 2u * (r * PITCH + kq);

    auto issue = [&](int k0, int bi) {
        const unsigned base = u0 + (unsigned)bi * (DBUF * 2);
        cp16(base + doff, pA + k0);
        cp16(base + doff + 16, pA + k0 + 8);
        cp16(base + DB * 2 + doff, pBh + k0);
        cp16(base + DB * 2 + doff + 16, pBh + k0 + 8);
        cp16(base + 2 * DB * 2 + doff, pBl + k0);
        cp16(base + 2 * DB * 2 + doff + 16, pBl + k0 + 8);
    };

    issue(0, 0); cp_commit();
    issue(32, 1); cp_commit();

    float acc[16][4] = {};
    for (int k0 = 0, it = 0; k0 < Cc; k0 += 32, ++it) {
        cp_wait1();
        __syncthreads();
        const unsigned ub = u0 + (it & 1) * (DBUF * 2);
        frag_step(ub, ub + DB * 2, ub + 2 * DB * 2, aoff, boff, wm, wn, 0, acc);
        frag_step(ub, ub + DB * 2, ub + 2 * DB * 2, aoff, boff, wm, wn, 1, acc);
        __syncthreads();
        if (k0 + 64 < Cc) issue(k0 + 64, it & 1);
        cp_commit();
    }

    const int g2 = lane >> 2, tq = (lane & 3) * 2;
#pragma unroll
    for (int i = 0; i < 4; i++) {
        const int r1 = m0 + wm + i * 16 + g2;
#pragma unroll
        for (int j = 0; j < 4; j++) {
            const int o = n0 + wn + j * 8 + tq;
            const float b0 = bias[o], b1 = bias[o + 1];
            float* c = acc[i * 4 + j];
#pragma unroll
            for (int h = 0; h < 2; h++) {
                const size_t rr = (size_t)(r1 + h * 8) * Cc + o;
                float2 prev = join2h(*(const unsigned*)(Ahi + rr),
                                     *(const unsigned*)(Alo + rr));
                float v0 = prev.x + 0.1f * fast_tanh(c[h * 2 + 0] + b0);
                float v1 = prev.y + 0.1f * fast_tanh(c[h * 2 + 1] + b1);
                unsigned uh, ul;
                split2h(v0, v1, uh, ul);
                *(unsigned*)(outh + rr) = uh;
                *(unsigned*)(outl + rr) = ul;
            }
        }
    }
}

// ---------------------------------------------------------------------------
// Proj: A = hf (hi only), B = W (hi+lo). Fused residual, transposed write.
// ---------------------------------------------------------------------------
__global__ void __launch_bounds__(256) proj_mma(const float* __restrict__ bias,
                                                const float* __restrict__ x,
                                                float* __restrict__ out) {
    extern __shared__ __align__(16) f16 dsm[];
    const int n0 = blockIdx.x * 128;
    const int m0 = blockIdx.y * 128;
    const int tid = threadIdx.x;
    const int lane = tid & 31;
    const int wid = tid >> 5;
    const int wm = (wid >> 2) * 64, wn = (wid & 3) * 32;
    const int aoff = a_lane_off(lane, PITCH), boff = b_lane_off(lane, PITCH);
    const unsigned u0 = smem_u32(dsm);

    const int r = tid >> 1, kq = (tid & 1) * 16;
    const f16* pA = g_hfh1 + (size_t)(m0 + r) * Cc + kq;
    const f16* pBh = g_wp_hi + (size_t)(n0 + r) * Cc + kq;
    const f16* pBl = g_wp_lo + (size_t)(n0 + r) * Cc + kq;
    const unsigned doff = 2u * (r * PITCH + kq);

    auto issue = [&](int k0, int bi) {
        const unsigned base = u0 + (unsigned)bi * (DBUF * 2);
        cp16(base + doff, pA + k0);
        cp16(base + doff + 16, pA + k0 + 8);
        cp16(base + DB * 2 + doff, pBh + k0);
        cp16(base + DB * 2 + doff + 16, pBh + k0 + 8);
        cp16(base + 2 * DB * 2 + doff, pBl + k0);
        cp16(base + 2 * DB * 2 + doff + 16, pBl + k0 + 8);
    };

    issue(0, 0); cp_commit();
    issue(32, 1); cp_commit();

    float acc[16][4] = {};
    for (int k0 = 0, it = 0; k0 < Cc; k0 += 32, ++it) {
        cp_wait1();
        __syncthreads();
        const unsigned ub = u0 + (it & 1) * (DBUF * 2);
        frag_step(ub, ub + DB * 2, ub + 2 * DB * 2, aoff, boff, wm, wn, 0, acc);
        frag_step(ub, ub + DB * 2, ub + 2 * DB * 2, aoff, boff, wm, wn, 1, acc);
        __syncthreads();
        if (k0 + 64 < Cc) issue(k0 + 64, it & 1);
        cp_commit();
    }

    const int g2 = lane >> 2, tq = (lane & 3) * 2;
    const int b = m0 >> 10;
#pragma unroll
    for (int i = 0; i < 4; i++) {
        const int s1 = (m0 & 1023) + wm + i * 16 + g2;
#pragma unroll
        for (int j = 0; j < 4; j++) {
            const int o = n0 + wn + j * 8 + tq;
            const float b0 = bias[o], b1 = bias[o + 1];
            float* c = acc[i * 4 + j];
#pragma unroll
            for (int h = 0; h < 2; h++) {
                const int s = s1 + h * 8;
                const size_t i0 = ((size_t)b * Cc + o) * Ss + s;
                const size_t i1 = i0 + Ss;
                out[i0] = x[i0] + c[h * 2 + 0] + b0;
                out[i1] = x[i1] + c[h * 2 + 1] + b1;
            }
        }
    }
}

// ---------------------------------------------------------------------------
extern "C" void kernel_launch(void* const* d_in, const int* in_sizes, int n_in,
                              void* d_out, int out_size) {
    const float* x = (const float*)d_in[0];
    const float* gn_scale = (const float*)d_in[1];
    const float* gn_bias = (const float*)d_in[2];
    const float* qkv_w = (const float*)d_in[3];
    const float* qkv_b = (const float*)d_in[4];
    const float* proj_w = (const float*)d_in[5];
    const float* proj_b = (const float*)d_in[6];
    const float* inl_w = (const float*)d_in[7];
    const float* inl_b = (const float*)d_in[8];
    float* out = (float*)d_out;

    static bool attr_set = false;
    if (!attr_set) {
        cudaFuncSetAttribute(qkv_mma, cudaFuncAttributeMaxDynamicSharedMemorySize, DENSE_SMEM);
        cudaFuncSetAttribute(inl_mma, cudaFuncAttributeMaxDynamicSharedMemorySize, DENSE_SMEM);
        cudaFuncSetAttribute(proj_mma, cudaFuncAttributeMaxDynamicSharedMemorySize, DENSE_SMEM);
        cudaFuncSetAttribute(attn_mma, cudaFuncAttributeMaxDynamicSharedMemorySize, ATTN_SMEM);
        attr_set = true;
    }

    // 0. Convert weights to fp16 (qkv: hi only; inl/proj: hi+lo)
    f16 *wq_hi, *wi_hi, *wi_lo, *wp_hi, *wp_lo;
    cudaGetSymbolAddress((void**)&wq_hi, g_wq_hi);
    cudaGetSymbolAddress((void**)&wi_hi, g_wi_hi);
    cudaGetSymbolAddress((void**)&wi_lo, g_wi_lo);
    cudaGetSymbolAddress((void**)&wp_hi, g_wp_hi);
    cudaGetSymbolAddress((void**)&wp_lo, g_wp_lo);
    convw_hi<<<(M3 * Cc) / 1024, 256>>>(qkv_w, wq_hi, M3 * Cc);
    convw<<<(Cc * Cc) / 1024, 256>>>(inl_w, wi_hi, wi_lo, Cc * Cc);
    convw<<<(Cc * Cc) / 1024, 256>>>(proj_w, wp_hi, wp_lo, Cc * Cc);

    // 1. GroupNorm (2-phase) -> g_h_hi/lo
    gn_stats<<<512, 256>>>(x);
    gn_apply<<<512, 256>>>(x, gn_scale, gn_bias);

    // 2. QKV GEMM -> g_qkv fp32 (q/k) + g_vh/g_vl (v)
    qkv_mma<<<dim3(Ss / 128, M3 / 128, Bb), 256, DENSE_SMEM>>>(qkv_b);

    // 2b. Q/K transpose + convert
    qk_conv<<<dim3(16, 64, 2), 256>>>();

    // 3. Attention -> g_hfh0/g_hfl0
    attn_mma<<<dim3(Ss / 128, Bb * NH), 256, ATTN_SMEM>>>();

    // 4. INL: 3 Euler steps (ping-pong split buffers), ends in g_hfh1/g_hfl1
    inl_mma<<<dim3(Cc / 128, Bb * Ss / 128), 256, DENSE_SMEM>>>(0, inl_b);
    inl_mma<<<dim3(Cc / 128, Bb * Ss / 128), 256, DENSE_SMEM>>>(1, inl_b);
    inl_mma<<<dim3(Cc / 128, Bb * Ss / 128), 256, DENSE_SMEM>>>(0, inl_b);

    // 5. Proj + residual -> d_out
    proj_mma<<<dim3(Cc / 128, Bb * Ss / 128), 256, DENSE_SMEM>>>(proj_b, x, out);
}